// round 4
// baseline (speedup 1.0000x reference)
#include <cuda_runtime.h>
#include <cuda_fp16.h>
#include <math.h>
#include <stdint.h>

#define NH   16
#define DKH  64
#define DM   1024
#define NB   2
#define SEQ  2048
#define MTOK (NB * SEQ)   // 4096

// ---------------------------------------------------------------------------
// Device scratch
// ---------------------------------------------------------------------------
__device__ float g_q[(size_t)MTOK * DM];
__device__ float g_k[(size_t)MTOK * DM];
__device__ float g_v[(size_t)MTOK * DM];
__device__ float g_ctx[(size_t)MTOK * DM];

__device__ __half g_xhi[(size_t)3 * MTOK * DM];
__device__ __half g_xlo[(size_t)3 * MTOK * DM];
__device__ __half g_whi[(size_t)4 * DM * DM];
__device__ __half g_wlo[(size_t)4 * DM * DM];
__device__ __half g_chi[(size_t)MTOK * DM];
__device__ __half g_clo[(size_t)MTOK * DM];

// ---------------------------------------------------------------------------
// Portable PTX helpers (sm_80+ ISA only — harness ptxas targets plain sm_103)
// ---------------------------------------------------------------------------
__device__ __forceinline__ uint32_t smem_u32(const void* p) {
    uint32_t a;
    asm("{ .reg .u64 t; cvta.to.shared.u64 t, %1; cvt.u32.u64 %0, t; }" : "=r"(a) : "l"(p));
    return a;
}

__device__ __forceinline__ void cp_async16(uint32_t dst, const void* src) {
    asm volatile("cp.async.cg.shared.global [%0], [%1], 16;" :: "r"(dst), "l"(src));
}
__device__ __forceinline__ void cp_commit() {
    asm volatile("cp.async.commit_group;");
}
__device__ __forceinline__ void cp_wait1() {
    asm volatile("cp.async.wait_group 1;");
}

__device__ __forceinline__ void ldsm4(uint32_t* r, uint32_t addr) {
    asm volatile("ldmatrix.sync.aligned.m8n8.x4.shared.b16 {%0,%1,%2,%3}, [%4];"
                 : "=r"(r[0]), "=r"(r[1]), "=r"(r[2]), "=r"(r[3]) : "r"(addr));
}

__device__ __forceinline__ void mma16816(float* c, const uint32_t* a, const uint32_t* b) {
    asm volatile(
        "mma.sync.aligned.m16n8k16.row.col.f32.f16.f16.f32 "
        "{%0,%1,%2,%3}, {%4,%5,%6,%7}, {%8,%9}, {%0,%1,%2,%3};"
        : "+f"(c[0]), "+f"(c[1]), "+f"(c[2]), "+f"(c[3])
        : "r"(a[0]), "r"(a[1]), "r"(a[2]), "r"(a[3]), "r"(b[0]), "r"(b[1]));
}

// Swizzle for 64-byte rows (32 halfs): XOR 16B-segment bits [4:6) with row bits 1-2.
// Conflict-free for both cp.async writes and ldmatrix 8-row reads.
__device__ __forceinline__ uint32_t swz64(uint32_t off) {
    return off ^ (((off >> 7) & 3u) << 4);
}

// ---------------------------------------------------------------------------
// Split-fp16 conversion: hi = f16(x), lo = f16(x - hi)
// ---------------------------------------------------------------------------
__global__ __launch_bounds__(256) void split_f16(const float* __restrict__ src,
                                                 __half* __restrict__ hi,
                                                 __half* __restrict__ lo, int n4) {
    int i = blockIdx.x * blockDim.x + threadIdx.x;
    if (i >= n4) return;
    float4 v = ((const float4*)src)[i];
    __half h0 = __float2half_rn(v.x), h1 = __float2half_rn(v.y);
    __half h2 = __float2half_rn(v.z), h3 = __float2half_rn(v.w);
    __half l0 = __float2half_rn(v.x - __half2float(h0));
    __half l1 = __float2half_rn(v.y - __half2float(h1));
    __half l2 = __float2half_rn(v.z - __half2float(h2));
    __half l3 = __float2half_rn(v.w - __half2float(h3));
    ((__half2*)hi)[2 * i]     = __halves2half2(h0, h1);
    ((__half2*)hi)[2 * i + 1] = __halves2half2(h2, h3);
    ((__half2*)lo)[2 * i]     = __halves2half2(l0, l1);
    ((__half2*)lo)[2 * i + 1] = __halves2half2(l2, l3);
}

// ---------------------------------------------------------------------------
// mma.sync split-fp16 GEMM (NT): C[M,N] = A[M,K]*W[N,K]^T + bias
// Block tile 128x128, BK=32, 8 warps (warp tile 32x64), double-buffered cp.async.
// ---------------------------------------------------------------------------
struct GemmArgs {
    const __half *xhi, *xlo, *whi, *wlo;
    const float *b0, *b1, *b2;
    float *o0, *o1, *o2;
    long long xstride, wstride;
};

#define TILE_B   8192                 // 128 rows x 32 halfs
#define STAGE_B  (4 * TILE_B)         // Ahi, Alo, Whi, Wlo
#define GEMM_SMEM (2 * STAGE_B)       // 64 KB
#define NCHUNK   (DM / 32)            // 32

__global__ __launch_bounds__(256) void gemm_tc(GemmArgs ar) {
    extern __shared__ char sm[];
    const uint32_t sbase = smem_u32(sm);

    const int tid = threadIdx.x;
    const int wid = tid >> 5;
    const int lid = tid & 31;
    const int z = blockIdx.z;

    const __half* xhi = ar.xhi + (size_t)z * ar.xstride;
    const __half* xlo = ar.xlo + (size_t)z * ar.xstride;
    const __half* whi = ar.whi + (size_t)z * ar.wstride;
    const __half* wlo = ar.wlo + (size_t)z * ar.wstride;
    const float* bias = (z == 0) ? ar.b0 : ((z == 1) ? ar.b1 : ar.b2);
    float* out = (z == 0) ? ar.o0 : ((z == 1) ? ar.o1 : ar.o2);

    const int bm = blockIdx.y * 128;
    const int bn = blockIdx.x * 128;

    // loader mapping: 2 x float4 per tile per thread
    const int lrow0 = tid >> 2;            // 0..63
    const int lseg  = tid & 3;             // 16B segment
    const uint32_t soff0 = swz64((uint32_t)(lrow0 * 64 + lseg * 16));
    const uint32_t soff1 = swz64((uint32_t)((lrow0 + 64) * 64 + lseg * 16));

    auto load_stage = [&](int chunk, int stage) {
        const int k0 = chunk * 32 + lseg * 8;
        const uint32_t st = sbase + stage * STAGE_B;
        const size_t ga0 = (size_t)(bm + lrow0) * DM + k0;
        const size_t ga1 = (size_t)(bm + lrow0 + 64) * DM + k0;
        const size_t gw0 = (size_t)(bn + lrow0) * DM + k0;
        const size_t gw1 = (size_t)(bn + lrow0 + 64) * DM + k0;
        cp_async16(st + soff0,              xhi + ga0);
        cp_async16(st + soff1,              xhi + ga1);
        cp_async16(st + TILE_B + soff0,     xlo + ga0);
        cp_async16(st + TILE_B + soff1,     xlo + ga1);
        cp_async16(st + 2 * TILE_B + soff0, whi + gw0);
        cp_async16(st + 2 * TILE_B + soff1, whi + gw1);
        cp_async16(st + 3 * TILE_B + soff0, wlo + gw0);
        cp_async16(st + 3 * TILE_B + soff1, wlo + gw1);
    };

    // warp tiling: 4 (M) x 2 (N) warps; warp tile 32x64
    const int wm = wid & 3;       // row block of 32
    const int wn = wid >> 2;      // col block of 64

    // ldmatrix lane addressing (row-in-16 and 16B column select)
    const int lm_row = (lid & 7) + 8 * ((lid >> 3) & 1);
    const int lm_cb  = 16 * (lid >> 4);

    float acc[2][8][4];
#pragma unroll
    for (int i = 0; i < 2; i++)
#pragma unroll
        for (int j = 0; j < 8; j++)
#pragma unroll
            for (int k = 0; k < 4; k++) acc[i][j][k] = 0.0f;

    load_stage(0, 0); cp_commit();
    load_stage(1, 1); cp_commit();

    for (int c = 0; c < NCHUNK; c++) {
        cp_wait1();
        __syncthreads();
        const uint32_t st = sbase + (c & 1) * STAGE_B;

#pragma unroll
        for (int ks = 0; ks < 2; ks++) {
            const int cb = ks * 32 + lm_cb;

            uint32_t ahi[2][4], alo[2][4];
#pragma unroll
            for (int mi = 0; mi < 2; mi++) {
                int row = wm * 32 + mi * 16 + lm_row;
                uint32_t off = swz64((uint32_t)(row * 64 + cb));
                ldsm4(ahi[mi], st + off);
                ldsm4(alo[mi], st + TILE_B + off);
            }
            uint32_t bhi[8][2], blo[8][2];
#pragma unroll
            for (int j = 0; j < 4; j++) {
                int row = wn * 64 + j * 16 + lm_row;
                uint32_t off = swz64((uint32_t)(row * 64 + cb));
                uint32_t r[4];
                ldsm4(r, st + 2 * TILE_B + off);
                bhi[2 * j][0] = r[0]; bhi[2 * j][1] = r[2];
                bhi[2 * j + 1][0] = r[1]; bhi[2 * j + 1][1] = r[3];
                ldsm4(r, st + 3 * TILE_B + off);
                blo[2 * j][0] = r[0]; blo[2 * j][1] = r[2];
                blo[2 * j + 1][0] = r[1]; blo[2 * j + 1][1] = r[3];
            }

            // hi*hi, then lo*hi, then hi*lo — reuse distance 16 on each accumulator
#pragma unroll
            for (int mi = 0; mi < 2; mi++)
#pragma unroll
                for (int ni = 0; ni < 8; ni++)
                    mma16816(acc[mi][ni], ahi[mi], bhi[ni]);
#pragma unroll
            for (int mi = 0; mi < 2; mi++)
#pragma unroll
                for (int ni = 0; ni < 8; ni++)
                    mma16816(acc[mi][ni], alo[mi], bhi[ni]);
#pragma unroll
            for (int mi = 0; mi < 2; mi++)
#pragma unroll
                for (int ni = 0; ni < 8; ni++)
                    mma16816(acc[mi][ni], ahi[mi], blo[ni]);
        }

        __syncthreads();
        if (c + 2 < NCHUNK) load_stage(c + 2, (c & 1));
        cp_commit();   // empty group when nothing loaded keeps wait counting uniform
    }

    // Epilogue: c frag thread mapping: rows (lid>>2) and +8; cols (lid&3)*2
    const int rbase = bm + wm * 32 + (lid >> 2);
    const int cbase = bn + wn * 64 + (lid & 3) * 2;
#pragma unroll
    for (int mi = 0; mi < 2; mi++) {
#pragma unroll
        for (int ni = 0; ni < 8; ni++) {
            int col = cbase + ni * 8;
            float bx = bias[col], by = bias[col + 1];
            int r0 = rbase + mi * 16;
            float2 v0 = make_float2(acc[mi][ni][0] + bx, acc[mi][ni][1] + by);
            float2 v1 = make_float2(acc[mi][ni][2] + bx, acc[mi][ni][3] + by);
            *(float2*)(out + (size_t)r0 * DM + col) = v0;
            *(float2*)(out + (size_t)(r0 + 8) * DM + col) = v1;
        }
    }
}

// ---------------------------------------------------------------------------
// Flash-style attention (fp32, one thread per query row)
// ---------------------------------------------------------------------------
__global__ __launch_bounds__(128) void attn_kernel()
{
    __shared__ float4 ks[64][16];
    __shared__ float4 vs[64][16];

    const int b = blockIdx.z;
    const int h = blockIdx.y;
    const int row = blockIdx.x * 128 + threadIdx.x;

    const size_t qoff = ((size_t)(b * SEQ + row)) * DM + h * DKH;
    const float scale = 0.125f;

    float4 q[16];
#pragma unroll
    for (int i = 0; i < 16; i++) {
        float4 t = *(const float4*)(g_q + qoff + i * 4);
        q[i].x = t.x * scale; q[i].y = t.y * scale;
        q[i].z = t.z * scale; q[i].w = t.w * scale;
    }

    float o[64];
#pragma unroll
    for (int i = 0; i < 64; i++) o[i] = 0.0f;
    float m = -1e30f, l = 0.0f;

    for (int kv0 = 0; kv0 < SEQ; kv0 += 64) {
        __syncthreads();
        for (int i = threadIdx.x; i < 64 * 16; i += 128) {
            int j = i >> 4;
            int dq = i & 15;
            size_t g = ((size_t)(b * SEQ + kv0 + j)) * DM + h * DKH + dq * 4;
            ks[j][dq] = *(const float4*)(g_k + g);
            vs[j][dq] = *(const float4*)(g_v + g);
        }
        __syncthreads();

#pragma unroll 1
        for (int c0 = 0; c0 < 64; c0 += 16) {
            float s[16];
#pragma unroll
            for (int c = 0; c < 16; c++) {
                float ax = 0.f, ay = 0.f, az = 0.f, aw = 0.f;
#pragma unroll
                for (int i = 0; i < 16; i++) {
                    float4 kk = ks[c0 + c][i];
                    ax = fmaf(q[i].x, kk.x, ax);
                    ay = fmaf(q[i].y, kk.y, ay);
                    az = fmaf(q[i].z, kk.z, az);
                    aw = fmaf(q[i].w, kk.w, aw);
                }
                s[c] = (ax + ay) + (az + aw);
            }

            float mc = s[0];
#pragma unroll
            for (int c = 1; c < 16; c++) mc = fmaxf(mc, s[c]);
            float mnew = fmaxf(m, mc);
            float corr = __expf(m - mnew);
            m = mnew;
            l *= corr;
#pragma unroll
            for (int i = 0; i < 64; i++) o[i] *= corr;

#pragma unroll
            for (int c = 0; c < 16; c++) {
                float p = __expf(s[c] - m);
                l += p;
#pragma unroll
                for (int i = 0; i < 16; i++) {
                    float4 vv = vs[c0 + c][i];
                    o[4 * i + 0] = fmaf(p, vv.x, o[4 * i + 0]);
                    o[4 * i + 1] = fmaf(p, vv.y, o[4 * i + 1]);
                    o[4 * i + 2] = fmaf(p, vv.z, o[4 * i + 2]);
                    o[4 * i + 3] = fmaf(p, vv.w, o[4 * i + 3]);
                }
            }
        }
    }

    const float inv = 1.0f / l;
    float* outp = g_ctx + qoff;
#pragma unroll
    for (int i = 0; i < 16; i++) {
        float4 t;
        t.x = o[4 * i + 0] * inv;
        t.y = o[4 * i + 1] * inv;
        t.z = o[4 * i + 2] * inv;
        t.w = o[4 * i + 3] * inv;
        *(float4*)(outp + i * 4) = t;
    }
}

// ---------------------------------------------------------------------------
extern "C" void kernel_launch(void* const* d_in, const int* in_sizes, int n_in,
                              void* d_out, int out_size)
{
    const float* query = (const float*)d_in[0];
    const float* key   = (const float*)d_in[1];
    const float* value = (const float*)d_in[2];
    const float* Wq    = (const float*)d_in[3];
    const float* bq    = (const float*)d_in[4];
    const float* Wk    = (const float*)d_in[5];
    const float* bk    = (const float*)d_in[6];
    const float* Wv    = (const float*)d_in[7];
    const float* bv    = (const float*)d_in[8];
    const float* Wo    = (const float*)d_in[9];
    const float* bo    = (const float*)d_in[10];

    float *qp, *kp, *vp, *cp;
    __half *xhi, *xlo, *whi, *wlo, *chi, *clo;
    cudaGetSymbolAddress((void**)&qp, g_q);
    cudaGetSymbolAddress((void**)&kp, g_k);
    cudaGetSymbolAddress((void**)&vp, g_v);
    cudaGetSymbolAddress((void**)&cp, g_ctx);
    cudaGetSymbolAddress((void**)&xhi, g_xhi);
    cudaGetSymbolAddress((void**)&xlo, g_xlo);
    cudaGetSymbolAddress((void**)&whi, g_whi);
    cudaGetSymbolAddress((void**)&wlo, g_wlo);
    cudaGetSymbolAddress((void**)&chi, g_chi);
    cudaGetSymbolAddress((void**)&clo, g_clo);

    cudaFuncSetAttribute(gemm_tc, cudaFuncAttributeMaxDynamicSharedMemorySize, GEMM_SMEM);

    const size_t XN = (size_t)MTOK * DM;
    const size_t WN = (size_t)DM * DM;
    const int xn4 = (int)(XN / 4), wn4 = (int)(WN / 4);

    split_f16<<<(xn4 + 255) / 256, 256>>>(query, xhi + 0 * XN, xlo + 0 * XN, xn4);
    split_f16<<<(xn4 + 255) / 256, 256>>>(key,   xhi + 1 * XN, xlo + 1 * XN, xn4);
    split_f16<<<(xn4 + 255) / 256, 256>>>(value, xhi + 2 * XN, xlo + 2 * XN, xn4);
    split_f16<<<(wn4 + 255) / 256, 256>>>(Wq, whi + 0 * WN, wlo + 0 * WN, wn4);
    split_f16<<<(wn4 + 255) / 256, 256>>>(Wk, whi + 1 * WN, wlo + 1 * WN, wn4);
    split_f16<<<(wn4 + 255) / 256, 256>>>(Wv, whi + 2 * WN, wlo + 2 * WN, wn4);
    split_f16<<<(wn4 + 255) / 256, 256>>>(Wo, whi + 3 * WN, wlo + 3 * WN, wn4);

    GemmArgs qkv;
    qkv.xhi = xhi; qkv.xlo = xlo; qkv.whi = whi; qkv.wlo = wlo;
    qkv.b0 = bq; qkv.b1 = bk; qkv.b2 = bv;
    qkv.o0 = qp; qkv.o1 = kp; qkv.o2 = vp;
    qkv.xstride = (long long)XN; qkv.wstride = (long long)WN;
    gemm_tc<<<dim3(DM / 128, MTOK / 128, 3), 256, GEMM_SMEM>>>(qkv);

    attn_kernel<<<dim3(SEQ / 128, NH, NB), 128>>>();

    split_f16<<<(xn4 + 255) / 256, 256>>>(cp, chi, clo, xn4);

    GemmArgs og;
    og.xhi = chi; og.xlo = clo; og.whi = whi + 3 * WN; og.wlo = wlo + 3 * WN;
    og.b0 = bo; og.b1 = bo; og.b2 = bo;
    og.o0 = (float*)d_out; og.o1 = (float*)d_out; og.o2 = (float*)d_out;
    og.xstride = 0; og.wstride = 0;
    gemm_tc<<<dim3(DM / 128, MTOK / 128, 1), 256, GEMM_SMEM>>>(og);
}

// round 7
// speedup vs baseline: 1.9369x; 1.9369x over previous
#include <cuda_runtime.h>
#include <cuda_fp16.h>
#include <math.h>
#include <stdint.h>

#define NH   16
#define DKH  64
#define DM   1024
#define NB   2
#define SEQ  2048
#define MTOK (NB * SEQ)   // 4096

// ---------------------------------------------------------------------------
// Device scratch
// ---------------------------------------------------------------------------
__device__ float g_q[(size_t)MTOK * DM];
__device__ float g_k[(size_t)MTOK * DM];
__device__ float g_v[(size_t)MTOK * DM];
__device__ float g_ctx[(size_t)MTOK * DM];

// ---------------------------------------------------------------------------
// fp32 GEMM (NT): C[M,N] = A[M,K] * W[N,K]^T + bias[N]   (proven R0 kernel)
// ---------------------------------------------------------------------------
#define BM 128
#define BN 128
#define BK 16

__global__ __launch_bounds__(256) void gemm_nt_bias(
    const float* __restrict__ A, const float* __restrict__ W,
    const float* __restrict__ bias, float* __restrict__ C,
    int M, int N, int K)
{
    __shared__ float As[BK][BM + 4];
    __shared__ float Bs[BK][BN + 4];

    const int tid = threadIdx.x;
    const int bm = blockIdx.y * BM;
    const int bn = blockIdx.x * BN;
    const int tx = tid & 15;
    const int ty = tid >> 4;

    float acc[8][8];
#pragma unroll
    for (int i = 0; i < 8; i++)
#pragma unroll
        for (int j = 0; j < 8; j++) acc[i][j] = 0.0f;

    const int lr = tid >> 2;
    const int lk = (tid & 3) << 2;

    for (int k0 = 0; k0 < K; k0 += BK) {
#pragma unroll
        for (int r = 0; r < 2; r++) {
            int row = lr + r * 64;
            float4 a4 = *(const float4*)(A + (size_t)(bm + row) * K + k0 + lk);
            As[lk + 0][row] = a4.x;
            As[lk + 1][row] = a4.y;
            As[lk + 2][row] = a4.z;
            As[lk + 3][row] = a4.w;
            float4 b4 = *(const float4*)(W + (size_t)(bn + row) * K + k0 + lk);
            Bs[lk + 0][row] = b4.x;
            Bs[lk + 1][row] = b4.y;
            Bs[lk + 2][row] = b4.z;
            Bs[lk + 3][row] = b4.w;
        }
        __syncthreads();

#pragma unroll
        for (int k = 0; k < BK; k++) {
            float a[8], b[8];
            *(float4*)&a[0] = *(const float4*)&As[k][ty * 8];
            *(float4*)&a[4] = *(const float4*)&As[k][ty * 8 + 4];
            *(float4*)&b[0] = *(const float4*)&Bs[k][tx * 8];
            *(float4*)&b[4] = *(const float4*)&Bs[k][tx * 8 + 4];
#pragma unroll
            for (int i = 0; i < 8; i++)
#pragma unroll
                for (int j = 0; j < 8; j++)
                    acc[i][j] = fmaf(a[i], b[j], acc[i][j]);
        }
        __syncthreads();
    }

#pragma unroll
    for (int i = 0; i < 8; i++) {
        int row = bm + ty * 8 + i;
#pragma unroll
        for (int j = 0; j < 8; j += 4) {
            int col = bn + tx * 8 + j;
            float4 o;
            o.x = acc[i][j + 0] + bias[col + 0];
            o.y = acc[i][j + 1] + bias[col + 1];
            o.z = acc[i][j + 2] + bias[col + 2];
            o.w = acc[i][j + 3] + bias[col + 3];
            *(float4*)(C + (size_t)row * N + col) = o;
        }
    }
}

// ---------------------------------------------------------------------------
// Tensor-core flash attention (mma.sync m16n8k16, split-fp16, online softmax)
// ---------------------------------------------------------------------------
__device__ __forceinline__ uint32_t smem_u32(const void* p) {
    uint32_t a;
    asm("{ .reg .u64 t; cvta.to.shared.u64 t, %1; cvt.u32.u64 %0, t; }" : "=r"(a) : "l"(p));
    return a;
}
__device__ __forceinline__ void ldsm4(uint32_t* r, uint32_t addr) {
    asm volatile("ldmatrix.sync.aligned.m8n8.x4.shared.b16 {%0,%1,%2,%3}, [%4];"
                 : "=r"(r[0]), "=r"(r[1]), "=r"(r[2]), "=r"(r[3]) : "r"(addr));
}
__device__ __forceinline__ void ldsm4t(uint32_t* r, uint32_t addr) {
    asm volatile("ldmatrix.sync.aligned.m8n8.x4.trans.shared.b16 {%0,%1,%2,%3}, [%4];"
                 : "=r"(r[0]), "=r"(r[1]), "=r"(r[2]), "=r"(r[3]) : "r"(addr));
}
__device__ __forceinline__ void mma16816(float* c, const uint32_t* a, const uint32_t* b) {
    asm volatile(
        "mma.sync.aligned.m16n8k16.row.col.f32.f16.f16.f32 "
        "{%0,%1,%2,%3}, {%4,%5,%6,%7}, {%8,%9}, {%0,%1,%2,%3};"
        : "+f"(c[0]), "+f"(c[1]), "+f"(c[2]), "+f"(c[3])
        : "r"(a[0]), "r"(a[1]), "r"(a[2]), "r"(a[3]), "r"(b[0]), "r"(b[1]));
}
__device__ __forceinline__ float ex2f(float x) {
    float y;
    asm("ex2.approx.f32 %0, %1;" : "=f"(y) : "f"(x));
    return y;
}
__device__ __forceinline__ uint32_t h2u(__half2 h) {
    return *reinterpret_cast<uint32_t*>(&h);
}

// smem byte offsets (from 1024-aligned base); 128x64 half tiles, 128B rows, SW128
#define SQ_HI 0
#define SQ_LO 16384
#define SK_HI 32768
#define SK_LO 49152
#define SV_HI 65536
#define SV_LO 81920
#define ATTN_SMEM (96 * 1024 + 1024)

// 0.125 (1/sqrt(dk)) * log2(e), folded into Q so softmax runs in base-2
#define QSCALE 0.18033688f

__global__ __launch_bounds__(256) void attn_mma()
{
    extern __shared__ char sm_raw[];
    const uint32_t sraw = smem_u32(sm_raw);
    const uint32_t sbase = (sraw + 1023u) & ~1023u;
    char* smp = sm_raw + (sbase - sraw);

    const int tid = threadIdx.x;
    const int wid = tid >> 5;
    const int lid = tid & 31;
    const int b = blockIdx.z;
    const int h = blockIdx.y;
    const int q0 = blockIdx.x * 128;

    // ---- conversion mapping: row = tid>>1 (0..127), colbase = (tid&1)*32 ----
    const int crow = tid >> 1;
    const int ccol = (tid & 1) * 32;
    const uint32_t coff = (uint32_t)(crow * 128 + ccol * 2);
    const uint32_t csw = ((uint32_t)(crow & 7)) << 4;

    // ---- stage Q (scaled + split) ----
    {
        const float* src = g_q + ((size_t)(b * SEQ + q0 + crow)) * DM + h * DKH + ccol;
#pragma unroll
        for (int i = 0; i < 8; i++) {
            float4 f = *(const float4*)(src + 4 * i);
            f.x *= QSCALE; f.y *= QSCALE; f.z *= QSCALE; f.w *= QSCALE;
            __half2 h0 = __floats2half2_rn(f.x, f.y);
            __half2 h1 = __floats2half2_rn(f.z, f.w);
            float2 g0 = __half22float2(h0);
            float2 g1 = __half22float2(h1);
            __half2 l0 = __floats2half2_rn(f.x - g0.x, f.y - g0.y);
            __half2 l1 = __floats2half2_rn(f.z - g1.x, f.w - g1.y);
            uint32_t ad = (coff + 8 * i) ^ csw;
            *(__half2*)(smp + SQ_HI + ad) = h0;
            *(__half2*)(smp + SQ_HI + ad + 4) = h1;
            *(__half2*)(smp + SQ_LO + ad) = l0;
            *(__half2*)(smp + SQ_LO + ad + 4) = l1;
        }
    }
    __syncthreads();

    // ---- ldmatrix lane addressing ----
    // row within a 16-row tile handled by this lane, and its swizzle key
    const int lm_row = (lid & 7) + 8 * ((lid >> 3) & 1);
    const uint32_t rbyte = (uint32_t)(lm_row * 128);
    const uint32_t lsw = ((uint32_t)(lm_row & 7)) << 4;
    const uint32_t cpick = (uint32_t)(16 * (lid >> 4));   // 16B column select for x4

    // ---- per-warp Q fragments (rows wid*16..+15, all 64 dk) ----
    uint32_t aq_hi[4][4], aq_lo[4][4];
    {
        uint32_t qb_hi = sbase + SQ_HI + (uint32_t)(wid * 2048) + rbyte;
        uint32_t qb_lo = sbase + SQ_LO + (uint32_t)(wid * 2048) + rbyte;
#pragma unroll
        for (int kg = 0; kg < 4; kg++) {
            uint32_t cb = (cpick + kg * 32) ^ lsw;      // swizzle AFTER full column calc
            ldsm4(aq_hi[kg], qb_hi + cb);
            ldsm4(aq_lo[kg], qb_lo + cb);
        }
    }

    float m0 = -1e30f, m1 = -1e30f, l0 = 0.0f, l1 = 0.0f;
    float acc_o[8][4];
#pragma unroll
    for (int n = 0; n < 8; n++)
#pragma unroll
        for (int j = 0; j < 4; j++) acc_o[n][j] = 0.0f;

    const uint32_t kb_hi = sbase + SK_HI + rbyte, kb_lo = sbase + SK_LO + rbyte;
    const uint32_t vb_hi = sbase + SV_HI + rbyte, vb_lo = sbase + SV_LO + rbyte;

    for (int t = 0; t < SEQ / 128; t++) {
        const int kv0 = t * 128;
        __syncthreads();   // previous tile's reads complete before overwrite

        // ---- convert K and V tile (split fp16) ----
        {
            const size_t gro = ((size_t)(b * SEQ + kv0 + crow)) * DM + h * DKH + ccol;
            const float* ksrc = g_k + gro;
            const float* vsrc = g_v + gro;
#pragma unroll
            for (int i = 0; i < 8; i++) {
                uint32_t ad = (coff + 8 * i) ^ csw;
                float4 f = *(const float4*)(ksrc + 4 * i);
                __half2 h0 = __floats2half2_rn(f.x, f.y);
                __half2 h1 = __floats2half2_rn(f.z, f.w);
                float2 g0 = __half22float2(h0);
                float2 g1 = __half22float2(h1);
                *(__half2*)(smp + SK_HI + ad) = h0;
                *(__half2*)(smp + SK_HI + ad + 4) = h1;
                *(__half2*)(smp + SK_LO + ad) = __floats2half2_rn(f.x - g0.x, f.y - g0.y);
                *(__half2*)(smp + SK_LO + ad + 4) = __floats2half2_rn(f.z - g1.x, f.w - g1.y);

                f = *(const float4*)(vsrc + 4 * i);
                h0 = __floats2half2_rn(f.x, f.y);
                h1 = __floats2half2_rn(f.z, f.w);
                g0 = __half22float2(h0);
                g1 = __half22float2(h1);
                *(__half2*)(smp + SV_HI + ad) = h0;
                *(__half2*)(smp + SV_HI + ad + 4) = h1;
                *(__half2*)(smp + SV_LO + ad) = __floats2half2_rn(f.x - g0.x, f.y - g0.y);
                *(__half2*)(smp + SV_LO + ad + 4) = __floats2half2_rn(f.z - g1.x, f.w - g1.y);
            }
        }
        __syncthreads();

        // ---- QK^T: scores S[16 rows][128 keys] per warp, 3-term split ----
        float c[16][4];
#pragma unroll
        for (int j = 0; j < 16; j++)
#pragma unroll
            for (int q = 0; q < 4; q++) c[j][q] = 0.0f;

#pragma unroll
        for (int j2 = 0; j2 < 8; j2++) {
            const uint32_t rowoff = (uint32_t)(j2 * 2048);
#pragma unroll
            for (int kg = 0; kg < 4; kg++) {
                uint32_t cb = (cpick + kg * 32) ^ lsw;
                uint32_t rh[4], rl[4];
                ldsm4(rh, kb_hi + rowoff + cb);
                ldsm4(rl, kb_lo + rowoff + cb);
                uint32_t bh0[2] = { rh[0], rh[2] }, bh1[2] = { rh[1], rh[3] };
                uint32_t bl0[2] = { rl[0], rl[2] }, bl1[2] = { rl[1], rl[3] };
                mma16816(c[2 * j2],     aq_hi[kg], bh0);
                mma16816(c[2 * j2],     aq_hi[kg], bl0);
                mma16816(c[2 * j2],     aq_lo[kg], bh0);
                mma16816(c[2 * j2 + 1], aq_hi[kg], bh1);
                mma16816(c[2 * j2 + 1], aq_hi[kg], bl1);
                mma16816(c[2 * j2 + 1], aq_lo[kg], bh1);
            }
        }

        // ---- online softmax (base-2) ----
        float mx0 = -1e30f, mx1 = -1e30f;
#pragma unroll
        for (int j = 0; j < 16; j++) {
            mx0 = fmaxf(mx0, fmaxf(c[j][0], c[j][1]));
            mx1 = fmaxf(mx1, fmaxf(c[j][2], c[j][3]));
        }
        mx0 = fmaxf(mx0, __shfl_xor_sync(0xffffffffu, mx0, 1));
        mx0 = fmaxf(mx0, __shfl_xor_sync(0xffffffffu, mx0, 2));
        mx1 = fmaxf(mx1, __shfl_xor_sync(0xffffffffu, mx1, 1));
        mx1 = fmaxf(mx1, __shfl_xor_sync(0xffffffffu, mx1, 2));

        float mn0 = fmaxf(m0, mx0), mn1 = fmaxf(m1, mx1);
        float al0 = ex2f(m0 - mn0), al1 = ex2f(m1 - mn1);
        m0 = mn0; m1 = mn1;

        float rs0 = 0.0f, rs1 = 0.0f;
#pragma unroll
        for (int j = 0; j < 16; j++) {
            c[j][0] = ex2f(c[j][0] - mn0);
            c[j][1] = ex2f(c[j][1] - mn0);
            c[j][2] = ex2f(c[j][2] - mn1);
            c[j][3] = ex2f(c[j][3] - mn1);
            rs0 += c[j][0] + c[j][1];
            rs1 += c[j][2] + c[j][3];
        }
        rs0 += __shfl_xor_sync(0xffffffffu, rs0, 1);
        rs0 += __shfl_xor_sync(0xffffffffu, rs0, 2);
        rs1 += __shfl_xor_sync(0xffffffffu, rs1, 1);
        rs1 += __shfl_xor_sync(0xffffffffu, rs1, 2);
        l0 = l0 * al0 + rs0;
        l1 = l1 * al1 + rs1;

#pragma unroll
        for (int n = 0; n < 8; n++) {
            acc_o[n][0] *= al0; acc_o[n][1] *= al0;
            acc_o[n][2] *= al1; acc_o[n][3] *= al1;
        }

        // ---- PV: ctx += P[16 x 128] * V[128 x 64], 3-term split ----
#pragma unroll
        for (int kg = 0; kg < 8; kg++) {
            uint32_t phi[4], plo[4];
#pragma unroll
            for (int q = 0; q < 2; q++) {
                float p0 = c[2 * kg + q][0], p1 = c[2 * kg + q][1];
                float p2 = c[2 * kg + q][2], p3 = c[2 * kg + q][3];
                __half2 hA = __floats2half2_rn(p0, p1);
                __half2 hB = __floats2half2_rn(p2, p3);
                float2 fA = __half22float2(hA);
                float2 fB = __half22float2(hB);
                phi[2 * q]     = h2u(hA);
                phi[2 * q + 1] = h2u(hB);
                plo[2 * q]     = h2u(__floats2half2_rn(p0 - fA.x, p1 - fA.y));
                plo[2 * q + 1] = h2u(__floats2half2_rn(p2 - fB.x, p3 - fB.y));
            }
            // A frag order: a0 (r, klow), a1 (r+8, klow), a2 (r, khigh), a3 (r+8, khigh)
            uint32_t af_hi[4] = { phi[0], phi[1], phi[2], phi[3] };
            uint32_t af_lo[4] = { plo[0], plo[1], plo[2], plo[3] };

            const uint32_t kvoff = (uint32_t)(kg * 2048);
#pragma unroll
            for (int d2 = 0; d2 < 4; d2++) {
                uint32_t cb = (cpick + d2 * 32) ^ lsw;
                uint32_t rhv[4], rlv[4];
                ldsm4t(rhv, vb_hi + kvoff + cb);
                ldsm4t(rlv, vb_lo + kvoff + cb);
                uint32_t bh0[2] = { rhv[0], rhv[1] }, bh1[2] = { rhv[2], rhv[3] };
                uint32_t bl0[2] = { rlv[0], rlv[1] }, bl1[2] = { rlv[2], rlv[3] };
                mma16816(acc_o[2 * d2],     af_hi, bh0);
                mma16816(acc_o[2 * d2],     af_hi, bl0);
                mma16816(acc_o[2 * d2],     af_lo, bh0);
                mma16816(acc_o[2 * d2 + 1], af_hi, bh1);
                mma16816(acc_o[2 * d2 + 1], af_hi, bl1);
                mma16816(acc_o[2 * d2 + 1], af_lo, bh1);
            }
        }
    }

    // ---- normalize + store ctx (layout [b, s, h*64+d]) ----
    const float inv0 = 1.0f / l0;
    const float inv1 = 1.0f / l1;
    const int gr0 = q0 + wid * 16 + (lid >> 2);
    const int gr1 = gr0 + 8;
    const int colb = h * DKH + (lid & 3) * 2;
#pragma unroll
    for (int n = 0; n < 8; n++) {
        int col = colb + n * 8;
        float2 v0 = make_float2(acc_o[n][0] * inv0, acc_o[n][1] * inv0);
        float2 v1 = make_float2(acc_o[n][2] * inv1, acc_o[n][3] * inv1);
        *(float2*)(g_ctx + (size_t)(b * SEQ + gr0) * DM + col) = v0;
        *(float2*)(g_ctx + (size_t)(b * SEQ + gr1) * DM + col) = v1;
    }
}

// ---------------------------------------------------------------------------
extern "C" void kernel_launch(void* const* d_in, const int* in_sizes, int n_in,
                              void* d_out, int out_size)
{
    const float* query = (const float*)d_in[0];
    const float* key   = (const float*)d_in[1];
    const float* value = (const float*)d_in[2];
    const float* Wq    = (const float*)d_in[3];
    const float* bq    = (const float*)d_in[4];
    const float* Wk    = (const float*)d_in[5];
    const float* bk    = (const float*)d_in[6];
    const float* Wv    = (const float*)d_in[7];
    const float* bv    = (const float*)d_in[8];
    const float* Wo    = (const float*)d_in[9];
    const float* bo    = (const float*)d_in[10];

    float *qp, *kp, *vp, *cp;
    cudaGetSymbolAddress((void**)&qp, g_q);
    cudaGetSymbolAddress((void**)&kp, g_k);
    cudaGetSymbolAddress((void**)&vp, g_v);
    cudaGetSymbolAddress((void**)&cp, g_ctx);

    cudaFuncSetAttribute(attn_mma, cudaFuncAttributeMaxDynamicSharedMemorySize, ATTN_SMEM);

    dim3 gemm_grid(DM / BN, MTOK / BM);   // (8, 32)
    gemm_nt_bias<<<gemm_grid, 256>>>(query, Wq, bq, qp, MTOK, DM, DM);
    gemm_nt_bias<<<gemm_grid, 256>>>(key,   Wk, bk, kp, MTOK, DM, DM);
    gemm_nt_bias<<<gemm_grid, 256>>>(value, Wv, bv, vp, MTOK, DM, DM);

    attn_mma<<<dim3(SEQ / 128, NH, NB), 256, ATTN_SMEM>>>();

    gemm_nt_bias<<<gemm_grid, 256>>>(cp, Wo, bo, (float*)d_out, MTOK, DM, DM);
}

// round 8
// speedup vs baseline: 3.0120x; 1.5550x over previous
#include <cuda_runtime.h>
#include <cuda_fp16.h>
#include <math.h>
#include <stdint.h>

#define NH   16
#define DKH  64
#define DM   1024
#define NB   2
#define SEQ  2048
#define MTOK (NB * SEQ)   // 4096

// ---------------------------------------------------------------------------
// Device scratch
// ---------------------------------------------------------------------------
__device__ float g_q[(size_t)MTOK * DM];
__device__ float g_k[(size_t)MTOK * DM];
__device__ float g_v[(size_t)MTOK * DM];

__device__ __half g_xhi[(size_t)3 * MTOK * DM];   // split q,k,v inputs
__device__ __half g_xlo[(size_t)3 * MTOK * DM];
__device__ __half g_whi[(size_t)4 * DM * DM];     // split Wq,Wk,Wv,Wo
__device__ __half g_wlo[(size_t)4 * DM * DM];
__device__ __half g_chi[(size_t)MTOK * DM];       // split ctx (written by attn)
__device__ __half g_clo[(size_t)MTOK * DM];

// ---------------------------------------------------------------------------
// PTX helpers (sm_80+ portable ISA)
// ---------------------------------------------------------------------------
__device__ __forceinline__ uint32_t smem_u32(const void* p) {
    uint32_t a;
    asm("{ .reg .u64 t; cvta.to.shared.u64 t, %1; cvt.u32.u64 %0, t; }" : "=r"(a) : "l"(p));
    return a;
}
__device__ __forceinline__ void cp_async16(uint32_t dst, const void* src) {
    asm volatile("cp.async.cg.shared.global [%0], [%1], 16;" :: "r"(dst), "l"(src));
}
__device__ __forceinline__ void cp_commit() {
    asm volatile("cp.async.commit_group;");
}
__device__ __forceinline__ void cp_wait2() {
    asm volatile("cp.async.wait_group 2;");
}
__device__ __forceinline__ void ldsm4(uint32_t* r, uint32_t addr) {
    asm volatile("ldmatrix.sync.aligned.m8n8.x4.shared.b16 {%0,%1,%2,%3}, [%4];"
                 : "=r"(r[0]), "=r"(r[1]), "=r"(r[2]), "=r"(r[3]) : "r"(addr));
}
__device__ __forceinline__ void ldsm4t(uint32_t* r, uint32_t addr) {
    asm volatile("ldmatrix.sync.aligned.m8n8.x4.trans.shared.b16 {%0,%1,%2,%3}, [%4];"
                 : "=r"(r[0]), "=r"(r[1]), "=r"(r[2]), "=r"(r[3]) : "r"(addr));
}
__device__ __forceinline__ void mma16816(float* c, const uint32_t* a, const uint32_t* b) {
    asm volatile(
        "mma.sync.aligned.m16n8k16.row.col.f32.f16.f16.f32 "
        "{%0,%1,%2,%3}, {%4,%5,%6,%7}, {%8,%9}, {%0,%1,%2,%3};"
        : "+f"(c[0]), "+f"(c[1]), "+f"(c[2]), "+f"(c[3])
        : "r"(a[0]), "r"(a[1]), "r"(a[2]), "r"(a[3]), "r"(b[0]), "r"(b[1]));
}
__device__ __forceinline__ float ex2f(float x) {
    float y;
    asm("ex2.approx.f32 %0, %1;" : "=f"(y) : "f"(x));
    return y;
}
__device__ __forceinline__ uint32_t h2u(__half2 h) {
    return *reinterpret_cast<uint32_t*>(&h);
}
// Swizzle for 64-byte rows (32 halfs) — verified by passing R4 GEMM
__device__ __forceinline__ uint32_t swz64(uint32_t off) {
    return off ^ (((off >> 7) & 3u) << 4);
}

// ---------------------------------------------------------------------------
// Split-fp16 conversion: hi = f16(x), lo = f16(x - hi)
// ---------------------------------------------------------------------------
__global__ __launch_bounds__(256) void split_f16(const float* __restrict__ src,
                                                 __half* __restrict__ hi,
                                                 __half* __restrict__ lo, int n4) {
    int i = blockIdx.x * blockDim.x + threadIdx.x;
    if (i >= n4) return;
    float4 v = ((const float4*)src)[i];
    __half h0 = __float2half_rn(v.x), h1 = __float2half_rn(v.y);
    __half h2 = __float2half_rn(v.z), h3 = __float2half_rn(v.w);
    __half l0 = __float2half_rn(v.x - __half2float(h0));
    __half l1 = __float2half_rn(v.y - __half2float(h1));
    __half l2 = __float2half_rn(v.z - __half2float(h2));
    __half l3 = __float2half_rn(v.w - __half2float(h3));
    ((__half2*)hi)[2 * i]     = __halves2half2(h0, h1);
    ((__half2*)hi)[2 * i + 1] = __halves2half2(h2, h3);
    ((__half2*)lo)[2 * i]     = __halves2half2(l0, l1);
    ((__half2*)lo)[2 * i + 1] = __halves2half2(l2, l3);
}

// ---------------------------------------------------------------------------
// mma.sync split-fp16 GEMM (NT): C = A[M,K]*W[N,K]^T + bias
// 128x128 tile, BK=32, 8 warps (32x64 warp tile), 3-stage cp.async, 2 CTAs/SM.
// ---------------------------------------------------------------------------
struct GemmArgs {
    const __half *xhi, *xlo, *whi, *wlo;
    const float *b0, *b1, *b2;
    float *o0, *o1, *o2;
    long long xstride, wstride;
};

#define TILE_B   8192                 // 128 rows x 32 halfs
#define STAGE_B  (4 * TILE_B)         // Ahi, Alo, Whi, Wlo = 32 KB
#define NSTAGE   3
#define GEMM_SMEM (NSTAGE * STAGE_B)  // 96 KB
#define NCHUNK   (DM / 32)            // 32

__global__ __launch_bounds__(256, 2) void gemm_tc(GemmArgs ar) {
    extern __shared__ char sm[];
    const uint32_t sbase = smem_u32(sm);

    const int tid = threadIdx.x;
    const int wid = tid >> 5;
    const int lid = tid & 31;
    const int z = blockIdx.z;

    const __half* xhi = ar.xhi + (size_t)z * ar.xstride;
    const __half* xlo = ar.xlo + (size_t)z * ar.xstride;
    const __half* whi = ar.whi + (size_t)z * ar.wstride;
    const __half* wlo = ar.wlo + (size_t)z * ar.wstride;
    const float* bias = (z == 0) ? ar.b0 : ((z == 1) ? ar.b1 : ar.b2);
    float* out = (z == 0) ? ar.o0 : ((z == 1) ? ar.o1 : ar.o2);

    const int bm = blockIdx.y * 128;
    const int bn = blockIdx.x * 128;

    // loader mapping: 2 x float4 per tile per thread
    const int lrow0 = tid >> 2;
    const int lseg  = tid & 3;
    const uint32_t soff0 = swz64((uint32_t)(lrow0 * 64 + lseg * 16));
    const uint32_t soff1 = swz64((uint32_t)((lrow0 + 64) * 64 + lseg * 16));

    auto load_stage = [&](int chunk, int stage) {
        const int k0 = chunk * 32 + lseg * 8;
        const uint32_t st = sbase + stage * STAGE_B;
        const size_t ga0 = (size_t)(bm + lrow0) * DM + k0;
        const size_t ga1 = (size_t)(bm + lrow0 + 64) * DM + k0;
        const size_t gw0 = (size_t)(bn + lrow0) * DM + k0;
        const size_t gw1 = (size_t)(bn + lrow0 + 64) * DM + k0;
        cp_async16(st + soff0,              xhi + ga0);
        cp_async16(st + soff1,              xhi + ga1);
        cp_async16(st + TILE_B + soff0,     xlo + ga0);
        cp_async16(st + TILE_B + soff1,     xlo + ga1);
        cp_async16(st + 2 * TILE_B + soff0, whi + gw0);
        cp_async16(st + 2 * TILE_B + soff1, whi + gw1);
        cp_async16(st + 3 * TILE_B + soff0, wlo + gw0);
        cp_async16(st + 3 * TILE_B + soff1, wlo + gw1);
    };

    // warp tiling: 4 (M) x 2 (N), warp tile 32x64
    const int wm = wid & 3;
    const int wn = wid >> 2;
    const int lm_row = (lid & 7) + 8 * ((lid >> 3) & 1);
    const int lm_cb  = 16 * (lid >> 4);

    float acc[2][8][4];
#pragma unroll
    for (int i = 0; i < 2; i++)
#pragma unroll
        for (int j = 0; j < 8; j++)
#pragma unroll
            for (int k = 0; k < 4; k++) acc[i][j][k] = 0.0f;

    load_stage(0, 0); cp_commit();
    load_stage(1, 1); cp_commit();
    load_stage(2, 2); cp_commit();

    for (int c = 0; c < NCHUNK; c++) {
        cp_wait2();
        __syncthreads();
        const uint32_t st = sbase + (uint32_t)(c % 3) * STAGE_B;

#pragma unroll
        for (int ks = 0; ks < 2; ks++) {
            const int cb = ks * 32 + lm_cb;

            uint32_t ahi[2][4], alo[2][4];
#pragma unroll
            for (int mi = 0; mi < 2; mi++) {
                uint32_t off = swz64((uint32_t)((wm * 32 + mi * 16 + lm_row) * 64 + cb));
                ldsm4(ahi[mi], st + off);
                ldsm4(alo[mi], st + TILE_B + off);
            }
#pragma unroll
            for (int j = 0; j < 4; j++) {
                uint32_t off = swz64((uint32_t)((wn * 64 + j * 16 + lm_row) * 64 + cb));
                uint32_t rh[4], rl[4];
                ldsm4(rh, st + 2 * TILE_B + off);
                ldsm4(rl, st + 3 * TILE_B + off);
                uint32_t bh0[2] = { rh[0], rh[2] }, bh1[2] = { rh[1], rh[3] };
                uint32_t bl0[2] = { rl[0], rl[2] }, bl1[2] = { rl[1], rl[3] };
#pragma unroll
                for (int mi = 0; mi < 2; mi++) {
                    mma16816(acc[mi][2 * j],     ahi[mi], bh0);
                    mma16816(acc[mi][2 * j],     alo[mi], bh0);
                    mma16816(acc[mi][2 * j],     ahi[mi], bl0);
                    mma16816(acc[mi][2 * j + 1], ahi[mi], bh1);
                    mma16816(acc[mi][2 * j + 1], alo[mi], bh1);
                    mma16816(acc[mi][2 * j + 1], ahi[mi], bl1);
                }
            }
        }

        __syncthreads();
        if (c + 3 < NCHUNK) load_stage(c + 3, c % 3);
        cp_commit();
    }

    const int rbase = bm + wm * 32 + (lid >> 2);
    const int cbase = bn + wn * 64 + (lid & 3) * 2;
#pragma unroll
    for (int mi = 0; mi < 2; mi++) {
#pragma unroll
        for (int ni = 0; ni < 8; ni++) {
            int col = cbase + ni * 8;
            float bx = bias[col], by = bias[col + 1];
            int r0 = rbase + mi * 16;
            float2 v0 = make_float2(acc[mi][ni][0] + bx, acc[mi][ni][1] + by);
            float2 v1 = make_float2(acc[mi][ni][2] + bx, acc[mi][ni][3] + by);
            *(float2*)(out + (size_t)r0 * DM + col) = v0;
            *(float2*)(out + (size_t)(r0 + 8) * DM + col) = v1;
        }
    }
}

// ---------------------------------------------------------------------------
// Tensor-core flash attention (unchanged from R7 except split-ctx epilogue)
// ---------------------------------------------------------------------------
#define SQ_HI 0
#define SQ_LO 16384
#define SK_HI 32768
#define SK_LO 49152
#define SV_HI 65536
#define SV_LO 81920
#define ATTN_SMEM (96 * 1024 + 1024)

#define QSCALE 0.18033688f   // (1/8) * log2(e)

__global__ __launch_bounds__(256) void attn_mma()
{
    extern __shared__ char sm_raw[];
    const uint32_t sraw = smem_u32(sm_raw);
    const uint32_t sbase = (sraw + 1023u) & ~1023u;
    char* smp = sm_raw + (sbase - sraw);

    const int tid = threadIdx.x;
    const int wid = tid >> 5;
    const int lid = tid & 31;
    const int b = blockIdx.z;
    const int h = blockIdx.y;
    const int q0 = blockIdx.x * 128;

    const int crow = tid >> 1;
    const int ccol = (tid & 1) * 32;
    const uint32_t coff = (uint32_t)(crow * 128 + ccol * 2);
    const uint32_t csw = ((uint32_t)(crow & 7)) << 4;

    {
        const float* src = g_q + ((size_t)(b * SEQ + q0 + crow)) * DM + h * DKH + ccol;
#pragma unroll
        for (int i = 0; i < 8; i++) {
            float4 f = *(const float4*)(src + 4 * i);
            f.x *= QSCALE; f.y *= QSCALE; f.z *= QSCALE; f.w *= QSCALE;
            __half2 h0 = __floats2half2_rn(f.x, f.y);
            __half2 h1 = __floats2half2_rn(f.z, f.w);
            float2 g0 = __half22float2(h0);
            float2 g1 = __half22float2(h1);
            __half2 l0 = __floats2half2_rn(f.x - g0.x, f.y - g0.y);
            __half2 l1 = __floats2half2_rn(f.z - g1.x, f.w - g1.y);
            uint32_t ad = (coff + 8 * i) ^ csw;
            *(__half2*)(smp + SQ_HI + ad) = h0;
            *(__half2*)(smp + SQ_HI + ad + 4) = h1;
            *(__half2*)(smp + SQ_LO + ad) = l0;
            *(__half2*)(smp + SQ_LO + ad + 4) = l1;
        }
    }
    __syncthreads();

    const int lm_row = (lid & 7) + 8 * ((lid >> 3) & 1);
    const uint32_t rbyte = (uint32_t)(lm_row * 128);
    const uint32_t lsw = ((uint32_t)(lm_row & 7)) << 4;
    const uint32_t cpick = (uint32_t)(16 * (lid >> 4));

    uint32_t aq_hi[4][4], aq_lo[4][4];
    {
        uint32_t qb_hi = sbase + SQ_HI + (uint32_t)(wid * 2048) + rbyte;
        uint32_t qb_lo = sbase + SQ_LO + (uint32_t)(wid * 2048) + rbyte;
#pragma unroll
        for (int kg = 0; kg < 4; kg++) {
            uint32_t cb = (cpick + kg * 32) ^ lsw;
            ldsm4(aq_hi[kg], qb_hi + cb);
            ldsm4(aq_lo[kg], qb_lo + cb);
        }
    }

    float m0 = -1e30f, m1 = -1e30f, l0 = 0.0f, l1 = 0.0f;
    float acc_o[8][4];
#pragma unroll
    for (int n = 0; n < 8; n++)
#pragma unroll
        for (int j = 0; j < 4; j++) acc_o[n][j] = 0.0f;

    const uint32_t kb_hi = sbase + SK_HI + rbyte, kb_lo = sbase + SK_LO + rbyte;
    const uint32_t vb_hi = sbase + SV_HI + rbyte, vb_lo = sbase + SV_LO + rbyte;

    for (int t = 0; t < SEQ / 128; t++) {
        const int kv0 = t * 128;
        __syncthreads();

        {
            const size_t gro = ((size_t)(b * SEQ + kv0 + crow)) * DM + h * DKH + ccol;
            const float* ksrc = g_k + gro;
            const float* vsrc = g_v + gro;
#pragma unroll
            for (int i = 0; i < 8; i++) {
                uint32_t ad = (coff + 8 * i) ^ csw;
                float4 f = *(const float4*)(ksrc + 4 * i);
                __half2 h0 = __floats2half2_rn(f.x, f.y);
                __half2 h1 = __floats2half2_rn(f.z, f.w);
                float2 g0 = __half22float2(h0);
                float2 g1 = __half22float2(h1);
                *(__half2*)(smp + SK_HI + ad) = h0;
                *(__half2*)(smp + SK_HI + ad + 4) = h1;
                *(__half2*)(smp + SK_LO + ad) = __floats2half2_rn(f.x - g0.x, f.y - g0.y);
                *(__half2*)(smp + SK_LO + ad + 4) = __floats2half2_rn(f.z - g1.x, f.w - g1.y);

                f = *(const float4*)(vsrc + 4 * i);
                h0 = __floats2half2_rn(f.x, f.y);
                h1 = __floats2half2_rn(f.z, f.w);
                g0 = __half22float2(h0);
                g1 = __half22float2(h1);
                *(__half2*)(smp + SV_HI + ad) = h0;
                *(__half2*)(smp + SV_HI + ad + 4) = h1;
                *(__half2*)(smp + SV_LO + ad) = __floats2half2_rn(f.x - g0.x, f.y - g0.y);
                *(__half2*)(smp + SV_LO + ad + 4) = __floats2half2_rn(f.z - g1.x, f.w - g1.y);
            }
        }
        __syncthreads();

        float c[16][4];
#pragma unroll
        for (int j = 0; j < 16; j++)
#pragma unroll
            for (int q = 0; q < 4; q++) c[j][q] = 0.0f;

#pragma unroll
        for (int j2 = 0; j2 < 8; j2++) {
            const uint32_t rowoff = (uint32_t)(j2 * 2048);
#pragma unroll
            for (int kg = 0; kg < 4; kg++) {
                uint32_t cb = (cpick + kg * 32) ^ lsw;
                uint32_t rh[4], rl[4];
                ldsm4(rh, kb_hi + rowoff + cb);
                ldsm4(rl, kb_lo + rowoff + cb);
                uint32_t bh0[2] = { rh[0], rh[2] }, bh1[2] = { rh[1], rh[3] };
                uint32_t bl0[2] = { rl[0], rl[2] }, bl1[2] = { rl[1], rl[3] };
                mma16816(c[2 * j2],     aq_hi[kg], bh0);
                mma16816(c[2 * j2],     aq_hi[kg], bl0);
                mma16816(c[2 * j2],     aq_lo[kg], bh0);
                mma16816(c[2 * j2 + 1], aq_hi[kg], bh1);
                mma16816(c[2 * j2 + 1], aq_hi[kg], bl1);
                mma16816(c[2 * j2 + 1], aq_lo[kg], bh1);
            }
        }

        float mx0 = -1e30f, mx1 = -1e30f;
#pragma unroll
        for (int j = 0; j < 16; j++) {
            mx0 = fmaxf(mx0, fmaxf(c[j][0], c[j][1]));
            mx1 = fmaxf(mx1, fmaxf(c[j][2], c[j][3]));
        }
        mx0 = fmaxf(mx0, __shfl_xor_sync(0xffffffffu, mx0, 1));
        mx0 = fmaxf(mx0, __shfl_xor_sync(0xffffffffu, mx0, 2));
        mx1 = fmaxf(mx1, __shfl_xor_sync(0xffffffffu, mx1, 1));
        mx1 = fmaxf(mx1, __shfl_xor_sync(0xffffffffu, mx1, 2));

        float mn0 = fmaxf(m0, mx0), mn1 = fmaxf(m1, mx1);
        float al0 = ex2f(m0 - mn0), al1 = ex2f(m1 - mn1);
        m0 = mn0; m1 = mn1;

        float rs0 = 0.0f, rs1 = 0.0f;
#pragma unroll
        for (int j = 0; j < 16; j++) {
            c[j][0] = ex2f(c[j][0] - mn0);
            c[j][1] = ex2f(c[j][1] - mn0);
            c[j][2] = ex2f(c[j][2] - mn1);
            c[j][3] = ex2f(c[j][3] - mn1);
            rs0 += c[j][0] + c[j][1];
            rs1 += c[j][2] + c[j][3];
        }
        rs0 += __shfl_xor_sync(0xffffffffu, rs0, 1);
        rs0 += __shfl_xor_sync(0xffffffffu, rs0, 2);
        rs1 += __shfl_xor_sync(0xffffffffu, rs1, 1);
        rs1 += __shfl_xor_sync(0xffffffffu, rs1, 2);
        l0 = l0 * al0 + rs0;
        l1 = l1 * al1 + rs1;

#pragma unroll
        for (int n = 0; n < 8; n++) {
            acc_o[n][0] *= al0; acc_o[n][1] *= al0;
            acc_o[n][2] *= al1; acc_o[n][3] *= al1;
        }

#pragma unroll
        for (int kg = 0; kg < 8; kg++) {
            uint32_t phi[4], plo[4];
#pragma unroll
            for (int q = 0; q < 2; q++) {
                float p0 = c[2 * kg + q][0], p1 = c[2 * kg + q][1];
                float p2 = c[2 * kg + q][2], p3 = c[2 * kg + q][3];
                __half2 hA = __floats2half2_rn(p0, p1);
                __half2 hB = __floats2half2_rn(p2, p3);
                float2 fA = __half22float2(hA);
                float2 fB = __half22float2(hB);
                phi[2 * q]     = h2u(hA);
                phi[2 * q + 1] = h2u(hB);
                plo[2 * q]     = h2u(__floats2half2_rn(p0 - fA.x, p1 - fA.y));
                plo[2 * q + 1] = h2u(__floats2half2_rn(p2 - fB.x, p3 - fB.y));
            }
            uint32_t af_hi[4] = { phi[0], phi[1], phi[2], phi[3] };
            uint32_t af_lo[4] = { plo[0], plo[1], plo[2], plo[3] };

            const uint32_t kvoff = (uint32_t)(kg * 2048);
#pragma unroll
            for (int d2 = 0; d2 < 4; d2++) {
                uint32_t cb = (cpick + d2 * 32) ^ lsw;
                uint32_t rhv[4], rlv[4];
                ldsm4t(rhv, vb_hi + kvoff + cb);
                ldsm4t(rlv, vb_lo + kvoff + cb);
                uint32_t bh0[2] = { rhv[0], rhv[1] }, bh1[2] = { rhv[2], rhv[3] };
                uint32_t bl0[2] = { rlv[0], rlv[1] }, bl1[2] = { rlv[2], rlv[3] };
                mma16816(acc_o[2 * d2],     af_hi, bh0);
                mma16816(acc_o[2 * d2],     af_hi, bl0);
                mma16816(acc_o[2 * d2],     af_lo, bh0);
                mma16816(acc_o[2 * d2 + 1], af_hi, bh1);
                mma16816(acc_o[2 * d2 + 1], af_hi, bl1);
                mma16816(acc_o[2 * d2 + 1], af_lo, bh1);
            }
        }
    }

    // ---- normalize + store split ctx directly (feeds O-proj GEMM) ----
    const float inv0 = 1.0f / l0;
    const float inv1 = 1.0f / l1;
    const int gr0 = q0 + wid * 16 + (lid >> 2);
    const int gr1 = gr0 + 8;
    const int colb = h * DKH + (lid & 3) * 2;
#pragma unroll
    for (int n = 0; n < 8; n++) {
        int col = colb + n * 8;
        size_t o0 = (size_t)(b * SEQ + gr0) * DM + col;
        size_t o1 = (size_t)(b * SEQ + gr1) * DM + col;
        float vx0 = acc_o[n][0] * inv0, vy0 = acc_o[n][1] * inv0;
        float vx1 = acc_o[n][2] * inv1, vy1 = acc_o[n][3] * inv1;
        __half2 h0 = __floats2half2_rn(vx0, vy0);
        __half2 h1 = __floats2half2_rn(vx1, vy1);
        float2 f0 = __half22float2(h0);
        float2 f1 = __half22float2(h1);
        *(__half2*)(g_chi + o0) = h0;
        *(__half2*)(g_chi + o1) = h1;
        *(__half2*)(g_clo + o0) = __floats2half2_rn(vx0 - f0.x, vy0 - f0.y);
        *(__half2*)(g_clo + o1) = __floats2half2_rn(vx1 - f1.x, vy1 - f1.y);
    }
}

// ---------------------------------------------------------------------------
extern "C" void kernel_launch(void* const* d_in, const int* in_sizes, int n_in,
                              void* d_out, int out_size)
{
    const float* query = (const float*)d_in[0];
    const float* key   = (const float*)d_in[1];
    const float* value = (const float*)d_in[2];
    const float* Wq    = (const float*)d_in[3];
    const float* bq    = (const float*)d_in[4];
    const float* Wk    = (const float*)d_in[5];
    const float* bk    = (const float*)d_in[6];
    const float* Wv    = (const float*)d_in[7];
    const float* bv    = (const float*)d_in[8];
    const float* Wo    = (const float*)d_in[9];
    const float* bo    = (const float*)d_in[10];

    float *qp, *kp, *vp;
    __half *xhi, *xlo, *whi, *wlo, *chi, *clo;
    cudaGetSymbolAddress((void**)&qp, g_q);
    cudaGetSymbolAddress((void**)&kp, g_k);
    cudaGetSymbolAddress((void**)&vp, g_v);
    cudaGetSymbolAddress((void**)&xhi, g_xhi);
    cudaGetSymbolAddress((void**)&xlo, g_xlo);
    cudaGetSymbolAddress((void**)&whi, g_whi);
    cudaGetSymbolAddress((void**)&wlo, g_wlo);
    cudaGetSymbolAddress((void**)&chi, g_chi);
    cudaGetSymbolAddress((void**)&clo, g_clo);

    cudaFuncSetAttribute(gemm_tc, cudaFuncAttributeMaxDynamicSharedMemorySize, GEMM_SMEM);
    cudaFuncSetAttribute(attn_mma, cudaFuncAttributeMaxDynamicSharedMemorySize, ATTN_SMEM);

    const size_t XN = (size_t)MTOK * DM;
    const size_t WN = (size_t)DM * DM;
    const int xn4 = (int)(XN / 4), wn4 = (int)(WN / 4);

    split_f16<<<(xn4 + 255) / 256, 256>>>(query, xhi + 0 * XN, xlo + 0 * XN, xn4);
    split_f16<<<(xn4 + 255) / 256, 256>>>(key,   xhi + 1 * XN, xlo + 1 * XN, xn4);
    split_f16<<<(xn4 + 255) / 256, 256>>>(value, xhi + 2 * XN, xlo + 2 * XN, xn4);
    split_f16<<<(wn4 + 255) / 256, 256>>>(Wq, whi + 0 * WN, wlo + 0 * WN, wn4);
    split_f16<<<(wn4 + 255) / 256, 256>>>(Wk, whi + 1 * WN, wlo + 1 * WN, wn4);
    split_f16<<<(wn4 + 255) / 256, 256>>>(Wv, whi + 2 * WN, wlo + 2 * WN, wn4);
    split_f16<<<(wn4 + 255) / 256, 256>>>(Wo, whi + 3 * WN, wlo + 3 * WN, wn4);

    GemmArgs qkv;
    qkv.xhi = xhi; qkv.xlo = xlo; qkv.whi = whi; qkv.wlo = wlo;
    qkv.b0 = bq; qkv.b1 = bk; qkv.b2 = bv;
    qkv.o0 = qp; qkv.o1 = kp; qkv.o2 = vp;
    qkv.xstride = (long long)XN; qkv.wstride = (long long)WN;
    gemm_tc<<<dim3(DM / 128, MTOK / 128, 3), 256, GEMM_SMEM>>>(qkv);

    attn_mma<<<dim3(SEQ / 128, NH, NB), 256, ATTN_SMEM>>>();

    GemmArgs og;
    og.xhi = chi; og.xlo = clo; og.whi = whi + 3 * WN; og.wlo = wlo + 3 * WN;
    og.b0 = bo; og.b1 = bo; og.b2 = bo;
    og.o0 = (float*)d_out; og.o1 = (float*)d_out; og.o2 = (float*)d_out;
    og.xstride = 0; og.wstride = 0;
    gemm_tc<<<dim3(DM / 128, MTOK / 128, 1), 256, GEMM_SMEM>>>(og);
}

// round 9
// speedup vs baseline: 3.9974x; 1.3272x over previous
#include <cuda_runtime.h>
#include <cuda_fp16.h>
#include <math.h>
#include <stdint.h>

#define NH   16
#define DKH  64
#define DM   1024
#define NB   2
#define SEQ  2048
#define MTOK (NB * SEQ)   // 4096

// ---------------------------------------------------------------------------
// Device scratch
// ---------------------------------------------------------------------------
__device__ __half g_xhi[(size_t)3 * MTOK * DM];   // split q,k,v inputs
__device__ __half g_xlo[(size_t)3 * MTOK * DM];
__device__ __half g_whi[(size_t)4 * DM * DM];     // split Wq,Wk,Wv,Wo
__device__ __half g_wlo[(size_t)4 * DM * DM];

__device__ __half g_qhi[(size_t)MTOK * DM];       // projected, split (Q pre-scaled)
__device__ __half g_qlo[(size_t)MTOK * DM];
__device__ __half g_khi[(size_t)MTOK * DM];
__device__ __half g_klo[(size_t)MTOK * DM];
__device__ __half g_vhi[(size_t)MTOK * DM];
__device__ __half g_vlo[(size_t)MTOK * DM];

__device__ __half g_chi[(size_t)MTOK * DM];       // split ctx (written by attn)
__device__ __half g_clo[(size_t)MTOK * DM];

// ---------------------------------------------------------------------------
// PTX helpers (sm_80+ portable ISA)
// ---------------------------------------------------------------------------
__device__ __forceinline__ uint32_t smem_u32(const void* p) {
    uint32_t a;
    asm("{ .reg .u64 t; cvta.to.shared.u64 t, %1; cvt.u32.u64 %0, t; }" : "=r"(a) : "l"(p));
    return a;
}
__device__ __forceinline__ void cp_async16(uint32_t dst, const void* src) {
    asm volatile("cp.async.cg.shared.global [%0], [%1], 16;" :: "r"(dst), "l"(src));
}
__device__ __forceinline__ void cp_commit() {
    asm volatile("cp.async.commit_group;");
}
__device__ __forceinline__ void cp_wait0() {
    asm volatile("cp.async.wait_group 0;");
}
__device__ __forceinline__ void cp_wait1() {
    asm volatile("cp.async.wait_group 1;");
}
__device__ __forceinline__ void cp_wait2() {
    asm volatile("cp.async.wait_group 2;");
}
__device__ __forceinline__ void ldsm4(uint32_t* r, uint32_t addr) {
    asm volatile("ldmatrix.sync.aligned.m8n8.x4.shared.b16 {%0,%1,%2,%3}, [%4];"
                 : "=r"(r[0]), "=r"(r[1]), "=r"(r[2]), "=r"(r[3]) : "r"(addr));
}
__device__ __forceinline__ void ldsm4t(uint32_t* r, uint32_t addr) {
    asm volatile("ldmatrix.sync.aligned.m8n8.x4.trans.shared.b16 {%0,%1,%2,%3}, [%4];"
                 : "=r"(r[0]), "=r"(r[1]), "=r"(r[2]), "=r"(r[3]) : "r"(addr));
}
__device__ __forceinline__ void mma16816(float* c, const uint32_t* a, const uint32_t* b) {
    asm volatile(
        "mma.sync.aligned.m16n8k16.row.col.f32.f16.f16.f32 "
        "{%0,%1,%2,%3}, {%4,%5,%6,%7}, {%8,%9}, {%0,%1,%2,%3};"
        : "+f"(c[0]), "+f"(c[1]), "+f"(c[2]), "+f"(c[3])
        : "r"(a[0]), "r"(a[1]), "r"(a[2]), "r"(a[3]), "r"(b[0]), "r"(b[1]));
}
__device__ __forceinline__ float ex2f(float x) {
    float y;
    asm("ex2.approx.f32 %0, %1;" : "=f"(y) : "f"(x));
    return y;
}
__device__ __forceinline__ uint32_t h2u(__half2 h) {
    return *reinterpret_cast<uint32_t*>(&h);
}
__device__ __forceinline__ uint32_t swz64(uint32_t off) {
    return off ^ (((off >> 7) & 3u) << 4);
}

// ---------------------------------------------------------------------------
// Split-fp16 conversion: hi = f16(x), lo = f16(x - hi)
// ---------------------------------------------------------------------------
__global__ __launch_bounds__(256) void split_f16(const float* __restrict__ src,
                                                 __half* __restrict__ hi,
                                                 __half* __restrict__ lo, int n4) {
    int i = blockIdx.x * blockDim.x + threadIdx.x;
    if (i >= n4) return;
    float4 v = ((const float4*)src)[i];
    __half h0 = __float2half_rn(v.x), h1 = __float2half_rn(v.y);
    __half h2 = __float2half_rn(v.z), h3 = __float2half_rn(v.w);
    __half l0 = __float2half_rn(v.x - __half2float(h0));
    __half l1 = __float2half_rn(v.y - __half2float(h1));
    __half l2 = __float2half_rn(v.z - __half2float(h2));
    __half l3 = __float2half_rn(v.w - __half2float(h3));
    ((__half2*)hi)[2 * i]     = __halves2half2(h0, h1);
    ((__half2*)hi)[2 * i + 1] = __halves2half2(h2, h3);
    ((__half2*)lo)[2 * i]     = __halves2half2(l0, l1);
    ((__half2*)lo)[2 * i + 1] = __halves2half2(l2, l3);
}

// ---------------------------------------------------------------------------
// mma.sync split-fp16 GEMM (NT): C = A[M,K]*W[N,K]^T + bias, optional scale,
// output either fp32 (o*) or split-fp16 (ohi*/olo*).
// 128x128 tile, BK=32, 8 warps, 3-stage cp.async, 2 CTAs/SM.
// ---------------------------------------------------------------------------
struct GemmArgs {
    const __half *xhi, *xlo, *whi, *wlo;
    const float *b0, *b1, *b2;
    float *o0, *o1, *o2;                      // fp32 outputs (NULL => split mode)
    __half *ohi0, *olo0, *ohi1, *olo1, *ohi2, *olo2;
    float s0, s1, s2;
    long long xstride, wstride;
};

#define TILE_B   8192
#define STAGE_B  (4 * TILE_B)
#define NSTAGE   3
#define GEMM_SMEM (NSTAGE * STAGE_B)
#define NCHUNK   (DM / 32)

__global__ __launch_bounds__(256, 2) void gemm_tc(GemmArgs ar) {
    extern __shared__ char sm[];
    const uint32_t sbase = smem_u32(sm);

    const int tid = threadIdx.x;
    const int wid = tid >> 5;
    const int lid = tid & 31;
    const int z = blockIdx.z;

    const __half* xhi = ar.xhi + (size_t)z * ar.xstride;
    const __half* xlo = ar.xlo + (size_t)z * ar.xstride;
    const __half* whi = ar.whi + (size_t)z * ar.wstride;
    const __half* wlo = ar.wlo + (size_t)z * ar.wstride;
    const float* bias = (z == 0) ? ar.b0 : ((z == 1) ? ar.b1 : ar.b2);
    const float scale = (z == 0) ? ar.s0 : ((z == 1) ? ar.s1 : ar.s2);

    const int bm = blockIdx.y * 128;
    const int bn = blockIdx.x * 128;

    const int lrow0 = tid >> 2;
    const int lseg  = tid & 3;
    const uint32_t soff0 = swz64((uint32_t)(lrow0 * 64 + lseg * 16));
    const uint32_t soff1 = swz64((uint32_t)((lrow0 + 64) * 64 + lseg * 16));

    auto load_stage = [&](int chunk, int stage) {
        const int k0 = chunk * 32 + lseg * 8;
        const uint32_t st = sbase + stage * STAGE_B;
        const size_t ga0 = (size_t)(bm + lrow0) * DM + k0;
        const size_t ga1 = (size_t)(bm + lrow0 + 64) * DM + k0;
        const size_t gw0 = (size_t)(bn + lrow0) * DM + k0;
        const size_t gw1 = (size_t)(bn + lrow0 + 64) * DM + k0;
        cp_async16(st + soff0,              xhi + ga0);
        cp_async16(st + soff1,              xhi + ga1);
        cp_async16(st + TILE_B + soff0,     xlo + ga0);
        cp_async16(st + TILE_B + soff1,     xlo + ga1);
        cp_async16(st + 2 * TILE_B + soff0, whi + gw0);
        cp_async16(st + 2 * TILE_B + soff1, whi + gw1);
        cp_async16(st + 3 * TILE_B + soff0, wlo + gw0);
        cp_async16(st + 3 * TILE_B + soff1, wlo + gw1);
    };

    const int wm = wid & 3;
    const int wn = wid >> 2;
    const int lm_row = (lid & 7) + 8 * ((lid >> 3) & 1);
    const int lm_cb  = 16 * (lid >> 4);

    float acc[2][8][4];
#pragma unroll
    for (int i = 0; i < 2; i++)
#pragma unroll
        for (int j = 0; j < 8; j++)
#pragma unroll
            for (int k = 0; k < 4; k++) acc[i][j][k] = 0.0f;

    load_stage(0, 0); cp_commit();
    load_stage(1, 1); cp_commit();
    load_stage(2, 2); cp_commit();

    for (int c = 0; c < NCHUNK; c++) {
        cp_wait2();
        __syncthreads();
        const uint32_t st = sbase + (uint32_t)(c % 3) * STAGE_B;

#pragma unroll
        for (int ks = 0; ks < 2; ks++) {
            const int cb = ks * 32 + lm_cb;

            uint32_t ahi[2][4], alo[2][4];
#pragma unroll
            for (int mi = 0; mi < 2; mi++) {
                uint32_t off = swz64((uint32_t)((wm * 32 + mi * 16 + lm_row) * 64 + cb));
                ldsm4(ahi[mi], st + off);
                ldsm4(alo[mi], st + TILE_B + off);
            }
#pragma unroll
            for (int j = 0; j < 4; j++) {
                uint32_t off = swz64((uint32_t)((wn * 64 + j * 16 + lm_row) * 64 + cb));
                uint32_t rh[4], rl[4];
                ldsm4(rh, st + 2 * TILE_B + off);
                ldsm4(rl, st + 3 * TILE_B + off);
                uint32_t bh0[2] = { rh[0], rh[2] }, bh1[2] = { rh[1], rh[3] };
                uint32_t bl0[2] = { rl[0], rl[2] }, bl1[2] = { rl[1], rl[3] };
#pragma unroll
                for (int mi = 0; mi < 2; mi++) {
                    mma16816(acc[mi][2 * j],     ahi[mi], bh0);
                    mma16816(acc[mi][2 * j],     alo[mi], bh0);
                    mma16816(acc[mi][2 * j],     ahi[mi], bl0);
                    mma16816(acc[mi][2 * j + 1], ahi[mi], bh1);
                    mma16816(acc[mi][2 * j + 1], alo[mi], bh1);
                    mma16816(acc[mi][2 * j + 1], ahi[mi], bl1);
                }
            }
        }

        __syncthreads();
        if (c + 3 < NCHUNK) load_stage(c + 3, c % 3);
        cp_commit();
    }

    const int rbase = bm + wm * 32 + (lid >> 2);
    const int cbase = bn + wn * 64 + (lid & 3) * 2;
    float* out = (z == 0) ? ar.o0 : ((z == 1) ? ar.o1 : ar.o2);

    if (out) {
#pragma unroll
        for (int mi = 0; mi < 2; mi++) {
#pragma unroll
            for (int ni = 0; ni < 8; ni++) {
                int col = cbase + ni * 8;
                float bx = bias[col], by = bias[col + 1];
                int r0 = rbase + mi * 16;
                float2 v0 = make_float2((acc[mi][ni][0] + bx) * scale, (acc[mi][ni][1] + by) * scale);
                float2 v1 = make_float2((acc[mi][ni][2] + bx) * scale, (acc[mi][ni][3] + by) * scale);
                *(float2*)(out + (size_t)r0 * DM + col) = v0;
                *(float2*)(out + (size_t)(r0 + 8) * DM + col) = v1;
            }
        }
    } else {
        __half* ohi = (z == 0) ? ar.ohi0 : ((z == 1) ? ar.ohi1 : ar.ohi2);
        __half* olo = (z == 0) ? ar.olo0 : ((z == 1) ? ar.olo1 : ar.olo2);
#pragma unroll
        for (int mi = 0; mi < 2; mi++) {
#pragma unroll
            for (int ni = 0; ni < 8; ni++) {
                int col = cbase + ni * 8;
                float bx = bias[col], by = bias[col + 1];
                int r0 = rbase + mi * 16;
                float v00 = (acc[mi][ni][0] + bx) * scale, v01 = (acc[mi][ni][1] + by) * scale;
                float v10 = (acc[mi][ni][2] + bx) * scale, v11 = (acc[mi][ni][3] + by) * scale;
                __half2 h0 = __floats2half2_rn(v00, v01);
                __half2 h1 = __floats2half2_rn(v10, v11);
                float2 f0 = __half22float2(h0);
                float2 f1 = __half22float2(h1);
                size_t p0 = (size_t)r0 * DM + col;
                size_t p1 = (size_t)(r0 + 8) * DM + col;
                *(__half2*)(ohi + p0) = h0;
                *(__half2*)(ohi + p1) = h1;
                *(__half2*)(olo + p0) = __floats2half2_rn(v00 - f0.x, v01 - f0.y);
                *(__half2*)(olo + p1) = __floats2half2_rn(v10 - f1.x, v11 - f1.y);
            }
        }
    }
}

// ---------------------------------------------------------------------------
// Tensor-core flash attention — pre-split inputs, cp.async double-buffered KV
// ---------------------------------------------------------------------------
// smem map (from 1024-aligned base):
//   [0, 16K)        Q hi          [16K, 32K)  Q lo
//   [32K + s*64K):  stage s: K hi | K lo | V hi | V lo (16K each)
#define AKV_BASE 32768
#define AKV_STAGE 65536
#define ATTN_SMEM (32768 + 2 * AKV_STAGE + 1024)

__global__ __launch_bounds__(256) void attn_mma()
{
    extern __shared__ char sm_raw[];
    const uint32_t sraw = smem_u32(sm_raw);
    const uint32_t sbase = (sraw + 1023u) & ~1023u;

    const int tid = threadIdx.x;
    const int wid = tid >> 5;
    const int lid = tid & 31;
    const int b = blockIdx.z;
    const int h = blockIdx.y;
    const int q0 = blockIdx.x * 128;

    const __half* khi = g_khi;
    const __half* klo = g_klo;
    const __half* vhi = g_vhi;
    const __half* vlo = g_vlo;

    // ---- Q tile: 2048 16B-segments (hi then lo), 8 per thread ----
#pragma unroll
    for (int i = 0; i < 8; i++) {
        int s = tid + 256 * i;
        int buf = s >> 10;             // 0=hi, 1=lo
        int r = (s & 1023) >> 3;
        int sg = s & 7;
        uint32_t off = ((uint32_t)(r * 128 + sg * 16)) ^ (((uint32_t)(r & 7)) << 4);
        const __half* src = (buf ? g_qlo : g_qhi) + (size_t)(b * SEQ + q0 + r) * DM + h * DKH + sg * 8;
        cp_async16(sbase + (uint32_t)buf * 16384 + off, src);
    }
    cp_commit();

    // ---- KV tile loader: 4096 segments (khi,klo,vhi,vlo), 16 per thread ----
    auto issue_kv = [&](int t, int stg) {
        const int kv0 = t * 128;
        const uint32_t stb = sbase + AKV_BASE + (uint32_t)stg * AKV_STAGE;
#pragma unroll
        for (int i = 0; i < 16; i++) {
            int s = tid + 256 * i;
            int buf = s >> 10;         // 0=khi,1=klo,2=vhi,3=vlo
            int r = (s & 1023) >> 3;
            int sg = s & 7;
            uint32_t off = ((uint32_t)(r * 128 + sg * 16)) ^ (((uint32_t)(r & 7)) << 4);
            const __half* base = (buf == 0) ? khi : ((buf == 1) ? klo : ((buf == 2) ? vhi : vlo));
            cp_async16(stb + (uint32_t)buf * 16384 + off,
                       base + (size_t)(b * SEQ + kv0 + r) * DM + h * DKH + sg * 8);
        }
    };

    issue_kv(0, 0); cp_commit();

    // ---- ldmatrix lane addressing ----
    const int lm_row = (lid & 7) + 8 * ((lid >> 3) & 1);
    const uint32_t rbyte = (uint32_t)(lm_row * 128);
    const uint32_t lsw = ((uint32_t)(lm_row & 7)) << 4;
    const uint32_t cpick = (uint32_t)(16 * (lid >> 4));

    // ---- Q fragments ----
    cp_wait1();          // Q group complete (KV0 may still be in flight)
    __syncthreads();
    uint32_t aq_hi[4][4], aq_lo[4][4];
    {
        uint32_t qb_hi = sbase + (uint32_t)(wid * 2048) + rbyte;
        uint32_t qb_lo = qb_hi + 16384;
#pragma unroll
        for (int kg = 0; kg < 4; kg++) {
            uint32_t cb = (cpick + kg * 32) ^ lsw;
            ldsm4(aq_hi[kg], qb_hi + cb);
            ldsm4(aq_lo[kg], qb_lo + cb);
        }
    }

    float m0 = -1e30f, m1 = -1e30f, l0 = 0.0f, l1 = 0.0f;
    float acc_o[8][4];
#pragma unroll
    for (int n = 0; n < 8; n++)
#pragma unroll
        for (int j = 0; j < 4; j++) acc_o[n][j] = 0.0f;

    for (int t = 0; t < SEQ / 128; t++) {
        cp_wait0();          // KV tile t resident
        __syncthreads();     // all threads done with previous compute + see data

        if (t + 1 < SEQ / 128) { issue_kv(t + 1, (t + 1) & 1); cp_commit(); }

        const uint32_t stb = sbase + AKV_BASE + (uint32_t)(t & 1) * AKV_STAGE;
        const uint32_t kb_hi = stb + rbyte;
        const uint32_t kb_lo = kb_hi + 16384;
        const uint32_t vb_hi = kb_hi + 32768;
        const uint32_t vb_lo = kb_hi + 49152;

        // ---- QK^T ----
        float c[16][4];
#pragma unroll
        for (int j = 0; j < 16; j++)
#pragma unroll
            for (int q = 0; q < 4; q++) c[j][q] = 0.0f;

#pragma unroll
        for (int j2 = 0; j2 < 8; j2++) {
            const uint32_t rowoff = (uint32_t)(j2 * 2048);
#pragma unroll
            for (int kg = 0; kg < 4; kg++) {
                uint32_t cb = (cpick + kg * 32) ^ lsw;
                uint32_t rh[4], rl[4];
                ldsm4(rh, kb_hi + rowoff + cb);
                ldsm4(rl, kb_lo + rowoff + cb);
                uint32_t bh0[2] = { rh[0], rh[2] }, bh1[2] = { rh[1], rh[3] };
                uint32_t bl0[2] = { rl[0], rl[2] }, bl1[2] = { rl[1], rl[3] };
                mma16816(c[2 * j2],     aq_hi[kg], bh0);
                mma16816(c[2 * j2],     aq_hi[kg], bl0);
                mma16816(c[2 * j2],     aq_lo[kg], bh0);
                mma16816(c[2 * j2 + 1], aq_hi[kg], bh1);
                mma16816(c[2 * j2 + 1], aq_hi[kg], bl1);
                mma16816(c[2 * j2 + 1], aq_lo[kg], bh1);
            }
        }

        // ---- online softmax (base-2) ----
        float mx0 = -1e30f, mx1 = -1e30f;
#pragma unroll
        for (int j = 0; j < 16; j++) {
            mx0 = fmaxf(mx0, fmaxf(c[j][0], c[j][1]));
            mx1 = fmaxf(mx1, fmaxf(c[j][2], c[j][3]));
        }
        mx0 = fmaxf(mx0, __shfl_xor_sync(0xffffffffu, mx0, 1));
        mx0 = fmaxf(mx0, __shfl_xor_sync(0xffffffffu, mx0, 2));
        mx1 = fmaxf(mx1, __shfl_xor_sync(0xffffffffu, mx1, 1));
        mx1 = fmaxf(mx1, __shfl_xor_sync(0xffffffffu, mx1, 2));

        float mn0 = fmaxf(m0, mx0), mn1 = fmaxf(m1, mx1);
        float al0 = ex2f(m0 - mn0), al1 = ex2f(m1 - mn1);
        m0 = mn0; m1 = mn1;

        float rs0 = 0.0f, rs1 = 0.0f;
#pragma unroll
        for (int j = 0; j < 16; j++) {
            c[j][0] = ex2f(c[j][0] - mn0);
            c[j][1] = ex2f(c[j][1] - mn0);
            c[j][2] = ex2f(c[j][2] - mn1);
            c[j][3] = ex2f(c[j][3] - mn1);
            rs0 += c[j][0] + c[j][1];
            rs1 += c[j][2] + c[j][3];
        }
        rs0 += __shfl_xor_sync(0xffffffffu, rs0, 1);
        rs0 += __shfl_xor_sync(0xffffffffu, rs0, 2);
        rs1 += __shfl_xor_sync(0xffffffffu, rs1, 1);
        rs1 += __shfl_xor_sync(0xffffffffu, rs1, 2);
        l0 = l0 * al0 + rs0;
        l1 = l1 * al1 + rs1;

#pragma unroll
        for (int n = 0; n < 8; n++) {
            acc_o[n][0] *= al0; acc_o[n][1] *= al0;
            acc_o[n][2] *= al1; acc_o[n][3] *= al1;
        }

        // ---- PV ----
#pragma unroll
        for (int kg = 0; kg < 8; kg++) {
            uint32_t phi[4], plo[4];
#pragma unroll
            for (int q = 0; q < 2; q++) {
                float p0 = c[2 * kg + q][0], p1 = c[2 * kg + q][1];
                float p2 = c[2 * kg + q][2], p3 = c[2 * kg + q][3];
                __half2 hA = __floats2half2_rn(p0, p1);
                __half2 hB = __floats2half2_rn(p2, p3);
                float2 fA = __half22float2(hA);
                float2 fB = __half22float2(hB);
                phi[2 * q]     = h2u(hA);
                phi[2 * q + 1] = h2u(hB);
                plo[2 * q]     = h2u(__floats2half2_rn(p0 - fA.x, p1 - fA.y));
                plo[2 * q + 1] = h2u(__floats2half2_rn(p2 - fB.x, p3 - fB.y));
            }

            const uint32_t kvoff = (uint32_t)(kg * 2048);
#pragma unroll
            for (int d2 = 0; d2 < 4; d2++) {
                uint32_t cb = (cpick + d2 * 32) ^ lsw;
                uint32_t rhv[4], rlv[4];
                ldsm4t(rhv, vb_hi + kvoff + cb);
                ldsm4t(rlv, vb_lo + kvoff + cb);
                uint32_t bh0[2] = { rhv[0], rhv[1] }, bh1[2] = { rhv[2], rhv[3] };
                uint32_t bl0[2] = { rlv[0], rlv[1] }, bl1[2] = { rlv[2], rlv[3] };
                mma16816(acc_o[2 * d2],     phi, bh0);
                mma16816(acc_o[2 * d2],     phi, bl0);
                mma16816(acc_o[2 * d2],     plo, bh0);
                mma16816(acc_o[2 * d2 + 1], phi, bh1);
                mma16816(acc_o[2 * d2 + 1], phi, bl1);
                mma16816(acc_o[2 * d2 + 1], plo, bh1);
            }
        }
    }

    // ---- normalize + store split ctx ----
    const float inv0 = 1.0f / l0;
    const float inv1 = 1.0f / l1;
    const int gr0 = q0 + wid * 16 + (lid >> 2);
    const int gr1 = gr0 + 8;
    const int colb = h * DKH + (lid & 3) * 2;
#pragma unroll
    for (int n = 0; n < 8; n++) {
        int col = colb + n * 8;
        size_t o0 = (size_t)(b * SEQ + gr0) * DM + col;
        size_t o1 = (size_t)(b * SEQ + gr1) * DM + col;
        float vx0 = acc_o[n][0] * inv0, vy0 = acc_o[n][1] * inv0;
        float vx1 = acc_o[n][2] * inv1, vy1 = acc_o[n][3] * inv1;
        __half2 h0 = __floats2half2_rn(vx0, vy0);
        __half2 h1 = __floats2half2_rn(vx1, vy1);
        float2 f0 = __half22float2(h0);
        float2 f1 = __half22float2(h1);
        *(__half2*)(g_chi + o0) = h0;
        *(__half2*)(g_chi + o1) = h1;
        *(__half2*)(g_clo + o0) = __floats2half2_rn(vx0 - f0.x, vy0 - f0.y);
        *(__half2*)(g_clo + o1) = __floats2half2_rn(vx1 - f1.x, vy1 - f1.y);
    }
}

// ---------------------------------------------------------------------------
#define QSCALE 0.18033688f   // (1/8) * log2(e)

extern "C" void kernel_launch(void* const* d_in, const int* in_sizes, int n_in,
                              void* d_out, int out_size)
{
    const float* query = (const float*)d_in[0];
    const float* key   = (const float*)d_in[1];
    const float* value = (const float*)d_in[2];
    const float* Wq    = (const float*)d_in[3];
    const float* bq    = (const float*)d_in[4];
    const float* Wk    = (const float*)d_in[5];
    const float* bk    = (const float*)d_in[6];
    const float* Wv    = (const float*)d_in[7];
    const float* bv    = (const float*)d_in[8];
    const float* Wo    = (const float*)d_in[9];
    const float* bo    = (const float*)d_in[10];

    __half *xhi, *xlo, *whi, *wlo, *chi, *clo;
    __half *qhi, *qlo, *khi, *klo, *vhi, *vlo;
    cudaGetSymbolAddress((void**)&xhi, g_xhi);
    cudaGetSymbolAddress((void**)&xlo, g_xlo);
    cudaGetSymbolAddress((void**)&whi, g_whi);
    cudaGetSymbolAddress((void**)&wlo, g_wlo);
    cudaGetSymbolAddress((void**)&chi, g_chi);
    cudaGetSymbolAddress((void**)&clo, g_clo);
    cudaGetSymbolAddress((void**)&qhi, g_qhi);
    cudaGetSymbolAddress((void**)&qlo, g_qlo);
    cudaGetSymbolAddress((void**)&khi, g_khi);
    cudaGetSymbolAddress((void**)&klo, g_klo);
    cudaGetSymbolAddress((void**)&vhi, g_vhi);
    cudaGetSymbolAddress((void**)&vlo, g_vlo);

    cudaFuncSetAttribute(gemm_tc, cudaFuncAttributeMaxDynamicSharedMemorySize, GEMM_SMEM);
    cudaFuncSetAttribute(attn_mma, cudaFuncAttributeMaxDynamicSharedMemorySize, ATTN_SMEM);

    const size_t XN = (size_t)MTOK * DM;
    const size_t WN = (size_t)DM * DM;
    const int xn4 = (int)(XN / 4), wn4 = (int)(WN / 4);

    split_f16<<<(xn4 + 255) / 256, 256>>>(query, xhi + 0 * XN, xlo + 0 * XN, xn4);
    split_f16<<<(xn4 + 255) / 256, 256>>>(key,   xhi + 1 * XN, xlo + 1 * XN, xn4);
    split_f16<<<(xn4 + 255) / 256, 256>>>(value, xhi + 2 * XN, xlo + 2 * XN, xn4);
    split_f16<<<(wn4 + 255) / 256, 256>>>(Wq, whi + 0 * WN, wlo + 0 * WN, wn4);
    split_f16<<<(wn4 + 255) / 256, 256>>>(Wk, whi + 1 * WN, wlo + 1 * WN, wn4);
    split_f16<<<(wn4 + 255) / 256, 256>>>(Wv, whi + 2 * WN, wlo + 2 * WN, wn4);
    split_f16<<<(wn4 + 255) / 256, 256>>>(Wo, whi + 3 * WN, wlo + 3 * WN, wn4);

    // QKV projections -> split-fp16 outputs (Q pre-scaled by QSCALE)
    GemmArgs qkv;
    qkv.xhi = xhi; qkv.xlo = xlo; qkv.whi = whi; qkv.wlo = wlo;
    qkv.b0 = bq; qkv.b1 = bk; qkv.b2 = bv;
    qkv.o0 = nullptr; qkv.o1 = nullptr; qkv.o2 = nullptr;
    qkv.ohi0 = qhi; qkv.olo0 = qlo;
    qkv.ohi1 = khi; qkv.olo1 = klo;
    qkv.ohi2 = vhi; qkv.olo2 = vlo;
    qkv.s0 = QSCALE; qkv.s1 = 1.0f; qkv.s2 = 1.0f;
    qkv.xstride = (long long)XN; qkv.wstride = (long long)WN;
    gemm_tc<<<dim3(DM / 128, MTOK / 128, 3), 256, GEMM_SMEM>>>(qkv);

    attn_mma<<<dim3(SEQ / 128, NH, NB), 256, ATTN_SMEM>>>();

    // O projection -> fp32 d_out
    GemmArgs og;
    og.xhi = chi; og.xlo = clo; og.whi = whi + 3 * WN; og.wlo = wlo + 3 * WN;
    og.b0 = bo; og.b1 = bo; og.b2 = bo;
    og.o0 = (float*)d_out; og.o1 = (float*)d_out; og.o2 = (float*)d_out;
    og.ohi0 = nullptr; og.olo0 = nullptr; og.ohi1 = nullptr; og.olo1 = nullptr;
    og.ohi2 = nullptr; og.olo2 = nullptr;
    og.s0 = 1.0f; og.s1 = 1.0f; og.s2 = 1.0f;
    og.xstride = 0; og.wstride = 0;
    gemm_tc<<<dim3(DM / 128, MTOK / 128, 1), 256, GEMM_SMEM>>>(og);
}

// round 10
// speedup vs baseline: 4.3695x; 1.0931x over previous
#include <cuda_runtime.h>
#include <cuda_fp16.h>
#include <math.h>
#include <stdint.h>

#define NH   16
#define DKH  64
#define DM   1024
#define NB   2
#define SEQ  2048
#define MTOK (NB * SEQ)   // 4096

// ---------------------------------------------------------------------------
// Device scratch
// ---------------------------------------------------------------------------
__device__ __half g_xhi[(size_t)3 * MTOK * DM];   // split q,k,v inputs
__device__ __half g_xlo[(size_t)3 * MTOK * DM];
__device__ __half g_whi[(size_t)4 * DM * DM];     // split Wq,Wk,Wv,Wo
__device__ __half g_wlo[(size_t)4 * DM * DM];

__device__ __half g_qhi[(size_t)MTOK * DM];       // projected, split (Q pre-scaled)
__device__ __half g_qlo[(size_t)MTOK * DM];
__device__ __half g_khi[(size_t)MTOK * DM];
__device__ __half g_klo[(size_t)MTOK * DM];
__device__ __half g_vhi[(size_t)MTOK * DM];
__device__ __half g_vlo[(size_t)MTOK * DM];

__device__ __half g_chi[(size_t)MTOK * DM];       // split ctx (written by attn)
__device__ __half g_clo[(size_t)MTOK * DM];

// ---------------------------------------------------------------------------
// PTX helpers (sm_80+ portable ISA)
// ---------------------------------------------------------------------------
__device__ __forceinline__ uint32_t smem_u32(const void* p) {
    uint32_t a;
    asm("{ .reg .u64 t; cvta.to.shared.u64 t, %1; cvt.u32.u64 %0, t; }" : "=r"(a) : "l"(p));
    return a;
}
__device__ __forceinline__ void cp_async16(uint32_t dst, const void* src) {
    asm volatile("cp.async.cg.shared.global [%0], [%1], 16;" :: "r"(dst), "l"(src));
}
__device__ __forceinline__ void cp_commit() {
    asm volatile("cp.async.commit_group;");
}
__device__ __forceinline__ void cp_wait0() {
    asm volatile("cp.async.wait_group 0;");
}
__device__ __forceinline__ void cp_wait1() {
    asm volatile("cp.async.wait_group 1;");
}
__device__ __forceinline__ void cp_wait2() {
    asm volatile("cp.async.wait_group 2;");
}
__device__ __forceinline__ void ldsm4(uint32_t* r, uint32_t addr) {
    asm volatile("ldmatrix.sync.aligned.m8n8.x4.shared.b16 {%0,%1,%2,%3}, [%4];"
                 : "=r"(r[0]), "=r"(r[1]), "=r"(r[2]), "=r"(r[3]) : "r"(addr));
}
__device__ __forceinline__ void ldsm4t(uint32_t* r, uint32_t addr) {
    asm volatile("ldmatrix.sync.aligned.m8n8.x4.trans.shared.b16 {%0,%1,%2,%3}, [%4];"
                 : "=r"(r[0]), "=r"(r[1]), "=r"(r[2]), "=r"(r[3]) : "r"(addr));
}
__device__ __forceinline__ void mma16816(float* c, const uint32_t* a, const uint32_t* b) {
    asm volatile(
        "mma.sync.aligned.m16n8k16.row.col.f32.f16.f16.f32 "
        "{%0,%1,%2,%3}, {%4,%5,%6,%7}, {%8,%9}, {%0,%1,%2,%3};"
        : "+f"(c[0]), "+f"(c[1]), "+f"(c[2]), "+f"(c[3])
        : "r"(a[0]), "r"(a[1]), "r"(a[2]), "r"(a[3]), "r"(b[0]), "r"(b[1]));
}
__device__ __forceinline__ float ex2f(float x) {
    float y;
    asm("ex2.approx.f32 %0, %1;" : "=f"(y) : "f"(x));
    return y;
}
__device__ __forceinline__ uint32_t ex2_h2(uint32_t x) {
    uint32_t y;
    asm("ex2.approx.f16x2 %0, %1;" : "=r"(y) : "r"(x));
    return y;
}
__device__ __forceinline__ uint32_t h2u(__half2 h) {
    return *reinterpret_cast<uint32_t*>(&h);
}
__device__ __forceinline__ uint32_t swz64(uint32_t off) {
    return off ^ (((off >> 7) & 3u) << 4);
}

// ---------------------------------------------------------------------------
// Split-fp16 conversion: hi = f16(x), lo = f16(x - hi)
// ---------------------------------------------------------------------------
__global__ __launch_bounds__(256) void split_f16(const float* __restrict__ src,
                                                 __half* __restrict__ hi,
                                                 __half* __restrict__ lo, int n4) {
    int i = blockIdx.x * blockDim.x + threadIdx.x;
    if (i >= n4) return;
    float4 v = ((const float4*)src)[i];
    __half h0 = __float2half_rn(v.x), h1 = __float2half_rn(v.y);
    __half h2 = __float2half_rn(v.z), h3 = __float2half_rn(v.w);
    __half l0 = __float2half_rn(v.x - __half2float(h0));
    __half l1 = __float2half_rn(v.y - __half2float(h1));
    __half l2 = __float2half_rn(v.z - __half2float(h2));
    __half l3 = __float2half_rn(v.w - __half2float(h3));
    ((__half2*)hi)[2 * i]     = __halves2half2(h0, h1);
    ((__half2*)hi)[2 * i + 1] = __halves2half2(h2, h3);
    ((__half2*)lo)[2 * i]     = __halves2half2(l0, l1);
    ((__half2*)lo)[2 * i + 1] = __halves2half2(l2, l3);
}

// ---------------------------------------------------------------------------
// mma.sync split-fp16 GEMM (NT): C = A[M,K]*W[N,K]^T + bias, optional scale,
// output either fp32 (o*) or split-fp16 (ohi*/olo*).
// ---------------------------------------------------------------------------
struct GemmArgs {
    const __half *xhi, *xlo, *whi, *wlo;
    const float *b0, *b1, *b2;
    float *o0, *o1, *o2;                      // fp32 outputs (NULL => split mode)
    __half *ohi0, *olo0, *ohi1, *olo1, *ohi2, *olo2;
    float s0, s1, s2;
    long long xstride, wstride;
};

#define TILE_B   8192
#define STAGE_B  (4 * TILE_B)
#define NSTAGE   3
#define GEMM_SMEM (NSTAGE * STAGE_B)
#define NCHUNK   (DM / 32)

__global__ __launch_bounds__(256, 2) void gemm_tc(GemmArgs ar) {
    extern __shared__ char sm[];
    const uint32_t sbase = smem_u32(sm);

    const int tid = threadIdx.x;
    const int wid = tid >> 5;
    const int lid = tid & 31;
    const int z = blockIdx.z;

    const __half* xhi = ar.xhi + (size_t)z * ar.xstride;
    const __half* xlo = ar.xlo + (size_t)z * ar.xstride;
    const __half* whi = ar.whi + (size_t)z * ar.wstride;
    const __half* wlo = ar.wlo + (size_t)z * ar.wstride;
    const float* bias = (z == 0) ? ar.b0 : ((z == 1) ? ar.b1 : ar.b2);
    const float scale = (z == 0) ? ar.s0 : ((z == 1) ? ar.s1 : ar.s2);

    const int bm = blockIdx.y * 128;
    const int bn = blockIdx.x * 128;

    const int lrow0 = tid >> 2;
    const int lseg  = tid & 3;
    const uint32_t soff0 = swz64((uint32_t)(lrow0 * 64 + lseg * 16));
    const uint32_t soff1 = swz64((uint32_t)((lrow0 + 64) * 64 + lseg * 16));

    auto load_stage = [&](int chunk, int stage) {
        const int k0 = chunk * 32 + lseg * 8;
        const uint32_t st = sbase + stage * STAGE_B;
        const size_t ga0 = (size_t)(bm + lrow0) * DM + k0;
        const size_t ga1 = (size_t)(bm + lrow0 + 64) * DM + k0;
        const size_t gw0 = (size_t)(bn + lrow0) * DM + k0;
        const size_t gw1 = (size_t)(bn + lrow0 + 64) * DM + k0;
        cp_async16(st + soff0,              xhi + ga0);
        cp_async16(st + soff1,              xhi + ga1);
        cp_async16(st + TILE_B + soff0,     xlo + ga0);
        cp_async16(st + TILE_B + soff1,     xlo + ga1);
        cp_async16(st + 2 * TILE_B + soff0, whi + gw0);
        cp_async16(st + 2 * TILE_B + soff1, whi + gw1);
        cp_async16(st + 3 * TILE_B + soff0, wlo + gw0);
        cp_async16(st + 3 * TILE_B + soff1, wlo + gw1);
    };

    const int wm = wid & 3;
    const int wn = wid >> 2;
    const int lm_row = (lid & 7) + 8 * ((lid >> 3) & 1);
    const int lm_cb  = 16 * (lid >> 4);

    float acc[2][8][4];
#pragma unroll
    for (int i = 0; i < 2; i++)
#pragma unroll
        for (int j = 0; j < 8; j++)
#pragma unroll
            for (int k = 0; k < 4; k++) acc[i][j][k] = 0.0f;

    load_stage(0, 0); cp_commit();
    load_stage(1, 1); cp_commit();
    load_stage(2, 2); cp_commit();

    for (int c = 0; c < NCHUNK; c++) {
        cp_wait2();
        __syncthreads();
        const uint32_t st = sbase + (uint32_t)(c % 3) * STAGE_B;

#pragma unroll
        for (int ks = 0; ks < 2; ks++) {
            const int cb = ks * 32 + lm_cb;

            uint32_t ahi[2][4], alo[2][4];
#pragma unroll
            for (int mi = 0; mi < 2; mi++) {
                uint32_t off = swz64((uint32_t)((wm * 32 + mi * 16 + lm_row) * 64 + cb));
                ldsm4(ahi[mi], st + off);
                ldsm4(alo[mi], st + TILE_B + off);
            }
#pragma unroll
            for (int j = 0; j < 4; j++) {
                uint32_t off = swz64((uint32_t)((wn * 64 + j * 16 + lm_row) * 64 + cb));
                uint32_t rh[4], rl[4];
                ldsm4(rh, st + 2 * TILE_B + off);
                ldsm4(rl, st + 3 * TILE_B + off);
                uint32_t bh0[2] = { rh[0], rh[2] }, bh1[2] = { rh[1], rh[3] };
                uint32_t bl0[2] = { rl[0], rl[2] }, bl1[2] = { rl[1], rl[3] };
#pragma unroll
                for (int mi = 0; mi < 2; mi++) {
                    mma16816(acc[mi][2 * j],     ahi[mi], bh0);
                    mma16816(acc[mi][2 * j],     alo[mi], bh0);
                    mma16816(acc[mi][2 * j],     ahi[mi], bl0);
                    mma16816(acc[mi][2 * j + 1], ahi[mi], bh1);
                    mma16816(acc[mi][2 * j + 1], alo[mi], bh1);
                    mma16816(acc[mi][2 * j + 1], ahi[mi], bl1);
                }
            }
        }

        __syncthreads();
        if (c + 3 < NCHUNK) load_stage(c + 3, c % 3);
        cp_commit();
    }

    const int rbase = bm + wm * 32 + (lid >> 2);
    const int cbase = bn + wn * 64 + (lid & 3) * 2;
    float* out = (z == 0) ? ar.o0 : ((z == 1) ? ar.o1 : ar.o2);

    if (out) {
#pragma unroll
        for (int mi = 0; mi < 2; mi++) {
#pragma unroll
            for (int ni = 0; ni < 8; ni++) {
                int col = cbase + ni * 8;
                float bx = bias[col], by = bias[col + 1];
                int r0 = rbase + mi * 16;
                float2 v0 = make_float2((acc[mi][ni][0] + bx) * scale, (acc[mi][ni][1] + by) * scale);
                float2 v1 = make_float2((acc[mi][ni][2] + bx) * scale, (acc[mi][ni][3] + by) * scale);
                *(float2*)(out + (size_t)r0 * DM + col) = v0;
                *(float2*)(out + (size_t)(r0 + 8) * DM + col) = v1;
            }
        }
    } else {
        __half* ohi = (z == 0) ? ar.ohi0 : ((z == 1) ? ar.ohi1 : ar.ohi2);
        __half* olo = (z == 0) ? ar.olo0 : ((z == 1) ? ar.olo1 : ar.olo2);
#pragma unroll
        for (int mi = 0; mi < 2; mi++) {
#pragma unroll
            for (int ni = 0; ni < 8; ni++) {
                int col = cbase + ni * 8;
                float bx = bias[col], by = bias[col + 1];
                int r0 = rbase + mi * 16;
                float v00 = (acc[mi][ni][0] + bx) * scale, v01 = (acc[mi][ni][1] + by) * scale;
                float v10 = (acc[mi][ni][2] + bx) * scale, v11 = (acc[mi][ni][3] + by) * scale;
                __half2 h0 = __floats2half2_rn(v00, v01);
                __half2 h1 = __floats2half2_rn(v10, v11);
                float2 f0 = __half22float2(h0);
                float2 f1 = __half22float2(h1);
                size_t p0 = (size_t)r0 * DM + col;
                size_t p1 = (size_t)(r0 + 8) * DM + col;
                *(__half2*)(ohi + p0) = h0;
                *(__half2*)(ohi + p1) = h1;
                *(__half2*)(olo + p0) = __floats2half2_rn(v00 - f0.x, v01 - f0.y);
                *(__half2*)(olo + p1) = __floats2half2_rn(v10 - f1.x, v11 - f1.y);
            }
        }
    }
}

// ---------------------------------------------------------------------------
// Tensor-core flash attention — fp16 probabilities, MMA row-sums
// ---------------------------------------------------------------------------
#define AKV_BASE 32768
#define AKV_STAGE 65536
#define ATTN_SMEM (32768 + 2 * AKV_STAGE + 1024)

__global__ __launch_bounds__(256) void attn_mma()
{
    extern __shared__ char sm_raw[];
    const uint32_t sraw = smem_u32(sm_raw);
    const uint32_t sbase = (sraw + 1023u) & ~1023u;

    const int tid = threadIdx.x;
    const int wid = tid >> 5;
    const int lid = tid & 31;
    const int b = blockIdx.z;
    const int h = blockIdx.y;
    const int q0 = blockIdx.x * 128;

    // ---- Q tile load (split hi/lo) ----
#pragma unroll
    for (int i = 0; i < 8; i++) {
        int s = tid + 256 * i;
        int buf = s >> 10;
        int r = (s & 1023) >> 3;
        int sg = s & 7;
        uint32_t off = ((uint32_t)(r * 128 + sg * 16)) ^ (((uint32_t)(r & 7)) << 4);
        const __half* src = (buf ? g_qlo : g_qhi) + (size_t)(b * SEQ + q0 + r) * DM + h * DKH + sg * 8;
        cp_async16(sbase + (uint32_t)buf * 16384 + off, src);
    }
    cp_commit();

    auto issue_kv = [&](int t, int stg) {
        const int kv0 = t * 128;
        const uint32_t stb = sbase + AKV_BASE + (uint32_t)stg * AKV_STAGE;
#pragma unroll
        for (int i = 0; i < 16; i++) {
            int s = tid + 256 * i;
            int buf = s >> 10;         // 0=khi,1=klo,2=vhi,3=vlo
            int r = (s & 1023) >> 3;
            int sg = s & 7;
            uint32_t off = ((uint32_t)(r * 128 + sg * 16)) ^ (((uint32_t)(r & 7)) << 4);
            const __half* base = (buf == 0) ? g_khi : ((buf == 1) ? g_klo : ((buf == 2) ? g_vhi : g_vlo));
            cp_async16(stb + (uint32_t)buf * 16384 + off,
                       base + (size_t)(b * SEQ + kv0 + r) * DM + h * DKH + sg * 8);
        }
    };

    issue_kv(0, 0); cp_commit();

    const int lm_row = (lid & 7) + 8 * ((lid >> 3) & 1);
    const uint32_t rbyte = (uint32_t)(lm_row * 128);
    const uint32_t lsw = ((uint32_t)(lm_row & 7)) << 4;
    const uint32_t cpick = (uint32_t)(16 * (lid >> 4));

    cp_wait1();
    __syncthreads();
    uint32_t aq_hi[4][4], aq_lo[4][4];
    {
        uint32_t qb_hi = sbase + (uint32_t)(wid * 2048) + rbyte;
        uint32_t qb_lo = qb_hi + 16384;
#pragma unroll
        for (int kg = 0; kg < 4; kg++) {
            uint32_t cb = (cpick + kg * 32) ^ lsw;
            ldsm4(aq_hi[kg], qb_hi + cb);
            ldsm4(aq_lo[kg], qb_lo + cb);
        }
    }

    float m0 = -1e30f, m1 = -1e30f;
    float acc_l[4];
    float acc_o[8][4];
#pragma unroll
    for (int j = 0; j < 4; j++) acc_l[j] = 0.0f;
#pragma unroll
    for (int n = 0; n < 8; n++)
#pragma unroll
        for (int j = 0; j < 4; j++) acc_o[n][j] = 0.0f;

    const uint32_t ones2[2] = { 0x3C003C00u, 0x3C003C00u };   // half2(1,1)

    for (int t = 0; t < SEQ / 128; t++) {
        cp_wait0();
        __syncthreads();

        if (t + 1 < SEQ / 128) { issue_kv(t + 1, (t + 1) & 1); cp_commit(); }

        const uint32_t stb = sbase + AKV_BASE + (uint32_t)(t & 1) * AKV_STAGE;
        const uint32_t kb_hi = stb + rbyte;
        const uint32_t kb_lo = kb_hi + 16384;
        const uint32_t vb_hi = kb_hi + 32768;
        const uint32_t vb_lo = kb_hi + 49152;

        // ---- QK^T (3-term split) ----
        float c[16][4];
#pragma unroll
        for (int j = 0; j < 16; j++)
#pragma unroll
            for (int q = 0; q < 4; q++) c[j][q] = 0.0f;

#pragma unroll
        for (int j2 = 0; j2 < 8; j2++) {
            const uint32_t rowoff = (uint32_t)(j2 * 2048);
#pragma unroll
            for (int kg = 0; kg < 4; kg++) {
                uint32_t cb = (cpick + kg * 32) ^ lsw;
                uint32_t rh[4], rl[4];
                ldsm4(rh, kb_hi + rowoff + cb);
                ldsm4(rl, kb_lo + rowoff + cb);
                uint32_t bh0[2] = { rh[0], rh[2] }, bh1[2] = { rh[1], rh[3] };
                uint32_t bl0[2] = { rl[0], rl[2] }, bl1[2] = { rl[1], rl[3] };
                mma16816(c[2 * j2],     aq_hi[kg], bh0);
                mma16816(c[2 * j2],     aq_hi[kg], bl0);
                mma16816(c[2 * j2],     aq_lo[kg], bh0);
                mma16816(c[2 * j2 + 1], aq_hi[kg], bh1);
                mma16816(c[2 * j2 + 1], aq_hi[kg], bl1);
                mma16816(c[2 * j2 + 1], aq_lo[kg], bh1);
            }
        }

        // ---- online softmax (base-2, probabilities in fp16) ----
        float mx0 = -1e30f, mx1 = -1e30f;
#pragma unroll
        for (int j = 0; j < 16; j++) {
            mx0 = fmaxf(mx0, fmaxf(c[j][0], c[j][1]));
            mx1 = fmaxf(mx1, fmaxf(c[j][2], c[j][3]));
        }
        mx0 = fmaxf(mx0, __shfl_xor_sync(0xffffffffu, mx0, 1));
        mx0 = fmaxf(mx0, __shfl_xor_sync(0xffffffffu, mx0, 2));
        mx1 = fmaxf(mx1, __shfl_xor_sync(0xffffffffu, mx1, 1));
        mx1 = fmaxf(mx1, __shfl_xor_sync(0xffffffffu, mx1, 2));

        float mn0 = fmaxf(m0, mx0), mn1 = fmaxf(m1, mx1);
        float al0 = ex2f(m0 - mn0), al1 = ex2f(m1 - mn1);
        m0 = mn0; m1 = mn1;

        acc_l[0] *= al0; acc_l[1] *= al0;
        acc_l[2] *= al1; acc_l[3] *= al1;
#pragma unroll
        for (int n = 0; n < 8; n++) {
            acc_o[n][0] *= al0; acc_o[n][1] *= al0;
            acc_o[n][2] *= al1; acc_o[n][3] *= al1;
        }

        // p = 2^(s-m) computed directly in fp16x2 (A-frag ready)
        uint32_t ph[16][2];
#pragma unroll
        for (int j = 0; j < 16; j++) {
            ph[j][0] = ex2_h2(h2u(__floats2half2_rn(c[j][0] - mn0, c[j][1] - mn0)));
            ph[j][1] = ex2_h2(h2u(__floats2half2_rn(c[j][2] - mn1, c[j][3] - mn1)));
        }

        // ---- row sums (P x ones) + PV (2-term: V split, P exact fp16) ----
#pragma unroll
        for (int kg = 0; kg < 8; kg++) {
            uint32_t A[4] = { ph[2 * kg][0], ph[2 * kg][1], ph[2 * kg + 1][0], ph[2 * kg + 1][1] };

            mma16816(acc_l, A, ones2);

            const uint32_t kvoff = (uint32_t)(kg * 2048);
#pragma unroll
            for (int d2 = 0; d2 < 4; d2++) {
                uint32_t cb = (cpick + d2 * 32) ^ lsw;
                uint32_t rhv[4], rlv[4];
                ldsm4t(rhv, vb_hi + kvoff + cb);
                ldsm4t(rlv, vb_lo + kvoff + cb);
                uint32_t bh0[2] = { rhv[0], rhv[1] }, bh1[2] = { rhv[2], rhv[3] };
                uint32_t bl0[2] = { rlv[0], rlv[1] }, bl1[2] = { rlv[2], rlv[3] };
                mma16816(acc_o[2 * d2],     A, bh0);
                mma16816(acc_o[2 * d2],     A, bl0);
                mma16816(acc_o[2 * d2 + 1], A, bh1);
                mma16816(acc_o[2 * d2 + 1], A, bl1);
            }
        }
    }

    // ---- normalize + store split ctx ----
    const float inv0 = 1.0f / acc_l[0];
    const float inv1 = 1.0f / acc_l[2];
    const int gr0 = q0 + wid * 16 + (lid >> 2);
    const int gr1 = gr0 + 8;
    const int colb = h * DKH + (lid & 3) * 2;
#pragma unroll
    for (int n = 0; n < 8; n++) {
        int col = colb + n * 8;
        size_t o0 = (size_t)(b * SEQ + gr0) * DM + col;
        size_t o1 = (size_t)(b * SEQ + gr1) * DM + col;
        float vx0 = acc_o[n][0] * inv0, vy0 = acc_o[n][1] * inv0;
        float vx1 = acc_o[n][2] * inv1, vy1 = acc_o[n][3] * inv1;
        __half2 h0 = __floats2half2_rn(vx0, vy0);
        __half2 h1 = __floats2half2_rn(vx1, vy1);
        float2 f0 = __half22float2(h0);
        float2 f1 = __half22float2(h1);
        *(__half2*)(g_chi + o0) = h0;
        *(__half2*)(g_chi + o1) = h1;
        *(__half2*)(g_clo + o0) = __floats2half2_rn(vx0 - f0.x, vy0 - f0.y);
        *(__half2*)(g_clo + o1) = __floats2half2_rn(vx1 - f1.x, vy1 - f1.y);
    }
}

// ---------------------------------------------------------------------------
#define QSCALE 0.18033688f   // (1/8) * log2(e)

extern "C" void kernel_launch(void* const* d_in, const int* in_sizes, int n_in,
                              void* d_out, int out_size)
{
    const float* query = (const float*)d_in[0];
    const float* key   = (const float*)d_in[1];
    const float* value = (const float*)d_in[2];
    const float* Wq    = (const float*)d_in[3];
    const float* bq    = (const float*)d_in[4];
    const float* Wk    = (const float*)d_in[5];
    const float* bk    = (const float*)d_in[6];
    const float* Wv    = (const float*)d_in[7];
    const float* bv    = (const float*)d_in[8];
    const float* Wo    = (const float*)d_in[9];
    const float* bo    = (const float*)d_in[10];

    __half *xhi, *xlo, *whi, *wlo, *chi, *clo;
    __half *qhi, *qlo, *khi, *klo, *vhi, *vlo;
    cudaGetSymbolAddress((void**)&xhi, g_xhi);
    cudaGetSymbolAddress((void**)&xlo, g_xlo);
    cudaGetSymbolAddress((void**)&whi, g_whi);
    cudaGetSymbolAddress((void**)&wlo, g_wlo);
    cudaGetSymbolAddress((void**)&chi, g_chi);
    cudaGetSymbolAddress((void**)&clo, g_clo);
    cudaGetSymbolAddress((void**)&qhi, g_qhi);
    cudaGetSymbolAddress((void**)&qlo, g_qlo);
    cudaGetSymbolAddress((void**)&khi, g_khi);
    cudaGetSymbolAddress((void**)&klo, g_klo);
    cudaGetSymbolAddress((void**)&vhi, g_vhi);
    cudaGetSymbolAddress((void**)&vlo, g_vlo);

    cudaFuncSetAttribute(gemm_tc, cudaFuncAttributeMaxDynamicSharedMemorySize, GEMM_SMEM);
    cudaFuncSetAttribute(attn_mma, cudaFuncAttributeMaxDynamicSharedMemorySize, ATTN_SMEM);

    const size_t XN = (size_t)MTOK * DM;
    const size_t WN = (size_t)DM * DM;
    const int xn4 = (int)(XN / 4), wn4 = (int)(WN / 4);

    split_f16<<<(xn4 + 255) / 256, 256>>>(query, xhi + 0 * XN, xlo + 0 * XN, xn4);
    split_f16<<<(xn4 + 255) / 256, 256>>>(key,   xhi + 1 * XN, xlo + 1 * XN, xn4);
    split_f16<<<(xn4 + 255) / 256, 256>>>(value, xhi + 2 * XN, xlo + 2 * XN, xn4);
    split_f16<<<(wn4 + 255) / 256, 256>>>(Wq, whi + 0 * WN, wlo + 0 * WN, wn4);
    split_f16<<<(wn4 + 255) / 256, 256>>>(Wk, whi + 1 * WN, wlo + 1 * WN, wn4);
    split_f16<<<(wn4 + 255) / 256, 256>>>(Wv, whi + 2 * WN, wlo + 2 * WN, wn4);
    split_f16<<<(wn4 + 255) / 256, 256>>>(Wo, whi + 3 * WN, wlo + 3 * WN, wn4);

    GemmArgs qkv;
    qkv.xhi = xhi; qkv.xlo = xlo; qkv.whi = whi; qkv.wlo = wlo;
    qkv.b0 = bq; qkv.b1 = bk; qkv.b2 = bv;
    qkv.o0 = nullptr; qkv.o1 = nullptr; qkv.o2 = nullptr;
    qkv.ohi0 = qhi; qkv.olo0 = qlo;
    qkv.ohi1 = khi; qkv.olo1 = klo;
    qkv.ohi2 = vhi; qkv.olo2 = vlo;
    qkv.s0 = QSCALE; qkv.s1 = 1.0f; qkv.s2 = 1.0f;
    qkv.xstride = (long long)XN; qkv.wstride = (long long)WN;
    gemm_tc<<<dim3(DM / 128, MTOK / 128, 3), 256, GEMM_SMEM>>>(qkv);

    attn_mma<<<dim3(SEQ / 128, NH, NB), 256, ATTN_SMEM>>>();

    GemmArgs og;
    og.xhi = chi; og.xlo = clo; og.whi = whi + 3 * WN; og.wlo = wlo + 3 * WN;
    og.b0 = bo; og.b1 = bo; og.b2 = bo;
    og.o0 = (float*)d_out; og.o1 = (float*)d_out; og.o2 = (float*)d_out;
    og.ohi0 = nullptr; og.olo0 = nullptr; og.ohi1 = nullptr; og.olo1 = nullptr;
    og.ohi2 = nullptr; og.olo2 = nullptr;
    og.s0 = 1.0f; og.s1 = 1.0f; og.s2 = 1.0f;
    og.xstride = 0; og.wstride = 0;
    gemm_tc<<<dim3(DM / 128, MTOK / 128, 1), 256, GEMM_SMEM>>>(og);
}

// round 11
// speedup vs baseline: 6.1014x; 1.3964x over previous
#include <cuda_runtime.h>
#include <cuda_fp16.h>
#include <math.h>
#include <stdint.h>

#define NH   16
#define DKH  64
#define DM   1024
#define NB   2
#define SEQ  2048
#define MTOK (NB * SEQ)   // 4096

// ---------------------------------------------------------------------------
// Device scratch
// ---------------------------------------------------------------------------
__device__ __half g_xhi[(size_t)3 * MTOK * DM];   // split q,k,v inputs
__device__ __half g_xlo[(size_t)3 * MTOK * DM];
__device__ __half g_whi[(size_t)4 * DM * DM];     // fp16 Wq,Wk,Wv,Wo (hi only)

__device__ __half g_qhi[(size_t)MTOK * DM];       // projected Q, split + pre-scaled
__device__ __half g_qlo[(size_t)MTOK * DM];
__device__ __half g_khi[(size_t)MTOK * DM];       // projected K (fp16 only)
__device__ __half g_vhi[(size_t)MTOK * DM];       // projected V (fp16 only)

__device__ __half g_chi[(size_t)MTOK * DM];       // split ctx (written by attn)
__device__ __half g_clo[(size_t)MTOK * DM];

// ---------------------------------------------------------------------------
// PTX helpers
// ---------------------------------------------------------------------------
__device__ __forceinline__ uint32_t smem_u32(const void* p) {
    uint32_t a;
    asm("{ .reg .u64 t; cvta.to.shared.u64 t, %1; cvt.u32.u64 %0, t; }" : "=r"(a) : "l"(p));
    return a;
}
__device__ __forceinline__ void cp_async16(uint32_t dst, const void* src) {
    asm volatile("cp.async.cg.shared.global [%0], [%1], 16;" :: "r"(dst), "l"(src));
}
__device__ __forceinline__ void cp_commit() {
    asm volatile("cp.async.commit_group;");
}
__device__ __forceinline__ void cp_wait0() {
    asm volatile("cp.async.wait_group 0;");
}
__device__ __forceinline__ void cp_wait1() {
    asm volatile("cp.async.wait_group 1;");
}
__device__ __forceinline__ void cp_wait2() {
    asm volatile("cp.async.wait_group 2;");
}
__device__ __forceinline__ void ldsm4(uint32_t* r, uint32_t addr) {
    asm volatile("ldmatrix.sync.aligned.m8n8.x4.shared.b16 {%0,%1,%2,%3}, [%4];"
                 : "=r"(r[0]), "=r"(r[1]), "=r"(r[2]), "=r"(r[3]) : "r"(addr));
}
__device__ __forceinline__ void ldsm4t(uint32_t* r, uint32_t addr) {
    asm volatile("ldmatrix.sync.aligned.m8n8.x4.trans.shared.b16 {%0,%1,%2,%3}, [%4];"
                 : "=r"(r[0]), "=r"(r[1]), "=r"(r[2]), "=r"(r[3]) : "r"(addr));
}
__device__ __forceinline__ void mma16816(float* c, const uint32_t* a, const uint32_t* b) {
    asm volatile(
        "mma.sync.aligned.m16n8k16.row.col.f32.f16.f16.f32 "
        "{%0,%1,%2,%3}, {%4,%5,%6,%7}, {%8,%9}, {%0,%1,%2,%3};"
        : "+f"(c[0]), "+f"(c[1]), "+f"(c[2]), "+f"(c[3])
        : "r"(a[0]), "r"(a[1]), "r"(a[2]), "r"(a[3]), "r"(b[0]), "r"(b[1]));
}
__device__ __forceinline__ float ex2f(float x) {
    float y;
    asm("ex2.approx.f32 %0, %1;" : "=f"(y) : "f"(x));
    return y;
}
__device__ __forceinline__ uint32_t ex2_h2(uint32_t x) {
    uint32_t y;
    asm("ex2.approx.f16x2 %0, %1;" : "=r"(y) : "r"(x));
    return y;
}
__device__ __forceinline__ uint32_t h2u(__half2 h) {
    return *reinterpret_cast<uint32_t*>(&h);
}
__device__ __forceinline__ uint32_t swz64(uint32_t off) {
    return off ^ (((off >> 7) & 3u) << 4);
}

// ---------------------------------------------------------------------------
// Conversions
// ---------------------------------------------------------------------------
__global__ __launch_bounds__(256) void split_f16(const float* __restrict__ src,
                                                 __half* __restrict__ hi,
                                                 __half* __restrict__ lo, int n4) {
    int i = blockIdx.x * blockDim.x + threadIdx.x;
    if (i >= n4) return;
    float4 v = ((const float4*)src)[i];
    __half h0 = __float2half_rn(v.x), h1 = __float2half_rn(v.y);
    __half h2 = __float2half_rn(v.z), h3 = __float2half_rn(v.w);
    __half l0 = __float2half_rn(v.x - __half2float(h0));
    __half l1 = __float2half_rn(v.y - __half2float(h1));
    __half l2 = __float2half_rn(v.z - __half2float(h2));
    __half l3 = __float2half_rn(v.w - __half2float(h3));
    ((__half2*)hi)[2 * i]     = __halves2half2(h0, h1);
    ((__half2*)hi)[2 * i + 1] = __halves2half2(h2, h3);
    ((__half2*)lo)[2 * i]     = __halves2half2(l0, l1);
    ((__half2*)lo)[2 * i + 1] = __halves2half2(l2, l3);
}

__global__ __launch_bounds__(256) void tohalf_f16(const float* __restrict__ src,
                                                  __half* __restrict__ hi, int n4) {
    int i = blockIdx.x * blockDim.x + threadIdx.x;
    if (i >= n4) return;
    float4 v = ((const float4*)src)[i];
    ((__half2*)hi)[2 * i]     = __floats2half2_rn(v.x, v.y);
    ((__half2*)hi)[2 * i + 1] = __floats2half2_rn(v.z, v.w);
}

// ---------------------------------------------------------------------------
// mma.sync GEMM (NT): C = A[M,K]*W[N,K]^T + bias; A split (hi+lo), W fp16.
// 2 MMAs per K-step: Ahi*W + Alo*W. 128x128 tile, BK=32, 3-stage, 2 CTAs/SM.
// ---------------------------------------------------------------------------
struct GemmArgs {
    const __half *xhi, *xlo, *whi;
    const float *b0, *b1, *b2;
    float *o0, *o1, *o2;                      // fp32 outputs (NULL => half mode)
    __half *ohi0, *olo0, *ohi1, *olo1, *ohi2, *olo2;   // olo may be NULL (hi only)
    float s0, s1, s2;
    long long xstride, wstride;
};

#define TILE_B   8192
#define STAGE_B  (3 * TILE_B)                 // Ahi, Alo, Whi = 24 KB
#define NSTAGE   3
#define GEMM_SMEM (NSTAGE * STAGE_B)          // 72 KB
#define NCHUNK   (DM / 32)

__global__ __launch_bounds__(256, 2) void gemm_tc(GemmArgs ar) {
    extern __shared__ char sm[];
    const uint32_t sbase = smem_u32(sm);

    const int tid = threadIdx.x;
    const int wid = tid >> 5;
    const int lid = tid & 31;
    const int z = blockIdx.z;

    const __half* xhi = ar.xhi + (size_t)z * ar.xstride;
    const __half* xlo = ar.xlo + (size_t)z * ar.xstride;
    const __half* whi = ar.whi + (size_t)z * ar.wstride;
    const float* bias = (z == 0) ? ar.b0 : ((z == 1) ? ar.b1 : ar.b2);
    const float scale = (z == 0) ? ar.s0 : ((z == 1) ? ar.s1 : ar.s2);

    const int bm = blockIdx.y * 128;
    const int bn = blockIdx.x * 128;

    const int lrow0 = tid >> 2;
    const int lseg  = tid & 3;
    const uint32_t soff0 = swz64((uint32_t)(lrow0 * 64 + lseg * 16));
    const uint32_t soff1 = swz64((uint32_t)((lrow0 + 64) * 64 + lseg * 16));

    auto load_stage = [&](int chunk, int stage) {
        const int k0 = chunk * 32 + lseg * 8;
        const uint32_t st = sbase + stage * STAGE_B;
        const size_t ga0 = (size_t)(bm + lrow0) * DM + k0;
        const size_t ga1 = (size_t)(bm + lrow0 + 64) * DM + k0;
        const size_t gw0 = (size_t)(bn + lrow0) * DM + k0;
        const size_t gw1 = (size_t)(bn + lrow0 + 64) * DM + k0;
        cp_async16(st + soff0,              xhi + ga0);
        cp_async16(st + soff1,              xhi + ga1);
        cp_async16(st + TILE_B + soff0,     xlo + ga0);
        cp_async16(st + TILE_B + soff1,     xlo + ga1);
        cp_async16(st + 2 * TILE_B + soff0, whi + gw0);
        cp_async16(st + 2 * TILE_B + soff1, whi + gw1);
    };

    const int wm = wid & 3;
    const int wn = wid >> 2;
    const int lm_row = (lid & 7) + 8 * ((lid >> 3) & 1);
    const int lm_cb  = 16 * (lid >> 4);

    float acc[2][8][4];
#pragma unroll
    for (int i = 0; i < 2; i++)
#pragma unroll
        for (int j = 0; j < 8; j++)
#pragma unroll
            for (int k = 0; k < 4; k++) acc[i][j][k] = 0.0f;

    load_stage(0, 0); cp_commit();
    load_stage(1, 1); cp_commit();
    load_stage(2, 2); cp_commit();

    for (int c = 0; c < NCHUNK; c++) {
        cp_wait2();
        __syncthreads();
        const uint32_t st = sbase + (uint32_t)(c % 3) * STAGE_B;

#pragma unroll
        for (int ks = 0; ks < 2; ks++) {
            const int cb = ks * 32 + lm_cb;

            uint32_t ahi[2][4], alo[2][4];
#pragma unroll
            for (int mi = 0; mi < 2; mi++) {
                uint32_t off = swz64((uint32_t)((wm * 32 + mi * 16 + lm_row) * 64 + cb));
                ldsm4(ahi[mi], st + off);
                ldsm4(alo[mi], st + TILE_B + off);
            }
#pragma unroll
            for (int j = 0; j < 4; j++) {
                uint32_t off = swz64((uint32_t)((wn * 64 + j * 16 + lm_row) * 64 + cb));
                uint32_t rh[4];
                ldsm4(rh, st + 2 * TILE_B + off);
                uint32_t bh0[2] = { rh[0], rh[2] }, bh1[2] = { rh[1], rh[3] };
#pragma unroll
                for (int mi = 0; mi < 2; mi++) {
                    mma16816(acc[mi][2 * j],     ahi[mi], bh0);
                    mma16816(acc[mi][2 * j],     alo[mi], bh0);
                    mma16816(acc[mi][2 * j + 1], ahi[mi], bh1);
                    mma16816(acc[mi][2 * j + 1], alo[mi], bh1);
                }
            }
        }

        __syncthreads();
        if (c + 3 < NCHUNK) load_stage(c + 3, c % 3);
        cp_commit();
    }

    const int rbase = bm + wm * 32 + (lid >> 2);
    const int cbase = bn + wn * 64 + (lid & 3) * 2;
    float* out = (z == 0) ? ar.o0 : ((z == 1) ? ar.o1 : ar.o2);

    if (out) {
#pragma unroll
        for (int mi = 0; mi < 2; mi++) {
#pragma unroll
            for (int ni = 0; ni < 8; ni++) {
                int col = cbase + ni * 8;
                float bx = bias[col], by = bias[col + 1];
                int r0 = rbase + mi * 16;
                float2 v0 = make_float2((acc[mi][ni][0] + bx) * scale, (acc[mi][ni][1] + by) * scale);
                float2 v1 = make_float2((acc[mi][ni][2] + bx) * scale, (acc[mi][ni][3] + by) * scale);
                *(float2*)(out + (size_t)r0 * DM + col) = v0;
                *(float2*)(out + (size_t)(r0 + 8) * DM + col) = v1;
            }
        }
    } else {
        __half* ohi = (z == 0) ? ar.ohi0 : ((z == 1) ? ar.ohi1 : ar.ohi2);
        __half* olo = (z == 0) ? ar.olo0 : ((z == 1) ? ar.olo1 : ar.olo2);
#pragma unroll
        for (int mi = 0; mi < 2; mi++) {
#pragma unroll
            for (int ni = 0; ni < 8; ni++) {
                int col = cbase + ni * 8;
                float bx = bias[col], by = bias[col + 1];
                int r0 = rbase + mi * 16;
                float v00 = (acc[mi][ni][0] + bx) * scale, v01 = (acc[mi][ni][1] + by) * scale;
                float v10 = (acc[mi][ni][2] + bx) * scale, v11 = (acc[mi][ni][3] + by) * scale;
                __half2 h0 = __floats2half2_rn(v00, v01);
                __half2 h1 = __floats2half2_rn(v10, v11);
                size_t p0 = (size_t)r0 * DM + col;
                size_t p1 = (size_t)(r0 + 8) * DM + col;
                *(__half2*)(ohi + p0) = h0;
                *(__half2*)(ohi + p1) = h1;
                if (olo) {
                    float2 f0 = __half22float2(h0);
                    float2 f1 = __half22float2(h1);
                    *(__half2*)(olo + p0) = __floats2half2_rn(v00 - f0.x, v01 - f0.y);
                    *(__half2*)(olo + p1) = __floats2half2_rn(v10 - f1.x, v11 - f1.y);
                }
            }
        }
    }
}

// ---------------------------------------------------------------------------
// Tensor-core flash attention — Q split, K/V fp16, fp16 P, MMA row-sums
// smem: [0,16K) Q hi, [16K,32K) Q lo, stage s at 32K+s*32K: {K 16K | V 16K}
// ---------------------------------------------------------------------------
#define AKV_BASE 32768
#define AKV_STAGE 32768
#define ATTN_SMEM (32768 + 2 * AKV_STAGE + 1024)

__global__ __launch_bounds__(256) void attn_mma()
{
    extern __shared__ char sm_raw[];
    const uint32_t sraw = smem_u32(sm_raw);
    const uint32_t sbase = (sraw + 1023u) & ~1023u;

    const int tid = threadIdx.x;
    const int wid = tid >> 5;
    const int lid = tid & 31;
    const int b = blockIdx.z;
    const int h = blockIdx.y;
    const int q0 = blockIdx.x * 128;

    // ---- Q tile load (split hi/lo): 2048 segments, 8/thread ----
#pragma unroll
    for (int i = 0; i < 8; i++) {
        int s = tid + 256 * i;
        int buf = s >> 10;
        int r = (s & 1023) >> 3;
        int sg = s & 7;
        uint32_t off = ((uint32_t)(r * 128 + sg * 16)) ^ (((uint32_t)(r & 7)) << 4);
        const __half* src = (buf ? g_qlo : g_qhi) + (size_t)(b * SEQ + q0 + r) * DM + h * DKH + sg * 8;
        cp_async16(sbase + (uint32_t)buf * 16384 + off, src);
    }
    cp_commit();

    // ---- KV loader: K + V fp16, 2048 segments, 8/thread ----
    auto issue_kv = [&](int t, int stg) {
        const int kv0 = t * 128;
        const uint32_t stb = sbase + AKV_BASE + (uint32_t)stg * AKV_STAGE;
#pragma unroll
        for (int i = 0; i < 8; i++) {
            int s = tid + 256 * i;
            int buf = s >> 10;         // 0=K, 1=V
            int r = (s & 1023) >> 3;
            int sg = s & 7;
            uint32_t off = ((uint32_t)(r * 128 + sg * 16)) ^ (((uint32_t)(r & 7)) << 4);
            const __half* base = buf ? g_vhi : g_khi;
            cp_async16(stb + (uint32_t)buf * 16384 + off,
                       base + (size_t)(b * SEQ + kv0 + r) * DM + h * DKH + sg * 8);
        }
    };

    issue_kv(0, 0); cp_commit();

    const int lm_row = (lid & 7) + 8 * ((lid >> 3) & 1);
    const uint32_t rbyte = (uint32_t)(lm_row * 128);
    const uint32_t lsw = ((uint32_t)(lm_row & 7)) << 4;
    const uint32_t cpick = (uint32_t)(16 * (lid >> 4));

    cp_wait1();
    __syncthreads();
    uint32_t aq_hi[4][4], aq_lo[4][4];
    {
        uint32_t qb_hi = sbase + (uint32_t)(wid * 2048) + rbyte;
        uint32_t qb_lo = qb_hi + 16384;
#pragma unroll
        for (int kg = 0; kg < 4; kg++) {
            uint32_t cb = (cpick + kg * 32) ^ lsw;
            ldsm4(aq_hi[kg], qb_hi + cb);
            ldsm4(aq_lo[kg], qb_lo + cb);
        }
    }

    float m0 = -1e30f, m1 = -1e30f;
    float acc_l[4];
    float acc_o[8][4];
#pragma unroll
    for (int j = 0; j < 4; j++) acc_l[j] = 0.0f;
#pragma unroll
    for (int n = 0; n < 8; n++)
#pragma unroll
        for (int j = 0; j < 4; j++) acc_o[n][j] = 0.0f;

    const uint32_t ones2[2] = { 0x3C003C00u, 0x3C003C00u };   // half2(1,1)

    for (int t = 0; t < SEQ / 128; t++) {
        cp_wait0();
        __syncthreads();

        if (t + 1 < SEQ / 128) { issue_kv(t + 1, (t + 1) & 1); cp_commit(); }

        const uint32_t stb = sbase + AKV_BASE + (uint32_t)(t & 1) * AKV_STAGE;
        const uint32_t kb = stb + rbyte;
        const uint32_t vb = kb + 16384;

        // ---- QK^T (2-term: q_hi*k + q_lo*k) ----
        float c[16][4];
#pragma unroll
        for (int j = 0; j < 16; j++)
#pragma unroll
            for (int q = 0; q < 4; q++) c[j][q] = 0.0f;

#pragma unroll
        for (int j2 = 0; j2 < 8; j2++) {
            const uint32_t rowoff = (uint32_t)(j2 * 2048);
#pragma unroll
            for (int kg = 0; kg < 4; kg++) {
                uint32_t cb = (cpick + kg * 32) ^ lsw;
                uint32_t rh[4];
                ldsm4(rh, kb + rowoff + cb);
                uint32_t bh0[2] = { rh[0], rh[2] }, bh1[2] = { rh[1], rh[3] };
                mma16816(c[2 * j2],     aq_hi[kg], bh0);
                mma16816(c[2 * j2],     aq_lo[kg], bh0);
                mma16816(c[2 * j2 + 1], aq_hi[kg], bh1);
                mma16816(c[2 * j2 + 1], aq_lo[kg], bh1);
            }
        }

        // ---- online softmax (base-2, fp16 probabilities) ----
        float mx0 = -1e30f, mx1 = -1e30f;
#pragma unroll
        for (int j = 0; j < 16; j++) {
            mx0 = fmaxf(mx0, fmaxf(c[j][0], c[j][1]));
            mx1 = fmaxf(mx1, fmaxf(c[j][2], c[j][3]));
        }
        mx0 = fmaxf(mx0, __shfl_xor_sync(0xffffffffu, mx0, 1));
        mx0 = fmaxf(mx0, __shfl_xor_sync(0xffffffffu, mx0, 2));
        mx1 = fmaxf(mx1, __shfl_xor_sync(0xffffffffu, mx1, 1));
        mx1 = fmaxf(mx1, __shfl_xor_sync(0xffffffffu, mx1, 2));

        float mn0 = fmaxf(m0, mx0), mn1 = fmaxf(m1, mx1);
        float al0 = ex2f(m0 - mn0), al1 = ex2f(m1 - mn1);
        m0 = mn0; m1 = mn1;

        acc_l[0] *= al0; acc_l[1] *= al0;
        acc_l[2] *= al1; acc_l[3] *= al1;
#pragma unroll
        for (int n = 0; n < 8; n++) {
            acc_o[n][0] *= al0; acc_o[n][1] *= al0;
            acc_o[n][2] *= al1; acc_o[n][3] *= al1;
        }

        uint32_t ph[16][2];
#pragma unroll
        for (int j = 0; j < 16; j++) {
            ph[j][0] = ex2_h2(h2u(__floats2half2_rn(c[j][0] - mn0, c[j][1] - mn0)));
            ph[j][1] = ex2_h2(h2u(__floats2half2_rn(c[j][2] - mn1, c[j][3] - mn1)));
        }

        // ---- row sums (P x ones) + PV (V fp16) ----
#pragma unroll
        for (int kg = 0; kg < 8; kg++) {
            uint32_t A[4] = { ph[2 * kg][0], ph[2 * kg][1], ph[2 * kg + 1][0], ph[2 * kg + 1][1] };

            mma16816(acc_l, A, ones2);

            const uint32_t kvoff = (uint32_t)(kg * 2048);
#pragma unroll
            for (int d2 = 0; d2 < 4; d2++) {
                uint32_t cb = (cpick + d2 * 32) ^ lsw;
                uint32_t rhv[4];
                ldsm4t(rhv, vb + kvoff + cb);
                uint32_t bh0[2] = { rhv[0], rhv[1] }, bh1[2] = { rhv[2], rhv[3] };
                mma16816(acc_o[2 * d2],     A, bh0);
                mma16816(acc_o[2 * d2 + 1], A, bh1);
            }
        }
    }

    // ---- normalize + store split ctx ----
    const float inv0 = 1.0f / acc_l[0];
    const float inv1 = 1.0f / acc_l[2];
    const int gr0 = q0 + wid * 16 + (lid >> 2);
    const int gr1 = gr0 + 8;
    const int colb = h * DKH + (lid & 3) * 2;
#pragma unroll
    for (int n = 0; n < 8; n++) {
        int col = colb + n * 8;
        size_t o0 = (size_t)(b * SEQ + gr0) * DM + col;
        size_t o1 = (size_t)(b * SEQ + gr1) * DM + col;
        float vx0 = acc_o[n][0] * inv0, vy0 = acc_o[n][1] * inv0;
        float vx1 = acc_o[n][2] * inv1, vy1 = acc_o[n][3] * inv1;
        __half2 h0 = __floats2half2_rn(vx0, vy0);
        __half2 h1 = __floats2half2_rn(vx1, vy1);
        float2 f0 = __half22float2(h0);
        float2 f1 = __half22float2(h1);
        *(__half2*)(g_chi + o0) = h0;
        *(__half2*)(g_chi + o1) = h1;
        *(__half2*)(g_clo + o0) = __floats2half2_rn(vx0 - f0.x, vy0 - f0.y);
        *(__half2*)(g_clo + o1) = __floats2half2_rn(vx1 - f1.x, vy1 - f1.y);
    }
}

// ---------------------------------------------------------------------------
#define QSCALE 0.18033688f   // (1/8) * log2(e)

extern "C" void kernel_launch(void* const* d_in, const int* in_sizes, int n_in,
                              void* d_out, int out_size)
{
    const float* query = (const float*)d_in[0];
    const float* key   = (const float*)d_in[1];
    const float* value = (const float*)d_in[2];
    const float* Wq    = (const float*)d_in[3];
    const float* bq    = (const float*)d_in[4];
    const float* Wk    = (const float*)d_in[5];
    const float* bk    = (const float*)d_in[6];
    const float* Wv    = (const float*)d_in[7];
    const float* bv    = (const float*)d_in[8];
    const float* Wo    = (const float*)d_in[9];
    const float* bo    = (const float*)d_in[10];

    __half *xhi, *xlo, *whi, *chi, *clo;
    __half *qhi, *qlo, *khi, *vhi;
    cudaGetSymbolAddress((void**)&xhi, g_xhi);
    cudaGetSymbolAddress((void**)&xlo, g_xlo);
    cudaGetSymbolAddress((void**)&whi, g_whi);
    cudaGetSymbolAddress((void**)&chi, g_chi);
    cudaGetSymbolAddress((void**)&clo, g_clo);
    cudaGetSymbolAddress((void**)&qhi, g_qhi);
    cudaGetSymbolAddress((void**)&qlo, g_qlo);
    cudaGetSymbolAddress((void**)&khi, g_khi);
    cudaGetSymbolAddress((void**)&vhi, g_vhi);

    cudaFuncSetAttribute(gemm_tc, cudaFuncAttributeMaxDynamicSharedMemorySize, GEMM_SMEM);
    cudaFuncSetAttribute(attn_mma, cudaFuncAttributeMaxDynamicSharedMemorySize, ATTN_SMEM);

    const size_t XN = (size_t)MTOK * DM;
    const size_t WN = (size_t)DM * DM;
    const int xn4 = (int)(XN / 4), wn4 = (int)(WN / 4);

    split_f16<<<(xn4 + 255) / 256, 256>>>(query, xhi + 0 * XN, xlo + 0 * XN, xn4);
    split_f16<<<(xn4 + 255) / 256, 256>>>(key,   xhi + 1 * XN, xlo + 1 * XN, xn4);
    split_f16<<<(xn4 + 255) / 256, 256>>>(value, xhi + 2 * XN, xlo + 2 * XN, xn4);
    tohalf_f16<<<(wn4 + 255) / 256, 256>>>(Wq, whi + 0 * WN, wn4);
    tohalf_f16<<<(wn4 + 255) / 256, 256>>>(Wk, whi + 1 * WN, wn4);
    tohalf_f16<<<(wn4 + 255) / 256, 256>>>(Wv, whi + 2 * WN, wn4);
    tohalf_f16<<<(wn4 + 255) / 256, 256>>>(Wo, whi + 3 * WN, wn4);

    // QKV projections: Q -> split (pre-scaled), K/V -> fp16 only
    GemmArgs qkv;
    qkv.xhi = xhi; qkv.xlo = xlo; qkv.whi = whi;
    qkv.b0 = bq; qkv.b1 = bk; qkv.b2 = bv;
    qkv.o0 = nullptr; qkv.o1 = nullptr; qkv.o2 = nullptr;
    qkv.ohi0 = qhi; qkv.olo0 = qlo;
    qkv.ohi1 = khi; qkv.olo1 = nullptr;
    qkv.ohi2 = vhi; qkv.olo2 = nullptr;
    qkv.s0 = QSCALE; qkv.s1 = 1.0f; qkv.s2 = 1.0f;
    qkv.xstride = (long long)XN; qkv.wstride = (long long)WN;
    gemm_tc<<<dim3(DM / 128, MTOK / 128, 3), 256, GEMM_SMEM>>>(qkv);

    attn_mma<<<dim3(SEQ / 128, NH, NB), 256, ATTN_SMEM>>>();

    // O projection -> fp32 d_out (ctx split, Wo fp16)
    GemmArgs og;
    og.xhi = chi; og.xlo = clo; og.whi = whi + 3 * WN;
    og.b0 = bo; og.b1 = bo; og.b2 = bo;
    og.o0 = (float*)d_out; og.o1 = (float*)d_out; og.o2 = (float*)d_out;
    og.ohi0 = nullptr; og.olo0 = nullptr; og.ohi1 = nullptr; og.olo1 = nullptr;
    og.ohi2 = nullptr; og.olo2 = nullptr;
    og.s0 = 1.0f; og.s1 = 1.0f; og.s2 = 1.0f;
    og.xstride = 0; og.wstride = 0;
    gemm_tc<<<dim3(DM / 128, MTOK / 128, 1), 256, GEMM_SMEM>>>(og);
}

// round 12
// speedup vs baseline: 6.1158x; 1.0024x over previous
#include <cuda_runtime.h>
#include <cuda_fp16.h>
#include <math.h>
#include <stdint.h>

#define NH   16
#define DKH  64
#define DM   1024
#define NB   2
#define SEQ  2048
#define MTOK (NB * SEQ)   // 4096

// ---------------------------------------------------------------------------
// Device scratch
// ---------------------------------------------------------------------------
__device__ __half g_xhi[(size_t)3 * MTOK * DM];   // split q,k,v inputs
__device__ __half g_xlo[(size_t)3 * MTOK * DM];
__device__ __half g_whi[(size_t)4 * DM * DM];     // fp16 Wq,Wk,Wv,Wo

__device__ __half g_qhi[(size_t)MTOK * DM];       // projected Q, split + pre-scaled
__device__ __half g_qlo[(size_t)MTOK * DM];
__device__ __half g_khi[(size_t)MTOK * DM];       // projected K (fp16)
__device__ __half g_vhi[(size_t)MTOK * DM];       // projected V (fp16)

__device__ __half g_chi[(size_t)MTOK * DM];       // split ctx (written by attn)
__device__ __half g_clo[(size_t)MTOK * DM];

// ---------------------------------------------------------------------------
// PTX helpers
// ---------------------------------------------------------------------------
__device__ __forceinline__ uint32_t smem_u32(const void* p) {
    uint32_t a;
    asm("{ .reg .u64 t; cvta.to.shared.u64 t, %1; cvt.u32.u64 %0, t; }" : "=r"(a) : "l"(p));
    return a;
}
__device__ __forceinline__ void cp_async16(uint32_t dst, const void* src) {
    asm volatile("cp.async.cg.shared.global [%0], [%1], 16;" :: "r"(dst), "l"(src));
}
__device__ __forceinline__ void cp_commit() {
    asm volatile("cp.async.commit_group;");
}
__device__ __forceinline__ void cp_wait0() {
    asm volatile("cp.async.wait_group 0;");
}
__device__ __forceinline__ void cp_wait1() {
    asm volatile("cp.async.wait_group 1;");
}
__device__ __forceinline__ void cp_wait2() {
    asm volatile("cp.async.wait_group 2;");
}
__device__ __forceinline__ void ldsm4(uint32_t* r, uint32_t addr) {
    asm volatile("ldmatrix.sync.aligned.m8n8.x4.shared.b16 {%0,%1,%2,%3}, [%4];"
                 : "=r"(r[0]), "=r"(r[1]), "=r"(r[2]), "=r"(r[3]) : "r"(addr));
}
__device__ __forceinline__ void ldsm4t(uint32_t* r, uint32_t addr) {
    asm volatile("ldmatrix.sync.aligned.m8n8.x4.trans.shared.b16 {%0,%1,%2,%3}, [%4];"
                 : "=r"(r[0]), "=r"(r[1]), "=r"(r[2]), "=r"(r[3]) : "r"(addr));
}
__device__ __forceinline__ void mma16816(float* c, const uint32_t* a, const uint32_t* b) {
    asm volatile(
        "mma.sync.aligned.m16n8k16.row.col.f32.f16.f16.f32 "
        "{%0,%1,%2,%3}, {%4,%5,%6,%7}, {%8,%9}, {%0,%1,%2,%3};"
        : "+f"(c[0]), "+f"(c[1]), "+f"(c[2]), "+f"(c[3])
        : "r"(a[0]), "r"(a[1]), "r"(a[2]), "r"(a[3]), "r"(b[0]), "r"(b[1]));
}
__device__ __forceinline__ float ex2f(float x) {
    float y;
    asm("ex2.approx.f32 %0, %1;" : "=f"(y) : "f"(x));
    return y;
}
__device__ __forceinline__ uint32_t ex2_h2(uint32_t x) {
    uint32_t y;
    asm("ex2.approx.f16x2 %0, %1;" : "=r"(y) : "r"(x));
    return y;
}
__device__ __forceinline__ uint32_t h2u(__half2 h) {
    return *reinterpret_cast<uint32_t*>(&h);
}
__device__ __forceinline__ uint32_t swz64(uint32_t off) {
    return off ^ (((off >> 7) & 3u) << 4);
}

// ---------------------------------------------------------------------------
// Fused conversions: 3 split (q,k,v) + 4 tohalf (W) in one launch
// ---------------------------------------------------------------------------
struct ConvArgs {
    const float *x0, *x1, *x2;
    const float *w0, *w1, *w2, *w3;
    __half *xhi, *xlo, *whi;
};

#define XQ4 ((size_t)MTOK * DM / 4)   // 1048576 float4 per X tensor
#define WQ4 ((size_t)DM * DM / 4)     // 262144 float4 per W
#define CONV_TOTAL (3 * 1048576 + 4 * 262144)   // 4194304

__global__ __launch_bounds__(256) void convert_all(ConvArgs a) {
    size_t i = (size_t)blockIdx.x * 256 + threadIdx.x;
    if (i < 3 * XQ4) {
        int which = (int)(i / XQ4);
        size_t off = i - (size_t)which * XQ4;
        const float* src = (which == 0) ? a.x0 : ((which == 1) ? a.x1 : a.x2);
        float4 v = ((const float4*)src)[off];
        size_t o = (size_t)which * XQ4 + off;
        __half2 h0 = __floats2half2_rn(v.x, v.y);
        __half2 h1 = __floats2half2_rn(v.z, v.w);
        float2 f0 = __half22float2(h0);
        float2 f1 = __half22float2(h1);
        ((__half2*)a.xhi)[2 * o]     = h0;
        ((__half2*)a.xhi)[2 * o + 1] = h1;
        ((__half2*)a.xlo)[2 * o]     = __floats2half2_rn(v.x - f0.x, v.y - f0.y);
        ((__half2*)a.xlo)[2 * o + 1] = __floats2half2_rn(v.z - f1.x, v.w - f1.y);
    } else {
        size_t j = i - 3 * XQ4;
        int which = (int)(j / WQ4);
        size_t off = j - (size_t)which * WQ4;
        const float* src = (which == 0) ? a.w0 : ((which == 1) ? a.w1 : ((which == 2) ? a.w2 : a.w3));
        float4 v = ((const float4*)src)[off];
        size_t o = (size_t)which * WQ4 + off;
        ((__half2*)a.whi)[2 * o]     = __floats2half2_rn(v.x, v.y);
        ((__half2*)a.whi)[2 * o + 1] = __floats2half2_rn(v.z, v.w);
    }
}

// ---------------------------------------------------------------------------
// mma.sync GEMM (NT): C = A[M,K]*W[N,K]^T + bias; A split (hi+lo), W fp16.
// 128x128 tile, BK=32, 4-stage cp.async, single sync/chunk, 2 CTAs/SM.
// ---------------------------------------------------------------------------
struct GemmArgs {
    const __half *xhi, *xlo, *whi;
    const float *b0, *b1, *b2;
    float *o0, *o1, *o2;                      // fp32 outputs (NULL => half mode)
    __half *ohi0, *olo0, *ohi1, *olo1, *ohi2, *olo2;   // olo may be NULL
    float s0, s1, s2;
    long long xstride, wstride;
};

#define TILE_B   8192
#define STAGE_B  (3 * TILE_B)                 // Ahi, Alo, Whi = 24 KB
#define NSTAGE   4
#define GEMM_SMEM (NSTAGE * STAGE_B)          // 96 KB
#define NCHUNK   (DM / 32)

__global__ __launch_bounds__(256, 2) void gemm_tc(GemmArgs ar) {
    extern __shared__ char sm[];
    const uint32_t sbase = smem_u32(sm);

    const int tid = threadIdx.x;
    const int wid = tid >> 5;
    const int lid = tid & 31;
    const int z = blockIdx.z;

    const __half* xhi = ar.xhi + (size_t)z * ar.xstride;
    const __half* xlo = ar.xlo + (size_t)z * ar.xstride;
    const __half* whi = ar.whi + (size_t)z * ar.wstride;
    const float* bias = (z == 0) ? ar.b0 : ((z == 1) ? ar.b1 : ar.b2);
    const float scale = (z == 0) ? ar.s0 : ((z == 1) ? ar.s1 : ar.s2);

    const int bm = blockIdx.y * 128;
    const int bn = blockIdx.x * 128;

    const int lrow0 = tid >> 2;
    const int lseg  = tid & 3;
    const uint32_t soff0 = swz64((uint32_t)(lrow0 * 64 + lseg * 16));
    const uint32_t soff1 = swz64((uint32_t)((lrow0 + 64) * 64 + lseg * 16));

    auto load_stage = [&](int chunk, int stage) {
        const int k0 = chunk * 32 + lseg * 8;
        const uint32_t st = sbase + stage * STAGE_B;
        const size_t ga0 = (size_t)(bm + lrow0) * DM + k0;
        const size_t ga1 = (size_t)(bm + lrow0 + 64) * DM + k0;
        const size_t gw0 = (size_t)(bn + lrow0) * DM + k0;
        const size_t gw1 = (size_t)(bn + lrow0 + 64) * DM + k0;
        cp_async16(st + soff0,              xhi + ga0);
        cp_async16(st + soff1,              xhi + ga1);
        cp_async16(st + TILE_B + soff0,     xlo + ga0);
        cp_async16(st + TILE_B + soff1,     xlo + ga1);
        cp_async16(st + 2 * TILE_B + soff0, whi + gw0);
        cp_async16(st + 2 * TILE_B + soff1, whi + gw1);
    };

    const int wm = wid & 3;
    const int wn = wid >> 2;
    const int lm_row = (lid & 7) + 8 * ((lid >> 3) & 1);
    const int lm_cb  = 16 * (lid >> 4);

    float acc[2][8][4];
#pragma unroll
    for (int i = 0; i < 2; i++)
#pragma unroll
        for (int j = 0; j < 8; j++)
#pragma unroll
            for (int k = 0; k < 4; k++) acc[i][j][k] = 0.0f;

    load_stage(0, 0); cp_commit();
    load_stage(1, 1); cp_commit();
    load_stage(2, 2); cp_commit();

    for (int c = 0; c < NCHUNK; c++) {
        cp_wait2();
        __syncthreads();
        // prefetch chunk c+3 into buffer (c+3)&3 = (c-1)&3 (compute done last iter)
        if (c + 3 < NCHUNK) load_stage(c + 3, (c + 3) & 3);
        cp_commit();

        const uint32_t st = sbase + (uint32_t)(c & 3) * STAGE_B;

#pragma unroll
        for (int ks = 0; ks < 2; ks++) {
            const int cb = ks * 32 + lm_cb;

            uint32_t ahi[2][4], alo[2][4];
#pragma unroll
            for (int mi = 0; mi < 2; mi++) {
                uint32_t off = swz64((uint32_t)((wm * 32 + mi * 16 + lm_row) * 64 + cb));
                ldsm4(ahi[mi], st + off);
                ldsm4(alo[mi], st + TILE_B + off);
            }
#pragma unroll
            for (int j = 0; j < 4; j++) {
                uint32_t off = swz64((uint32_t)((wn * 64 + j * 16 + lm_row) * 64 + cb));
                uint32_t rh[4];
                ldsm4(rh, st + 2 * TILE_B + off);
                uint32_t bh0[2] = { rh[0], rh[2] }, bh1[2] = { rh[1], rh[3] };
#pragma unroll
                for (int mi = 0; mi < 2; mi++) {
                    mma16816(acc[mi][2 * j],     ahi[mi], bh0);
                    mma16816(acc[mi][2 * j],     alo[mi], bh0);
                    mma16816(acc[mi][2 * j + 1], ahi[mi], bh1);
                    mma16816(acc[mi][2 * j + 1], alo[mi], bh1);
                }
            }
        }
        __syncthreads();   // compute done before next iter's prefetch overwrites
    }

    const int rbase = bm + wm * 32 + (lid >> 2);
    const int cbase = bn + wn * 64 + (lid & 3) * 2;
    float* out = (z == 0) ? ar.o0 : ((z == 1) ? ar.o1 : ar.o2);

    if (out) {
#pragma unroll
        for (int mi = 0; mi < 2; mi++) {
#pragma unroll
            for (int ni = 0; ni < 8; ni++) {
                int col = cbase + ni * 8;
                float bx = bias[col], by = bias[col + 1];
                int r0 = rbase + mi * 16;
                float2 v0 = make_float2((acc[mi][ni][0] + bx) * scale, (acc[mi][ni][1] + by) * scale);
                float2 v1 = make_float2((acc[mi][ni][2] + bx) * scale, (acc[mi][ni][3] + by) * scale);
                *(float2*)(out + (size_t)r0 * DM + col) = v0;
                *(float2*)(out + (size_t)(r0 + 8) * DM + col) = v1;
            }
        }
    } else {
        __half* ohi = (z == 0) ? ar.ohi0 : ((z == 1) ? ar.ohi1 : ar.ohi2);
        __half* olo = (z == 0) ? ar.olo0 : ((z == 1) ? ar.olo1 : ar.olo2);
#pragma unroll
        for (int mi = 0; mi < 2; mi++) {
#pragma unroll
            for (int ni = 0; ni < 8; ni++) {
                int col = cbase + ni * 8;
                float bx = bias[col], by = bias[col + 1];
                int r0 = rbase + mi * 16;
                float v00 = (acc[mi][ni][0] + bx) * scale, v01 = (acc[mi][ni][1] + by) * scale;
                float v10 = (acc[mi][ni][2] + bx) * scale, v11 = (acc[mi][ni][3] + by) * scale;
                __half2 h0 = __floats2half2_rn(v00, v01);
                __half2 h1 = __floats2half2_rn(v10, v11);
                size_t p0 = (size_t)r0 * DM + col;
                size_t p1 = (size_t)(r0 + 8) * DM + col;
                *(__half2*)(ohi + p0) = h0;
                *(__half2*)(ohi + p1) = h1;
                if (olo) {
                    float2 f0 = __half22float2(h0);
                    float2 f1 = __half22float2(h1);
                    *(__half2*)(olo + p0) = __floats2half2_rn(v00 - f0.x, v01 - f0.y);
                    *(__half2*)(olo + p1) = __floats2half2_rn(v10 - f1.x, v11 - f1.y);
                }
            }
        }
    }
}

// ---------------------------------------------------------------------------
// Tensor-core flash attention — Q split, K/V fp16, fp16 P, MMA row-sums
// smem: [0,16K) Q hi, [16K,32K) Q lo, stage s at 32K+s*32K: {K 16K | V 16K}
// 2 CTAs/SM (97KB x 2 = 194KB <= 228KB).
// ---------------------------------------------------------------------------
#define AKV_BASE 32768
#define AKV_STAGE 32768
#define ATTN_SMEM (32768 + 2 * AKV_STAGE + 1024)

__global__ __launch_bounds__(256, 2) void attn_mma()
{
    extern __shared__ char sm_raw[];
    const uint32_t sraw = smem_u32(sm_raw);
    const uint32_t sbase = (sraw + 1023u) & ~1023u;

    const int tid = threadIdx.x;
    const int wid = tid >> 5;
    const int lid = tid & 31;
    const int b = blockIdx.z;
    const int h = blockIdx.y;
    const int q0 = blockIdx.x * 128;

    // ---- Q tile load (split hi/lo): 2048 segments, 8/thread ----
#pragma unroll
    for (int i = 0; i < 8; i++) {
        int s = tid + 256 * i;
        int buf = s >> 10;
        int r = (s & 1023) >> 3;
        int sg = s & 7;
        uint32_t off = ((uint32_t)(r * 128 + sg * 16)) ^ (((uint32_t)(r & 7)) << 4);
        const __half* src = (buf ? g_qlo : g_qhi) + (size_t)(b * SEQ + q0 + r) * DM + h * DKH + sg * 8;
        cp_async16(sbase + (uint32_t)buf * 16384 + off, src);
    }
    cp_commit();

    // ---- KV loader: K + V fp16, 2048 segments, 8/thread ----
    auto issue_kv = [&](int t, int stg) {
        const int kv0 = t * 128;
        const uint32_t stb = sbase + AKV_BASE + (uint32_t)stg * AKV_STAGE;
#pragma unroll
        for (int i = 0; i < 8; i++) {
            int s = tid + 256 * i;
            int buf = s >> 10;         // 0=K, 1=V
            int r = (s & 1023) >> 3;
            int sg = s & 7;
            uint32_t off = ((uint32_t)(r * 128 + sg * 16)) ^ (((uint32_t)(r & 7)) << 4);
            const __half* base = buf ? g_vhi : g_khi;
            cp_async16(stb + (uint32_t)buf * 16384 + off,
                       base + (size_t)(b * SEQ + kv0 + r) * DM + h * DKH + sg * 8);
        }
    };

    issue_kv(0, 0); cp_commit();

    const int lm_row = (lid & 7) + 8 * ((lid >> 3) & 1);
    const uint32_t rbyte = (uint32_t)(lm_row * 128);
    const uint32_t lsw = ((uint32_t)(lm_row & 7)) << 4;
    const uint32_t cpick = (uint32_t)(16 * (lid >> 4));

    cp_wait1();
    __syncthreads();
    uint32_t aq_hi[4][4], aq_lo[4][4];
    {
        uint32_t qb_hi = sbase + (uint32_t)(wid * 2048) + rbyte;
        uint32_t qb_lo = qb_hi + 16384;
#pragma unroll
        for (int kg = 0; kg < 4; kg++) {
            uint32_t cb = (cpick + kg * 32) ^ lsw;
            ldsm4(aq_hi[kg], qb_hi + cb);
            ldsm4(aq_lo[kg], qb_lo + cb);
        }
    }

    float m0 = -1e30f, m1 = -1e30f;
    float acc_l[4];
    float acc_o[8][4];
#pragma unroll
    for (int j = 0; j < 4; j++) acc_l[j] = 0.0f;
#pragma unroll
    for (int n = 0; n < 8; n++)
#pragma unroll
        for (int j = 0; j < 4; j++) acc_o[n][j] = 0.0f;

    const uint32_t ones2[2] = { 0x3C003C00u, 0x3C003C00u };   // half2(1,1)

    for (int t = 0; t < SEQ / 128; t++) {
        cp_wait0();
        __syncthreads();

        if (t + 1 < SEQ / 128) { issue_kv(t + 1, (t + 1) & 1); cp_commit(); }

        const uint32_t stb = sbase + AKV_BASE + (uint32_t)(t & 1) * AKV_STAGE;
        const uint32_t kb = stb + rbyte;
        const uint32_t vb = kb + 16384;

        // ---- QK^T (2-term: q_hi*k + q_lo*k) ----
        float c[16][4];
#pragma unroll
        for (int j = 0; j < 16; j++)
#pragma unroll
            for (int q = 0; q < 4; q++) c[j][q] = 0.0f;

#pragma unroll
        for (int j2 = 0; j2 < 8; j2++) {
            const uint32_t rowoff = (uint32_t)(j2 * 2048);
#pragma unroll
            for (int kg = 0; kg < 4; kg++) {
                uint32_t cb = (cpick + kg * 32) ^ lsw;
                uint32_t rh[4];
                ldsm4(rh, kb + rowoff + cb);
                uint32_t bh0[2] = { rh[0], rh[2] }, bh1[2] = { rh[1], rh[3] };
                mma16816(c[2 * j2],     aq_hi[kg], bh0);
                mma16816(c[2 * j2],     aq_lo[kg], bh0);
                mma16816(c[2 * j2 + 1], aq_hi[kg], bh1);
                mma16816(c[2 * j2 + 1], aq_lo[kg], bh1);
            }
        }

        // ---- online softmax (base-2, fp16 probabilities) ----
        float mx0 = -1e30f, mx1 = -1e30f;
#pragma unroll
        for (int j = 0; j < 16; j++) {
            mx0 = fmaxf(mx0, fmaxf(c[j][0], c[j][1]));
            mx1 = fmaxf(mx1, fmaxf(c[j][2], c[j][3]));
        }
        mx0 = fmaxf(mx0, __shfl_xor_sync(0xffffffffu, mx0, 1));
        mx0 = fmaxf(mx0, __shfl_xor_sync(0xffffffffu, mx0, 2));
        mx1 = fmaxf(mx1, __shfl_xor_sync(0xffffffffu, mx1, 1));
        mx1 = fmaxf(mx1, __shfl_xor_sync(0xffffffffu, mx1, 2));

        float mn0 = fmaxf(m0, mx0), mn1 = fmaxf(m1, mx1);
        float al0 = ex2f(m0 - mn0), al1 = ex2f(m1 - mn1);
        m0 = mn0; m1 = mn1;

        acc_l[0] *= al0; acc_l[1] *= al0;
        acc_l[2] *= al1; acc_l[3] *= al1;
#pragma unroll
        for (int n = 0; n < 8; n++) {
            acc_o[n][0] *= al0; acc_o[n][1] *= al0;
            acc_o[n][2] *= al1; acc_o[n][3] *= al1;
        }

        uint32_t ph[16][2];
#pragma unroll
        for (int j = 0; j < 16; j++) {
            ph[j][0] = ex2_h2(h2u(__floats2half2_rn(c[j][0] - mn0, c[j][1] - mn0)));
            ph[j][1] = ex2_h2(h2u(__floats2half2_rn(c[j][2] - mn1, c[j][3] - mn1)));
        }

        // ---- row sums (P x ones) + PV (V fp16) ----
#pragma unroll
        for (int kg = 0; kg < 8; kg++) {
            uint32_t A[4] = { ph[2 * kg][0], ph[2 * kg][1], ph[2 * kg + 1][0], ph[2 * kg + 1][1] };

            mma16816(acc_l, A, ones2);

            const uint32_t kvoff = (uint32_t)(kg * 2048);
#pragma unroll
            for (int d2 = 0; d2 < 4; d2++) {
                uint32_t cb = (cpick + d2 * 32) ^ lsw;
                uint32_t rhv[4];
                ldsm4t(rhv, vb + kvoff + cb);
                uint32_t bh0[2] = { rhv[0], rhv[1] }, bh1[2] = { rhv[2], rhv[3] };
                mma16816(acc_o[2 * d2],     A, bh0);
                mma16816(acc_o[2 * d2 + 1], A, bh1);
            }
        }
    }

    // ---- normalize + store split ctx ----
    const float inv0 = 1.0f / acc_l[0];
    const float inv1 = 1.0f / acc_l[2];
    const int gr0 = q0 + wid * 16 + (lid >> 2);
    const int gr1 = gr0 + 8;
    const int colb = h * DKH + (lid & 3) * 2;
#pragma unroll
    for (int n = 0; n < 8; n++) {
        int col = colb + n * 8;
        size_t o0 = (size_t)(b * SEQ + gr0) * DM + col;
        size_t o1 = (size_t)(b * SEQ + gr1) * DM + col;
        float vx0 = acc_o[n][0] * inv0, vy0 = acc_o[n][1] * inv0;
        float vx1 = acc_o[n][2] * inv1, vy1 = acc_o[n][3] * inv1;
        __half2 h0 = __floats2half2_rn(vx0, vy0);
        __half2 h1 = __floats2half2_rn(vx1, vy1);
        float2 f0 = __half22float2(h0);
        float2 f1 = __half22float2(h1);
        *(__half2*)(g_chi + o0) = h0;
        *(__half2*)(g_chi + o1) = h1;
        *(__half2*)(g_clo + o0) = __floats2half2_rn(vx0 - f0.x, vy0 - f0.y);
        *(__half2*)(g_clo + o1) = __floats2half2_rn(vx1 - f1.x, vy1 - f1.y);
    }
}

// ---------------------------------------------------------------------------
#define QSCALE 0.18033688f   // (1/8) * log2(e)

extern "C" void kernel_launch(void* const* d_in, const int* in_sizes, int n_in,
                              void* d_out, int out_size)
{
    const float* query = (const float*)d_in[0];
    const float* key   = (const float*)d_in[1];
    const float* value = (const float*)d_in[2];
    const float* Wq    = (const float*)d_in[3];
    const float* bq    = (const float*)d_in[4];
    const float* Wk    = (const float*)d_in[5];
    const float* bk    = (const float*)d_in[6];
    const float* Wv    = (const float*)d_in[7];
    const float* bv    = (const float*)d_in[8];
    const float* Wo    = (const float*)d_in[9];
    const float* bo    = (const float*)d_in[10];

    __half *xhi, *xlo, *whi, *chi, *clo;
    __half *qhi, *qlo, *khi, *vhi;
    cudaGetSymbolAddress((void**)&xhi, g_xhi);
    cudaGetSymbolAddress((void**)&xlo, g_xlo);
    cudaGetSymbolAddress((void**)&whi, g_whi);
    cudaGetSymbolAddress((void**)&chi, g_chi);
    cudaGetSymbolAddress((void**)&clo, g_clo);
    cudaGetSymbolAddress((void**)&qhi, g_qhi);
    cudaGetSymbolAddress((void**)&qlo, g_qlo);
    cudaGetSymbolAddress((void**)&khi, g_khi);
    cudaGetSymbolAddress((void**)&vhi, g_vhi);

    cudaFuncSetAttribute(gemm_tc, cudaFuncAttributeMaxDynamicSharedMemorySize, GEMM_SMEM);
    cudaFuncSetAttribute(attn_mma, cudaFuncAttributeMaxDynamicSharedMemorySize, ATTN_SMEM);

    const size_t XN = (size_t)MTOK * DM;
    const size_t WN = (size_t)DM * DM;

    // fused conversions (3 splits + 4 halves) in one launch
    ConvArgs ca;
    ca.x0 = query; ca.x1 = key; ca.x2 = value;
    ca.w0 = Wq; ca.w1 = Wk; ca.w2 = Wv; ca.w3 = Wo;
    ca.xhi = xhi; ca.xlo = xlo; ca.whi = whi;
    convert_all<<<CONV_TOTAL / 256, 256>>>(ca);

    // QKV projections: Q -> split (pre-scaled), K/V -> fp16 only
    GemmArgs qkv;
    qkv.xhi = xhi; qkv.xlo = xlo; qkv.whi = whi;
    qkv.b0 = bq; qkv.b1 = bk; qkv.b2 = bv;
    qkv.o0 = nullptr; qkv.o1 = nullptr; qkv.o2 = nullptr;
    qkv.ohi0 = qhi; qkv.olo0 = qlo;
    qkv.ohi1 = khi; qkv.olo1 = nullptr;
    qkv.ohi2 = vhi; qkv.olo2 = nullptr;
    qkv.s0 = QSCALE; qkv.s1 = 1.0f; qkv.s2 = 1.0f;
    qkv.xstride = (long long)XN; qkv.wstride = (long long)WN;
    gemm_tc<<<dim3(DM / 128, MTOK / 128, 3), 256, GEMM_SMEM>>>(qkv);

    attn_mma<<<dim3(SEQ / 128, NH, NB), 256, ATTN_SMEM>>>();

    // O projection -> fp32 d_out (ctx split, Wo fp16)
    GemmArgs og;
    og.xhi = chi; og.xlo = clo; og.whi = whi + 3 * WN;
    og.b0 = bo; og.b1 = bo; og.b2 = bo;
    og.o0 = (float*)d_out; og.o1 = (float*)d_out; og.o2 = (float*)d_out;
    og.ohi0 = nullptr; og.olo0 = nullptr; og.ohi1 = nullptr; og.olo1 = nullptr;
    og.ohi2 = nullptr; og.olo2 = nullptr;
    og.s0 = 1.0f; og.s1 = 1.0f; og.s2 = 1.0f;
    og.xstride = 0; og.wstride = 0;
    gemm_tc<<<dim3(DM / 128, MTOK / 128, 1), 256, GEMM_SMEM>>>(og);
}

// round 14
// speedup vs baseline: 6.3452x; 1.0375x over previous
#include <cuda_runtime.h>
#include <cuda_fp16.h>
#include <math.h>
#include <stdint.h>

#define NH   16
#define DKH  64
#define DM   1024
#define NB   2
#define SEQ  2048
#define MTOK (NB * SEQ)   // 4096

// ---------------------------------------------------------------------------
// Device scratch
// ---------------------------------------------------------------------------
__device__ __half g_xhi[(size_t)3 * MTOK * DM];   // split q,k,v inputs
__device__ __half g_xlo[(size_t)3 * MTOK * DM];
__device__ __half g_whi[(size_t)4 * DM * DM];     // fp16 Wq,Wk,Wv,Wo

__device__ __half g_qhi[(size_t)MTOK * DM];       // projected Q, split + pre-scaled
__device__ __half g_qlo[(size_t)MTOK * DM];
__device__ __half g_khi[(size_t)MTOK * DM];       // projected K (fp16)
__device__ __half g_vhi[(size_t)MTOK * DM];       // projected V (fp16)

__device__ __half g_chi[(size_t)MTOK * DM];       // split ctx (written by attn)
__device__ __half g_clo[(size_t)MTOK * DM];

// ---------------------------------------------------------------------------
// PTX helpers
// ---------------------------------------------------------------------------
__device__ __forceinline__ uint32_t smem_u32(const void* p) {
    uint32_t a;
    asm("{ .reg .u64 t; cvta.to.shared.u64 t, %1; cvt.u32.u64 %0, t; }" : "=r"(a) : "l"(p));
    return a;
}
__device__ __forceinline__ void cp_async16(uint32_t dst, const void* src) {
    asm volatile("cp.async.cg.shared.global [%0], [%1], 16;" :: "r"(dst), "l"(src));
}
__device__ __forceinline__ void cp_commit() {
    asm volatile("cp.async.commit_group;");
}
__device__ __forceinline__ void cp_wait0() {
    asm volatile("cp.async.wait_group 0;");
}
__device__ __forceinline__ void cp_wait1() {
    asm volatile("cp.async.wait_group 1;");
}
__device__ __forceinline__ void cp_wait2() {
    asm volatile("cp.async.wait_group 2;");
}
__device__ __forceinline__ void ldsm4(uint32_t* r, uint32_t addr) {
    asm volatile("ldmatrix.sync.aligned.m8n8.x4.shared.b16 {%0,%1,%2,%3}, [%4];"
                 : "=r"(r[0]), "=r"(r[1]), "=r"(r[2]), "=r"(r[3]) : "r"(addr));
}
__device__ __forceinline__ void ldsm4t(uint32_t* r, uint32_t addr) {
    asm volatile("ldmatrix.sync.aligned.m8n8.x4.trans.shared.b16 {%0,%1,%2,%3}, [%4];"
                 : "=r"(r[0]), "=r"(r[1]), "=r"(r[2]), "=r"(r[3]) : "r"(addr));
}
__device__ __forceinline__ void mma16816(float* c, const uint32_t* a, const uint32_t* b) {
    asm volatile(
        "mma.sync.aligned.m16n8k16.row.col.f32.f16.f16.f32 "
        "{%0,%1,%2,%3}, {%4,%5,%6,%7}, {%8,%9}, {%0,%1,%2,%3};"
        : "+f"(c[0]), "+f"(c[1]), "+f"(c[2]), "+f"(c[3])
        : "r"(a[0]), "r"(a[1]), "r"(a[2]), "r"(a[3]), "r"(b[0]), "r"(b[1]));
}
__device__ __forceinline__ float ex2f(float x) {
    float y;
    asm("ex2.approx.f32 %0, %1;" : "=f"(y) : "f"(x));
    return y;
}
__device__ __forceinline__ uint32_t ex2_h2(uint32_t x) {
    uint32_t y;
    asm("ex2.approx.f16x2 %0, %1;" : "=r"(y) : "r"(x));
    return y;
}
__device__ __forceinline__ uint32_t h2u(__half2 h) {
    return *reinterpret_cast<uint32_t*>(&h);
}
__device__ __forceinline__ uint32_t swz64(uint32_t off) {
    return off ^ (((off >> 7) & 3u) << 4);
}

// ---------------------------------------------------------------------------
// Fused conversions: 3 split (q,k,v) + 4 tohalf (W) in one launch
// ---------------------------------------------------------------------------
struct ConvArgs {
    const float *x0, *x1, *x2;
    const float *w0, *w1, *w2, *w3;
    __half *xhi, *xlo, *whi;
};

#define XQ4 ((size_t)MTOK * DM / 4)
#define WQ4 ((size_t)DM * DM / 4)
#define CONV_TOTAL (3 * 1048576 + 4 * 262144)

__global__ __launch_bounds__(256) void convert_all(ConvArgs a) {
    size_t i = (size_t)blockIdx.x * 256 + threadIdx.x;
    if (i < 3 * XQ4) {
        int which = (int)(i / XQ4);
        size_t off = i - (size_t)which * XQ4;
        const float* src = (which == 0) ? a.x0 : ((which == 1) ? a.x1 : a.x2);
        float4 v = ((const float4*)src)[off];
        size_t o = (size_t)which * XQ4 + off;
        __half2 h0 = __floats2half2_rn(v.x, v.y);
        __half2 h1 = __floats2half2_rn(v.z, v.w);
        float2 f0 = __half22float2(h0);
        float2 f1 = __half22float2(h1);
        ((__half2*)a.xhi)[2 * o]     = h0;
        ((__half2*)a.xhi)[2 * o + 1] = h1;
        ((__half2*)a.xlo)[2 * o]     = __floats2half2_rn(v.x - f0.x, v.y - f0.y);
        ((__half2*)a.xlo)[2 * o + 1] = __floats2half2_rn(v.z - f1.x, v.w - f1.y);
    } else {
        size_t j = i - 3 * XQ4;
        int which = (int)(j / WQ4);
        size_t off = j - (size_t)which * WQ4;
        const float* src = (which == 0) ? a.w0 : ((which == 1) ? a.w1 : ((which == 2) ? a.w2 : a.w3));
        float4 v = ((const float4*)src)[off];
        size_t o = (size_t)which * WQ4 + off;
        ((__half2*)a.whi)[2 * o]     = __floats2half2_rn(v.x, v.y);
        ((__half2*)a.whi)[2 * o + 1] = __floats2half2_rn(v.z, v.w);
    }
}

// ---------------------------------------------------------------------------
// mma.sync GEMM (NT): C = A[M,K]*W[N,K]^T + bias; A split (hi+lo), W fp16.
// 128x128 tile, BK=32, 4-stage cp.async, hi/lo passes (reuse distance 16).
// ---------------------------------------------------------------------------
struct GemmArgs {
    const __half *xhi, *xlo, *whi;
    const float *b0, *b1, *b2;
    float *o0, *o1, *o2;                      // fp32 outputs (NULL => half mode)
    __half *ohi0, *olo0, *ohi1, *olo1, *ohi2, *olo2;
    float s0, s1, s2;
    long long xstride, wstride;
};

#define TILE_B   8192
#define STAGE_B  (3 * TILE_B)
#define NSTAGE   4
#define GEMM_SMEM (NSTAGE * STAGE_B)          // 96 KB
#define NCHUNK   (DM / 32)

__global__ __launch_bounds__(256, 2) void gemm_tc(GemmArgs ar) {
    extern __shared__ char sm[];
    const uint32_t sbase = smem_u32(sm);

    const int tid = threadIdx.x;
    const int wid = tid >> 5;
    const int lid = tid & 31;
    const int z = blockIdx.z;

    const __half* xhi = ar.xhi + (size_t)z * ar.xstride;
    const __half* xlo = ar.xlo + (size_t)z * ar.xstride;
    const __half* whi = ar.whi + (size_t)z * ar.wstride;
    const float* bias = (z == 0) ? ar.b0 : ((z == 1) ? ar.b1 : ar.b2);
    const float scale = (z == 0) ? ar.s0 : ((z == 1) ? ar.s1 : ar.s2);

    const int bm = blockIdx.y * 128;
    const int bn = blockIdx.x * 128;

    const int lrow0 = tid >> 2;
    const int lseg  = tid & 3;
    const uint32_t soff0 = swz64((uint32_t)(lrow0 * 64 + lseg * 16));
    const uint32_t soff1 = swz64((uint32_t)((lrow0 + 64) * 64 + lseg * 16));

    // hoisted global base pointers (64-bit math once)
    const __half* pA0 = xhi + (size_t)(bm + lrow0) * DM + lseg * 8;
    const __half* pA1 = xhi + (size_t)(bm + lrow0 + 64) * DM + lseg * 8;
    const __half* pL0 = xlo + (size_t)(bm + lrow0) * DM + lseg * 8;
    const __half* pL1 = xlo + (size_t)(bm + lrow0 + 64) * DM + lseg * 8;
    const __half* pW0 = whi + (size_t)(bn + lrow0) * DM + lseg * 8;
    const __half* pW1 = whi + (size_t)(bn + lrow0 + 64) * DM + lseg * 8;

    auto load_stage = [&](int chunk, int stage) {
        const int k0 = chunk * 32;
        const uint32_t st = sbase + stage * STAGE_B;
        cp_async16(st + soff0,              pA0 + k0);
        cp_async16(st + soff1,              pA1 + k0);
        cp_async16(st + TILE_B + soff0,     pL0 + k0);
        cp_async16(st + TILE_B + soff1,     pL1 + k0);
        cp_async16(st + 2 * TILE_B + soff0, pW0 + k0);
        cp_async16(st + 2 * TILE_B + soff1, pW1 + k0);
    };

    const int wm = wid & 3;
    const int wn = wid >> 2;
    const int lm_row = (lid & 7) + 8 * ((lid >> 3) & 1);
    const int lm_cb  = 16 * (lid >> 4);

    // hoisted smem ldsm offsets (stage-relative)
    uint32_t aoff[2][2], woff[2][4];
#pragma unroll
    for (int ks = 0; ks < 2; ks++) {
        const int cb = ks * 32 + lm_cb;
#pragma unroll
        for (int mi = 0; mi < 2; mi++)
            aoff[ks][mi] = swz64((uint32_t)((wm * 32 + mi * 16 + lm_row) * 64 + cb));
#pragma unroll
        for (int j = 0; j < 4; j++)
            woff[ks][j] = swz64((uint32_t)((wn * 64 + j * 16 + lm_row) * 64 + cb));
    }

    float acc[2][8][4];
#pragma unroll
    for (int i = 0; i < 2; i++)
#pragma unroll
        for (int j = 0; j < 8; j++)
#pragma unroll
            for (int k = 0; k < 4; k++) acc[i][j][k] = 0.0f;

    load_stage(0, 0); cp_commit();
    load_stage(1, 1); cp_commit();
    load_stage(2, 2); cp_commit();

    for (int c = 0; c < NCHUNK; c++) {
        cp_wait2();
        __syncthreads();
        if (c + 3 < NCHUNK) load_stage(c + 3, (c + 3) & 3);
        cp_commit();

        const uint32_t st = sbase + (uint32_t)(c & 3) * STAGE_B;

#pragma unroll
        for (int ks = 0; ks < 2; ks++) {
            uint32_t ahi[2][4], alo[2][4];
#pragma unroll
            for (int mi = 0; mi < 2; mi++) {
                ldsm4(ahi[mi], st + aoff[ks][mi]);
                ldsm4(alo[mi], st + TILE_B + aoff[ks][mi]);
            }
            uint32_t rh[4][4];
#pragma unroll
            for (int j = 0; j < 4; j++)
                ldsm4(rh[j], st + 2 * TILE_B + woff[ks][j]);

            // hi pass: 16 MMAs across 16 accumulators
#pragma unroll
            for (int j = 0; j < 4; j++) {
                uint32_t bh0[2] = { rh[j][0], rh[j][2] }, bh1[2] = { rh[j][1], rh[j][3] };
#pragma unroll
                for (int mi = 0; mi < 2; mi++) {
                    mma16816(acc[mi][2 * j],     ahi[mi], bh0);
                    mma16816(acc[mi][2 * j + 1], ahi[mi], bh1);
                }
            }
            // lo pass
#pragma unroll
            for (int j = 0; j < 4; j++) {
                uint32_t bh0[2] = { rh[j][0], rh[j][2] }, bh1[2] = { rh[j][1], rh[j][3] };
#pragma unroll
                for (int mi = 0; mi < 2; mi++) {
                    mma16816(acc[mi][2 * j],     alo[mi], bh0);
                    mma16816(acc[mi][2 * j + 1], alo[mi], bh1);
                }
            }
        }
        __syncthreads();
    }

    const int rbase = bm + wm * 32 + (lid >> 2);
    const int cbase = bn + wn * 64 + (lid & 3) * 2;
    float* out = (z == 0) ? ar.o0 : ((z == 1) ? ar.o1 : ar.o2);

    if (out) {
#pragma unroll
        for (int mi = 0; mi < 2; mi++) {
#pragma unroll
            for (int ni = 0; ni < 8; ni++) {
                int col = cbase + ni * 8;
                float bx = bias[col], by = bias[col + 1];
                int r0 = rbase + mi * 16;
                float2 v0 = make_float2((acc[mi][ni][0] + bx) * scale, (acc[mi][ni][1] + by) * scale);
                float2 v1 = make_float2((acc[mi][ni][2] + bx) * scale, (acc[mi][ni][3] + by) * scale);
                *(float2*)(out + (size_t)r0 * DM + col) = v0;
                *(float2*)(out + (size_t)(r0 + 8) * DM + col) = v1;
            }
        }
    } else {
        __half* ohi = (z == 0) ? ar.ohi0 : ((z == 1) ? ar.ohi1 : ar.ohi2);
        __half* olo = (z == 0) ? ar.olo0 : ((z == 1) ? ar.olo1 : ar.olo2);
#pragma unroll
        for (int mi = 0; mi < 2; mi++) {
#pragma unroll
            for (int ni = 0; ni < 8; ni++) {
                int col = cbase + ni * 8;
                float bx = bias[col], by = bias[col + 1];
                int r0 = rbase + mi * 16;
                float v00 = (acc[mi][ni][0] + bx) * scale, v01 = (acc[mi][ni][1] + by) * scale;
                float v10 = (acc[mi][ni][2] + bx) * scale, v11 = (acc[mi][ni][3] + by) * scale;
                __half2 h0 = __floats2half2_rn(v00, v01);
                __half2 h1 = __floats2half2_rn(v10, v11);
                size_t p0 = (size_t)r0 * DM + col;
                size_t p1 = (size_t)(r0 + 8) * DM + col;
                *(__half2*)(ohi + p0) = h0;
                *(__half2*)(ohi + p1) = h1;
                if (olo) {
                    float2 f0 = __half22float2(h0);
                    float2 f1 = __half22float2(h1);
                    *(__half2*)(olo + p0) = __floats2half2_rn(v00 - f0.x, v01 - f0.y);
                    *(__half2*)(olo + p1) = __floats2half2_rn(v10 - f1.x, v11 - f1.y);
                }
            }
        }
    }
}

// ---------------------------------------------------------------------------
// Tensor-core flash attention — Q split, K/V fp16, fp16 P, MMA row-sums.
// QK restructured: kg-outer, j2-halves, hi/lo passes (reuse distance 8).
// ---------------------------------------------------------------------------
#define AKV_BASE 32768
#define AKV_STAGE 32768
#define ATTN_SMEM (32768 + 2 * AKV_STAGE + 1024)

__global__ __launch_bounds__(256) void attn_mma()
{
    extern __shared__ char sm_raw[];
    const uint32_t sraw = smem_u32(sm_raw);
    const uint32_t sbase = (sraw + 1023u) & ~1023u;

    const int tid = threadIdx.x;
    const int wid = tid >> 5;
    const int lid = tid & 31;
    const int b = blockIdx.z;
    const int h = blockIdx.y;
    const int q0 = blockIdx.x * 128;

    // ---- Q tile load (split hi/lo) ----
#pragma unroll
    for (int i = 0; i < 8; i++) {
        int s = tid + 256 * i;
        int buf = s >> 10;
        int r = (s & 1023) >> 3;
        int sg = s & 7;
        uint32_t off = ((uint32_t)(r * 128 + sg * 16)) ^ (((uint32_t)(r & 7)) << 4);
        const __half* src = (buf ? g_qlo : g_qhi) + (size_t)(b * SEQ + q0 + r) * DM + h * DKH + sg * 8;
        cp_async16(sbase + (uint32_t)buf * 16384 + off, src);
    }
    cp_commit();

    auto issue_kv = [&](int t, int stg) {
        const int kv0 = t * 128;
        const uint32_t stb = sbase + AKV_BASE + (uint32_t)stg * AKV_STAGE;
#pragma unroll
        for (int i = 0; i < 8; i++) {
            int s = tid + 256 * i;
            int buf = s >> 10;
            int r = (s & 1023) >> 3;
            int sg = s & 7;
            uint32_t off = ((uint32_t)(r * 128 + sg * 16)) ^ (((uint32_t)(r & 7)) << 4);
            const __half* base = buf ? g_vhi : g_khi;
            cp_async16(stb + (uint32_t)buf * 16384 + off,
                       base + (size_t)(b * SEQ + kv0 + r) * DM + h * DKH + sg * 8);
        }
    };

    issue_kv(0, 0); cp_commit();

    const int lm_row = (lid & 7) + 8 * ((lid >> 3) & 1);
    const uint32_t rbyte = (uint32_t)(lm_row * 128);
    const uint32_t lsw = ((uint32_t)(lm_row & 7)) << 4;
    const uint32_t cpick = (uint32_t)(16 * (lid >> 4));

    cp_wait1();
    __syncthreads();
    uint32_t aq_hi[4][4], aq_lo[4][4];
    {
        uint32_t qb_hi = sbase + (uint32_t)(wid * 2048) + rbyte;
        uint32_t qb_lo = qb_hi + 16384;
#pragma unroll
        for (int kg = 0; kg < 4; kg++) {
            uint32_t cb = (cpick + kg * 32) ^ lsw;
            ldsm4(aq_hi[kg], qb_hi + cb);
            ldsm4(aq_lo[kg], qb_lo + cb);
        }
    }

    float m0 = -1e30f, m1 = -1e30f;
    float acc_l[4];
    float acc_o[8][4];
#pragma unroll
    for (int j = 0; j < 4; j++) acc_l[j] = 0.0f;
#pragma unroll
    for (int n = 0; n < 8; n++)
#pragma unroll
        for (int j = 0; j < 4; j++) acc_o[n][j] = 0.0f;

    const uint32_t ones2[2] = { 0x3C003C00u, 0x3C003C00u };

    for (int t = 0; t < SEQ / 128; t++) {
        cp_wait0();
        __syncthreads();

        if (t + 1 < SEQ / 128) { issue_kv(t + 1, (t + 1) & 1); cp_commit(); }

        const uint32_t stb = sbase + AKV_BASE + (uint32_t)(t & 1) * AKV_STAGE;
        const uint32_t kb = stb + rbyte;
        const uint32_t vb = kb + 16384;

        // ---- QK^T: kg outer, j2-halves of 4, hi/lo passes ----
        float c[16][4];
#pragma unroll
        for (int j = 0; j < 16; j++)
#pragma unroll
            for (int q = 0; q < 4; q++) c[j][q] = 0.0f;

#pragma unroll
        for (int kg = 0; kg < 4; kg++) {
            const uint32_t cb = (cpick + kg * 32) ^ lsw;
#pragma unroll
            for (int half = 0; half < 2; half++) {
                uint32_t rh[4][4];
#pragma unroll
                for (int jj = 0; jj < 4; jj++)
                    ldsm4(rh[jj], kb + (uint32_t)((half * 4 + jj) * 2048) + cb);
#pragma unroll
                for (int jj = 0; jj < 4; jj++) {
                    int j2 = half * 4 + jj;
                    uint32_t bh0[2] = { rh[jj][0], rh[jj][2] }, bh1[2] = { rh[jj][1], rh[jj][3] };
                    mma16816(c[2 * j2],     aq_hi[kg], bh0);
                    mma16816(c[2 * j2 + 1], aq_hi[kg], bh1);
                }
#pragma unroll
                for (int jj = 0; jj < 4; jj++) {
                    int j2 = half * 4 + jj;
                    uint32_t bh0[2] = { rh[jj][0], rh[jj][2] }, bh1[2] = { rh[jj][1], rh[jj][3] };
                    mma16816(c[2 * j2],     aq_lo[kg], bh0);
                    mma16816(c[2 * j2 + 1], aq_lo[kg], bh1);
                }
            }
        }

        // ---- online softmax (base-2, fp16 probabilities) ----
        float mx0 = -1e30f, mx1 = -1e30f;
#pragma unroll
        for (int j = 0; j < 16; j++) {
            mx0 = fmaxf(mx0, fmaxf(c[j][0], c[j][1]));
            mx1 = fmaxf(mx1, fmaxf(c[j][2], c[j][3]));
        }
        mx0 = fmaxf(mx0, __shfl_xor_sync(0xffffffffu, mx0, 1));
        mx0 = fmaxf(mx0, __shfl_xor_sync(0xffffffffu, mx0, 2));
        mx1 = fmaxf(mx1, __shfl_xor_sync(0xffffffffu, mx1, 1));
        mx1 = fmaxf(mx1, __shfl_xor_sync(0xffffffffu, mx1, 2));

        float mn0 = fmaxf(m0, mx0), mn1 = fmaxf(m1, mx1);
        float al0 = ex2f(m0 - mn0), al1 = ex2f(m1 - mn1);
        m0 = mn0; m1 = mn1;

        acc_l[0] *= al0; acc_l[1] *= al0;
        acc_l[2] *= al1; acc_l[3] *= al1;
#pragma unroll
        for (int n = 0; n < 8; n++) {
            acc_o[n][0] *= al0; acc_o[n][1] *= al0;
            acc_o[n][2] *= al1; acc_o[n][3] *= al1;
        }

        uint32_t ph[16][2];
#pragma unroll
        for (int j = 0; j < 16; j++) {
            ph[j][0] = ex2_h2(h2u(__floats2half2_rn(c[j][0] - mn0, c[j][1] - mn0)));
            ph[j][1] = ex2_h2(h2u(__floats2half2_rn(c[j][2] - mn1, c[j][3] - mn1)));
        }

        // ---- row sums (P x ones) + PV (V fp16) ----
#pragma unroll
        for (int kg = 0; kg < 8; kg++) {
            uint32_t A[4] = { ph[2 * kg][0], ph[2 * kg][1], ph[2 * kg + 1][0], ph[2 * kg + 1][1] };

            mma16816(acc_l, A, ones2);

            const uint32_t kvoff = (uint32_t)(kg * 2048);
#pragma unroll
            for (int d2 = 0; d2 < 4; d2++) {
                uint32_t cb = (cpick + d2 * 32) ^ lsw;
                uint32_t rhv[4];
                ldsm4t(rhv, vb + kvoff + cb);
                uint32_t bh0[2] = { rhv[0], rhv[1] }, bh1[2] = { rhv[2], rhv[3] };
                mma16816(acc_o[2 * d2],     A, bh0);
                mma16816(acc_o[2 * d2 + 1], A, bh1);
            }
        }
    }

    // ---- normalize + store split ctx ----
    const float inv0 = 1.0f / acc_l[0];
    const float inv1 = 1.0f / acc_l[2];
    const int gr0 = q0 + wid * 16 + (lid >> 2);
    const int gr1 = gr0 + 8;
    const int colb = h * DKH + (lid & 3) * 2;
#pragma unroll
    for (int n = 0; n < 8; n++) {
        int col = colb + n * 8;
        size_t o0 = (size_t)(b * SEQ + gr0) * DM + col;
        size_t o1 = (size_t)(b * SEQ + gr1) * DM + col;
        float vx0 = acc_o[n][0] * inv0, vy0 = acc_o[n][1] * inv0;
        float vx1 = acc_o[n][2] * inv1, vy1 = acc_o[n][3] * inv1;
        __half2 h0 = __floats2half2_rn(vx0, vy0);
        __half2 h1 = __floats2half2_rn(vx1, vy1);
        float2 f0 = __half22float2(h0);
        float2 f1 = __half22float2(h1);
        *(__half2*)(g_chi + o0) = h0;
        *(__half2*)(g_chi + o1) = h1;
        *(__half2*)(g_clo + o0) = __floats2half2_rn(vx0 - f0.x, vy0 - f0.y);
        *(__half2*)(g_clo + o1) = __floats2half2_rn(vx1 - f1.x, vy1 - f1.y);
    }
}

// ---------------------------------------------------------------------------
#define QSCALE 0.18033688f   // (1/8) * log2(e)

extern "C" void kernel_launch(void* const* d_in, const int* in_sizes, int n_in,
                              void* d_out, int out_size)
{
    const float* query = (const float*)d_in[0];
    const float* key   = (const float*)d_in[1];
    const float* value = (const float*)d_in[2];
    const float* Wq    = (const float*)d_in[3];
    const float* bq    = (const float*)d_in[4];
    const float* Wk    = (const float*)d_in[5];
    const float* bk    = (const float*)d_in[6];
    const float* Wv    = (const float*)d_in[7];
    const float* bv    = (const float*)d_in[8];
    const float* Wo    = (const float*)d_in[9];
    const float* bo    = (const float*)d_in[10];

    __half *xhi, *xlo, *whi, *chi, *clo;
    __half *qhi, *qlo, *khi, *vhi;
    cudaGetSymbolAddress((void**)&xhi, g_xhi);
    cudaGetSymbolAddress((void**)&xlo, g_xlo);
    cudaGetSymbolAddress((void**)&whi, g_whi);
    cudaGetSymbolAddress((void**)&chi, g_chi);
    cudaGetSymbolAddress((void**)&clo, g_clo);
    cudaGetSymbolAddress((void**)&qhi, g_qhi);
    cudaGetSymbolAddress((void**)&qlo, g_qlo);
    cudaGetSymbolAddress((void**)&khi, g_khi);
    cudaGetSymbolAddress((void**)&vhi, g_vhi);

    cudaFuncSetAttribute(gemm_tc, cudaFuncAttributeMaxDynamicSharedMemorySize, GEMM_SMEM);
    cudaFuncSetAttribute(attn_mma, cudaFuncAttributeMaxDynamicSharedMemorySize, ATTN_SMEM);

    const size_t XN = (size_t)MTOK * DM;
    const size_t WN = (size_t)DM * DM;

    ConvArgs ca;
    ca.x0 = query; ca.x1 = key; ca.x2 = value;
    ca.w0 = Wq; ca.w1 = Wk; ca.w2 = Wv; ca.w3 = Wo;
    ca.xhi = xhi; ca.xlo = xlo; ca.whi = whi;
    convert_all<<<CONV_TOTAL / 256, 256>>>(ca);

    GemmArgs qkv;
    qkv.xhi = xhi; qkv.xlo = xlo; qkv.whi = whi;
    qkv.b0 = bq; qkv.b1 = bk; qkv.b2 = bv;
    qkv.o0 = nullptr; qkv.o1 = nullptr; qkv.o2 = nullptr;
    qkv.ohi0 = qhi; qkv.olo0 = qlo;
    qkv.ohi1 = khi; qkv.olo1 = nullptr;
    qkv.ohi2 = vhi; qkv.olo2 = nullptr;
    qkv.s0 = QSCALE; qkv.s1 = 1.0f; qkv.s2 = 1.0f;
    qkv.xstride = (long long)XN; qkv.wstride = (long long)WN;
    gemm_tc<<<dim3(DM / 128, MTOK / 128, 3), 256, GEMM_SMEM>>>(qkv);

    attn_mma<<<dim3(SEQ / 128, NH, NB), 256, ATTN_SMEM>>>();

    GemmArgs og;
    og.xhi = chi; og.xlo = clo; og.whi = whi + 3 * WN;
    og.b0 = bo; og.b1 = bo; og.b2 = bo;
    og.o0 = (float*)d_out; og.o1 = (float*)d_out; og.o2 = (float*)d_out;
    og.ohi0 = nullptr; og.olo0 = nullptr; og.ohi1 = nullptr; og.olo1 = nullptr;
    og.ohi2 = nullptr; og.olo2 = nullptr;
    og.s0 = 1.0f; og.s1 = 1.0f; og.s2 = 1.0f;
    og.xstride = 0; og.wstride = 0;
    gemm_tc<<<dim3(DM / 128, MTOK / 128, 1), 256, GEMM_SMEM>>>(og);
}